// round 11
// baseline (speedup 1.0000x reference)
#include <cuda_runtime.h>
#include <cstdint>

// ---------------------------------------------------------------------------
// CaT transformer, tf32 mma.sync (portable sm_100 target).
// R11: AQ GEMM fused into attention kernel as phase 0 (bit-exact K-order),
// deleting the AQ4 global round-trip. Oracle rel_err 7.903782e-4.
// ---------------------------------------------------------------------------

#define DI __device__ __forceinline__

static DI float swishf(float x) { return x / (1.f + __expf(-x)); }

// ------------------------- static device scratch ---------------------------
__device__ float g_Wqkvt[4 * 1536 * 256];   // tf32
__device__ float g_Bqkv [4 * 1536];
__device__ float g_Wpt  [4 * 256 * 512];    // tf32
__device__ float g_W1t  [4 * 1024 * 256];   // tf32
__device__ float g_W2t  [4 * 256 * 1024];   // tf32
__device__ float g_Wlmt [256 * 256];        // tf32
__device__ unsigned char g_Amask[2 * 512 * 512];
__device__ float g_Amaskf[2 * 512 * 512];   // 0.0 / 1.0
__device__ float g_KQV[3 * 512 * 8192];     // K | Qt | Vt (tf32)
__device__ float g_Ob [8192 * 512];         // tf32
__device__ float g_Mha[8192 * 256];         // exact residual
__device__ float g_Mhar[8192 * 256];        // tf32
__device__ float g_Ff [8192 * 1024];        // tf32
__device__ float g_Xb [8192 * 256];         // tf32

// --------------------------- helpers ---------------------------------------
DI unsigned tf32_rn(float x) {
    unsigned r;
    asm("cvt.rn.tf32.f32 %0, %1;" : "=r"(r) : "f"(x));
    return r;
}
DI float tf32f(float x) { return __uint_as_float(tf32_rn(x)); }
DI unsigned cvta_s(const void* p) { return (unsigned)__cvta_generic_to_shared(p); }
DI void cpa16(unsigned dst, const void* src) {
    asm volatile("cp.async.cg.shared.global [%0], [%1], 16;" :: "r"(dst), "l"(src) : "memory");
}
#define CPA_COMMIT() asm volatile("cp.async.commit_group;" ::: "memory")
#define CPA_WAIT(N)  asm volatile("cp.async.wait_group %0;" :: "n"(N) : "memory")

#define LDM_X4(r0, r1, r2, r3, addr) \
    asm volatile("ldmatrix.sync.aligned.m8n8.x4.shared.b16 {%0,%1,%2,%3}, [%4];" \
                 : "=r"(r0), "=r"(r1), "=r"(r2), "=r"(r3) : "r"(addr))
#define MMA_TF32(d, a, b) \
    asm volatile("mma.sync.aligned.m16n8k8.row.col.f32.tf32.tf32.f32 " \
                 "{%0,%1,%2,%3}, {%4,%5,%6,%7}, {%8,%9}, {%0,%1,%2,%3};" \
                 : "+f"((d)[0]), "+f"((d)[1]), "+f"((d)[2]), "+f"((d)[3]) \
                 : "r"((a)[0]), "r"((a)[1]), "r"((a)[2]), "r"((a)[3]), \
                   "r"((b)[0]), "r"((b)[1]))

// ------------------------------ prep kernels -------------------------------
__global__ void pack_qkv_k(const float* __restrict__ Wk, const float* __restrict__ Wq,
                           const float* __restrict__ Wv, const float* __restrict__ bk,
                           const float* __restrict__ bq, const float* __restrict__ bv) {
    int idx = blockIdx.x * 256 + threadIdx.x;          // < 1572864
    int l = idx / 393216;
    int rem = idx - l * 393216;
    int r = rem >> 8;
    int d = rem & 255;
    int t = r >> 9, h = (r >> 6) & 7, hs = r & 63;
    const float* W = (t == 0) ? Wk : (t == 1) ? Wq : Wv;
    g_Wqkvt[idx] = tf32f(W[(((size_t)(l * 8 + h)) * 256 + d) * 64 + hs]);
    if (idx < 4 * 1536) {
        int ll = idx / 1536;
        int c = idx - ll * 1536;
        int tt = c >> 9, hh = (c >> 6) & 7, hss = c & 63;
        const float* bb = (tt == 0) ? bk : (tt == 1) ? bq : bv;
        g_Bqkv[idx] = bb[(ll * 8 + hh) * 64 + hss];
    }
}

__global__ void pack_rest_k(const float* __restrict__ Wp, const float* __restrict__ W1,
                            const float* __restrict__ W2, const float* __restrict__ Wlm) {
    int idx = blockIdx.x * 256 + threadIdx.x;          // < 2686976
    if (idx < 524288) {
        int l = idx >> 17, rem = idx & 131071;
        int n = rem >> 9, k = rem & 511;
        g_Wpt[idx] = tf32f(Wp[((size_t)l * 512 + k) * 256 + n]);
        return;
    }
    idx -= 524288;
    if (idx < 1048576) {
        int l = idx >> 18, rem = idx & 262143;
        int n = rem >> 8, d = rem & 255;
        g_W1t[idx] = tf32f(W1[((size_t)l * 256 + d) * 1024 + n]);
        return;
    }
    idx -= 1048576;
    if (idx < 1048576) {
        int l = idx >> 18, rem = idx & 262143;
        int n = rem >> 10, f = rem & 1023;
        g_W2t[idx] = tf32f(W2[((size_t)l * 1024 + f) * 256 + n]);
        return;
    }
    idx -= 1048576;
    if (idx < 65536) {
        int n = idx >> 8, d = idx & 255;
        g_Wlmt[idx] = tf32f(Wlm[d * 256 + n]);
    }
}

__global__ void mask_k(const int* __restrict__ dag) {
    int idx = blockIdx.x * 256 + threadIdx.x;          // < 524288
    int v = idx >> 18;
    int rem = idx & 262143;
    int i = rem >> 9;
    int j = rem & 511;
    unsigned char m = (dag[j * 512 + i] != 0 || (v && i == j)) ? 1 : 0;
    g_Amask[idx] = m;
    g_Amaskf[idx] = (float)m;
}

__global__ void xr_k(const float* __restrict__ X) {
    int i = blockIdx.x * 256 + threadIdx.x;            // < 2097152
    g_Xb[i] = tf32f(X[i]);
}

// ------------------------------- GEMM core ---------------------------------
struct GP {
    const float* A; const float* B; float* C;
    const float* bias; const float* res;
    float* dst0;
    int K, lda, ldb, ldc;
    long long sAz, sBz, sCz;
};

static const int GEMM_SMEM128 = 4 * (128 * 20 + 128 * 20) * 4;   // 81920 B
static const int GEMM_SMEM64  = 4 * (128 * 20 +  64 * 20) * 4;   // 61440 B

// MODE: 1 QKV scatter  4 bias+swish(rounded)  5 bias+res(rounded)
//       6 bias(exact)  8 bias+swish dual (C exact, dst0 rounded)
template <int BN, int MODE>
__global__ __launch_bounds__(256, 2) void gemm_tc(GP p) {
    constexpr int BM = 128, PITCH = 20, NS = 4;
    constexpr int WNW = (BN == 128) ? 4 : 2;
    constexpr int WM  = (BN == 128) ? 64 : 32;
    constexpr int WN  = 32;
    constexpr int MT = WM / 16, NT = WN / 8, NT2 = NT / 2;
    constexpr int ASZ = BM * PITCH, BSZ = BN * PITCH;

    extern __shared__ float dsm[];
    const unsigned sA = cvta_s(dsm);
    const unsigned sB = cvta_s(dsm + NS * ASZ);

    const int t = threadIdx.x, lane = t & 31, w = t >> 5;
    const int wm = w / WNW, wn = w % WNW;
    const int g = lane >> 2, cc = lane & 3;
    const int lrow = lane & 15;
    const unsigned loff = (unsigned)((lane >> 4) << 4);
    const int bx = blockIdx.x, by = blockIdx.y, bz = blockIdx.z;
    const int ar = t >> 2, ac = (t & 3) << 2;

    const float* Af = p.A + (size_t)bz * p.sAz + (size_t)by * BM * p.lda;
    const float* Bp = p.B + (size_t)bz * p.sBz + (size_t)bx * BN * p.ldb;
    float* C = p.C + (size_t)bz * p.sCz;

    float acc[MT][NT][4];
#pragma unroll
    for (int i = 0; i < MT; i++)
#pragma unroll
        for (int j = 0; j < NT; j++)
#pragma unroll
            for (int r = 0; r < 4; r++) acc[i][j][r] = 0.f;

    auto issue = [&](int ch, int s) {
        const int k0 = ch << 4;
        cpa16(sA + (unsigned)((s * ASZ + ar * PITCH + ac) * 4),
              Af + (size_t)ar * p.lda + k0 + ac);
        cpa16(sA + (unsigned)((s * ASZ + (ar + 64) * PITCH + ac) * 4),
              Af + (size_t)(ar + 64) * p.lda + k0 + ac);
        cpa16(sB + (unsigned)((s * BSZ + ar * PITCH + ac) * 4),
              Bp + (size_t)ar * p.ldb + k0 + ac);
        if (BN == 128)
            cpa16(sB + (unsigned)((s * BSZ + (ar + 64) * PITCH + ac) * 4),
                  Bp + (size_t)(ar + 64) * p.ldb + k0 + ac);
        CPA_COMMIT();
    };

    const int nch = p.K >> 4;
    issue(0, 0); issue(1, 1); issue(2, 2);
    for (int c = 0; c < nch; c++) {
        CPA_WAIT(2);
        __syncthreads();
        if (c + 3 < nch) issue(c + 3, (c + 3) & 3); else CPA_COMMIT();
        const int buf = c & 3;
#pragma unroll
        for (int ks = 0; ks < 2; ks++) {
            unsigned a[MT][4], b[NT][2];
#pragma unroll
            for (int i = 0; i < MT; i++) {
                const unsigned addr = sA + (unsigned)((buf * ASZ
                                    + (wm * WM + i * 16 + lrow) * PITCH + ks * 8) * 4) + loff;
                LDM_X4(a[i][0], a[i][1], a[i][2], a[i][3], addr);
            }
#pragma unroll
            for (int j2 = 0; j2 < NT2; j2++) {
                const unsigned addr = sB + (unsigned)((buf * BSZ
                                    + (wn * WN + j2 * 16 + lrow) * PITCH + ks * 8) * 4) + loff;
                LDM_X4(b[2 * j2][0], b[2 * j2 + 1][0], b[2 * j2][1], b[2 * j2 + 1][1], addr);
            }
#pragma unroll
            for (int i = 0; i < MT; i++)
#pragma unroll
                for (int j = 0; j < NT; j++)
                    MMA_TF32(acc[i][j], a[i], b[j]);
        }
    }

    // ------------------------------ epilogue -------------------------------
#pragma unroll
    for (int i = 0; i < MT; i++)
#pragma unroll
        for (int j = 0; j < NT; j++)
#pragma unroll
            for (int r = 0; r < 4; r++) {
                const int gm = by * BM + wm * WM + i * 16 + ((r >> 1) << 3) + g;
                const int gn = bx * BN + wn * WN + j * 8 + (cc << 1) + (r & 1);
                float v = acc[i][j][r];
                if (MODE == 1) {
                    v = swishf(v + p.bias[gn]);
                    const int tt = gn >> 9, h = (gn >> 6) & 7, hs = gn & 63;
                    const int b = gm >> 9, n = gm & 511, z = b * 8 + h;
                    if (tt == 0)      p.dst0[(size_t)(z * 512 + n) * 64 + hs] = tf32f(v);
                    else if (tt == 1) p.dst0[4194304u + (size_t)(z * 64 + hs) * 512 + n] = tf32f(v);
                    else              p.dst0[8388608u + (size_t)(z * 64 + hs) * 512 + n] = tf32f(v);
                } else if (MODE == 4) {
                    C[(size_t)gm * p.ldc + gn] = tf32f(swishf(v + p.bias[gn]));
                } else if (MODE == 5) {
                    C[(size_t)gm * p.ldc + gn] =
                        tf32f(v + p.bias[gn] + p.res[(size_t)gm * p.ldc + gn]);
                } else if (MODE == 6) {
                    C[(size_t)gm * p.ldc + gn] = v + p.bias[gn];
                } else {   // MODE 8
                    const float e = swishf(v + p.bias[gn]);
                    C[(size_t)gm * p.ldc + gn] = e;
                    p.dst0[(size_t)gm * p.ldc + gn] = tf32f(e);
                }
            }
}

// ------------- fused attention: AQ + scores + softmax + PV -----------------
// Grid (8 i-tiles, 128 z), 512 threads (16 warps).
// smem floats: S 64x516 @0 | At 64x68 @33024 | Bt @37376 (17408 floats)
static const int ATTN_SMEM = (33024 + 4352 + 17408) * 4;   // 219136 B

__global__ __launch_bounds__(512) void attn_k(
    const float* __restrict__ Qt, const float* __restrict__ Kb,
    const float* __restrict__ Vt, const unsigned char* __restrict__ Mk,
    const float* __restrict__ Mf, float* __restrict__ Ob) {
    extern __shared__ float sm[];
    float* S  = sm;
    float* At = sm + 33024;

    const int t = threadIdx.x, lane = t & 31, w = t >> 5;     // w: 0..15
    const int g = lane >> 2, cc = lane & 3;
    const int lrow = lane & 15;
    const unsigned loff = (unsigned)((lane >> 4) << 4);
    const int i0 = blockIdx.x * 64, z = blockIdx.y;

    const float* Qz = Qt + (size_t)z * 32768;                 // 64(hs) x 512(n)
    const float* Kp = Kb + (size_t)z * 32768;                 // 512 x 64
    const float* Vz = Vt + (size_t)z * 32768;                 // 64 x 512

    const unsigned sS = cvta_s(S);
    const unsigned sA = cvta_s(At);
    const unsigned sB = cvta_s(sm + 37376);
    const unsigned sM = sB;                                   // mask tiles 2x(64x36)
    const unsigned sQ = sB + 4608u * 4;                       // Q tiles    2x(64x36)

    auto issueK = [&](int jc, int s) {
#pragma unroll
        for (int i = 0; i < 4; i++) {
            const int idx = i * 512 + t;
            const int r = idx >> 4, c = (idx & 15) << 2;
            cpa16(sB + (unsigned)((s * 8704 + r * 68 + c) * 4),
                  Kp + (size_t)(jc * 128 + r) * 64 + c);
        }
        CPA_COMMIT();
    };

    // ========== phase 0: At = maskf[i0:+64,:] @ Qz^T  (K=512, BK=32) =======
    {
        const int wm = w >> 2, wn = w & 3;      // 4x4 warps: 16 x 16 out each
        float acc[2][4];
#pragma unroll
        for (int j = 0; j < 2; j++)
#pragma unroll
            for (int r = 0; r < 4; r++) acc[j][r] = 0.f;

        auto issueMQ = [&](int kc, int s) {
            const int k0 = kc << 5;
            const int r = t >> 3, c = (t & 7) << 2;
            cpa16(sM + (unsigned)((s * 2304 + r * 36 + c) * 4),
                  Mf + (size_t)(i0 + r) * 512 + k0 + c);
            cpa16(sQ + (unsigned)((s * 2304 + r * 36 + c) * 4),
                  Qz + (size_t)r * 512 + k0 + c);
            CPA_COMMIT();
        };
        issueMQ(0, 0);
        for (int kc = 0; kc < 16; kc++) {
            if (kc + 1 < 16) issueMQ(kc + 1, (kc + 1) & 1); else CPA_COMMIT();
            CPA_WAIT(1);
            __syncthreads();
            const int buf = kc & 1;
#pragma unroll
            for (int ks = 0; ks < 4; ks++) {
                unsigned a[4], b[2][2];
                LDM_X4(a[0], a[1], a[2], a[3],
                       sM + (unsigned)((buf * 2304 + (wm * 16 + lrow) * 36 + ks * 8) * 4) + loff);
                LDM_X4(b[0][0], b[1][0], b[0][1], b[1][1],
                       sQ + (unsigned)((buf * 2304 + (wn * 16 + lrow) * 36 + ks * 8) * 4) + loff);
                MMA_TF32(acc[0], a, b[0]);
                MMA_TF32(acc[1], a, b[1]);
            }
            __syncthreads();
        }
        // overlap: start K chunk 0 for phase 1
        issueK(0, 0);
        // epilogue -> At (pitch 68), tf32-rounded (same values AQ4 held)
#pragma unroll
        for (int j = 0; j < 2; j++)
#pragma unroll
            for (int r = 0; r < 4; r++) {
                const int gm = wm * 16 + ((r >> 1) << 3) + g;
                const int gn = wn * 16 + j * 8 + (cc << 1) + (r & 1);
                At[gm * 68 + gn] = tf32f(acc[j][r]);
            }
    }

    // ================= phase 1: S = At @ K^T, mask+scale ====================
    {
        const int wm = w >> 2, wn = w & 3;      // 4x4 warps: 16 rows x 32 cols
        float acc[4][4];
        for (int jc = 0; jc < 4; jc++) {
            if (jc + 1 < 4) issueK(jc + 1, (jc + 1) & 1); else CPA_COMMIT();
            CPA_WAIT(1);
            __syncthreads();
#pragma unroll
            for (int j = 0; j < 4; j++)
#pragma unroll
                for (int r = 0; r < 4; r++) acc[j][r] = 0.f;
            const int buf = jc & 1;
#pragma unroll
            for (int ks = 0; ks < 8; ks++) {
                unsigned a[4], b[4][2];
                {
                    const unsigned addr = sA + (unsigned)(((wm * 16 + lrow) * 68
                                        + ks * 8) * 4) + loff;
                    LDM_X4(a[0], a[1], a[2], a[3], addr);
                }
#pragma unroll
                for (int j2 = 0; j2 < 2; j2++) {
                    const unsigned addr = sB + (unsigned)((buf * 8704
                                        + (wn * 32 + j2 * 16 + lrow) * 68 + ks * 8) * 4) + loff;
                    LDM_X4(b[2 * j2][0], b[2 * j2 + 1][0], b[2 * j2][1], b[2 * j2 + 1][1], addr);
                }
#pragma unroll
                for (int j = 0; j < 4; j++)
                    MMA_TF32(acc[j], a, b[j]);
            }
            // epilogue: mask+scale -> S
#pragma unroll
            for (int j = 0; j < 4; j++)
#pragma unroll
                for (int r = 0; r < 4; r++) {
                    const int gm = wm * 16 + ((r >> 1) << 3) + g;
                    const int gn = jc * 128 + wn * 32 + j * 8 + (cc << 1) + (r & 1);
                    const float v = acc[j][r];
                    S[gm * 516 + gn] =
                        Mk[(size_t)(i0 + gm) * 512 + gn] ? v * 0.125f : -3.0e38f;
                }
            __syncthreads();
        }
    }

    // ---- overlap: start V chunk 0 copy before softmax ----
    auto issueV = [&](int kc, int s) {
#pragma unroll
        for (int i = 0; i < 4; i++) {
            const int idx = i * 512 + t;
            const int r = idx >> 5, c = (idx & 31) << 2;
            cpa16(sB + (unsigned)((s * 8448 + r * 132 + c) * 4),
                  Vz + (size_t)r * 512 + kc * 128 + c);
        }
        CPA_COMMIT();
    };
    issueV(0, 0);

    // ================= phase 2: exact softmax + (P + A), tf32 ===============
    for (int it = 0; it < 4; it++) {
        const int ir = it * 16 + w;
        float* r = S + ir * 516;
        const unsigned char* mr = Mk + (size_t)(i0 + ir) * 512;
        float x[16];
        float m = -3.4e38f;
#pragma unroll
        for (int k = 0; k < 16; k++) { x[k] = r[k * 32 + lane]; m = fmaxf(m, x[k]); }
#pragma unroll
        for (int o = 16; o; o >>= 1) m = fmaxf(m, __shfl_xor_sync(0xffffffffu, m, o));
        if (m <= -1e37f) {
#pragma unroll
            for (int k = 0; k < 16; k++) r[k * 32 + lane] = 0.f;
        } else {
            float s = 0.f;
#pragma unroll
            for (int k = 0; k < 16; k++) { x[k] = __expf(x[k] - m); s += x[k]; }
#pragma unroll
            for (int o = 16; o; o >>= 1) s += __shfl_xor_sync(0xffffffffu, s, o);
            const float inv = 1.f / s;
#pragma unroll
            for (int k = 0; k < 16; k++)
                r[k * 32 + lane] = tf32f(x[k] * inv + (float)mr[k * 32 + lane]);
        }
    }
    __syncthreads();

    // ================= phase 3: O = Ssm @ V^T (4 x K=128 chunks) ============
    {
        const int wm = w >> 2, wn = w & 3;      // 4x4 warps: 16 rows x 16 cols
        float oa[2][4];
#pragma unroll
        for (int j = 0; j < 2; j++)
#pragma unroll
            for (int r = 0; r < 4; r++) oa[j][r] = 0.f;
        for (int kc = 0; kc < 4; kc++) {
            if (kc + 1 < 4) issueV(kc + 1, (kc + 1) & 1); else CPA_COMMIT();
            CPA_WAIT(1);
            __syncthreads();
            const int buf = kc & 1;
#pragma unroll
            for (int ks = 0; ks < 16; ks++) {
                unsigned a[4], b[2][2];
                {
                    const unsigned addr = sS + (unsigned)(((wm * 16 + lrow) * 516
                                        + kc * 128 + ks * 8) * 4) + loff;
                    LDM_X4(a[0], a[1], a[2], a[3], addr);
                }
                {
                    const unsigned addr = sB + (unsigned)((buf * 8448
                                        + (wn * 16 + lrow) * 132 + ks * 8) * 4) + loff;
                    LDM_X4(b[0][0], b[1][0], b[0][1], b[1][1], addr);
                }
#pragma unroll
                for (int j = 0; j < 2; j++)
                    MMA_TF32(oa[j], a, b[j]);
            }
            __syncthreads();
        }
        // epilogue -> Ob[(b*512 + i)][(h*64 + hs)]  (rounded)
        const int b = z >> 3, h = z & 7;
#pragma unroll
        for (int j = 0; j < 2; j++)
#pragma unroll
            for (int r = 0; r < 4; r++) {
                const int gm = wm * 16 + ((r >> 1) << 3) + g;
                const int gn = wn * 16 + j * 8 + (cc << 1) + (r & 1);
                Ob[(size_t)(b * 512 + i0 + gm) * 512 + h * 64 + gn] = tf32f(oa[j][r]);
            }
    }
}

// ------------------------------ host driver --------------------------------
extern "C" void kernel_launch(void* const* d_in, const int* in_sizes, int n_in,
                              void* d_out, int out_size) {
    (void)in_sizes; (void)n_in; (void)out_size;
    const float* X   = (const float*)d_in[0];
    const int*   dag = (const int*)d_in[1];
    const float* Wk  = (const float*)d_in[2],  *bk  = (const float*)d_in[3];
    const float* Wq  = (const float*)d_in[4],  *bq  = (const float*)d_in[5];
    const float* Wv  = (const float*)d_in[6],  *bv  = (const float*)d_in[7];
    const float* Wp  = (const float*)d_in[8],  *bp  = (const float*)d_in[9];
    const float* W1  = (const float*)d_in[10], *b1  = (const float*)d_in[11];
    const float* W2  = (const float*)d_in[12], *b2  = (const float*)d_in[13];
    const float* Wlm = (const float*)d_in[14], *blm = (const float*)d_in[15];
    float* out = (float*)d_out;

    cudaFuncSetAttribute(gemm_tc<128, 1>, cudaFuncAttributeMaxDynamicSharedMemorySize, GEMM_SMEM128);
    cudaFuncSetAttribute(gemm_tc<128, 4>, cudaFuncAttributeMaxDynamicSharedMemorySize, GEMM_SMEM128);
    cudaFuncSetAttribute(gemm_tc<64, 8>,  cudaFuncAttributeMaxDynamicSharedMemorySize, GEMM_SMEM64);
    cudaFuncSetAttribute(gemm_tc<64, 5>,  cudaFuncAttributeMaxDynamicSharedMemorySize, GEMM_SMEM64);
    cudaFuncSetAttribute(gemm_tc<64, 6>,  cudaFuncAttributeMaxDynamicSharedMemorySize, GEMM_SMEM64);
    cudaFuncSetAttribute(attn_k, cudaFuncAttributeMaxDynamicSharedMemorySize, ATTN_SMEM);

    void* pv;
    cudaGetSymbolAddress(&pv, g_Wqkvt); float* Wqkvt = (float*)pv;
    cudaGetSymbolAddress(&pv, g_Bqkv);  float* Bqkv  = (float*)pv;
    cudaGetSymbolAddress(&pv, g_Wpt);   float* Wpt   = (float*)pv;
    cudaGetSymbolAddress(&pv, g_W1t);   float* W1t   = (float*)pv;
    cudaGetSymbolAddress(&pv, g_W2t);   float* W2t   = (float*)pv;
    cudaGetSymbolAddress(&pv, g_Wlmt);  float* Wlmt  = (float*)pv;
    cudaGetSymbolAddress(&pv, g_Amask); unsigned char* Amask = (unsigned char*)pv;
    cudaGetSymbolAddress(&pv, g_Amaskf); float* Amaskf = (float*)pv;
    cudaGetSymbolAddress(&pv, g_KQV);   float* KQV = (float*)pv;
    cudaGetSymbolAddress(&pv, g_Ob);    float* Ob  = (float*)pv;
    cudaGetSymbolAddress(&pv, g_Mha);   float* Mha = (float*)pv;
    cudaGetSymbolAddress(&pv, g_Mhar);  float* Mhar = (float*)pv;
    cudaGetSymbolAddress(&pv, g_Ff);    float* Ff  = (float*)pv;
    cudaGetSymbolAddress(&pv, g_Xb);    float* Xb  = (float*)pv;

    pack_qkv_k<<<6144, 256>>>(Wk, Wq, Wv, bk, bq, bv);
    pack_rest_k<<<10496, 256>>>(Wp, W1, W2, Wlm);
    mask_k<<<2048, 256>>>(dag);
    xr_k<<<8192, 256>>>(X);

    for (int l = 0; l < 4; l++) {
        const unsigned char* Am = Amask + (l ? 262144 : 0);
        const float* Amf = Amaskf + (l ? 262144 : 0);
        {   // QKV: Xb @ Wqkvt^T -> scatter K/Qt/Vt (+bias+swish, rounded)
            GP p{}; p.A = Xb; p.lda = 256;
            p.B = Wqkvt + (size_t)l * 1536 * 256; p.ldb = 256;
            p.bias = Bqkv + l * 1536; p.dst0 = KQV; p.K = 256;
            gemm_tc<128, 1><<<dim3(12, 64, 1), 256, GEMM_SMEM128>>>(p);
        }
        // fused AQ + scores + softmax + PV
        attn_k<<<dim3(8, 128), 512, ATTN_SMEM>>>(
            KQV + 4194304, KQV, KQV + 2 * 4194304, Am, Amf, Ob);
        {   // mha = swish(Ob @ Wpt^T + bp): Mha exact + Mhar rounded
            GP p{}; p.A = Ob; p.lda = 512;
            p.B = Wpt + (size_t)l * 256 * 512; p.ldb = 512;
            p.bias = bp + l * 256; p.C = Mha; p.ldc = 256; p.dst0 = Mhar; p.K = 512;
            gemm_tc<64, 8><<<dim3(4, 64, 1), 256, GEMM_SMEM64>>>(p);
        }
        {   // ff = swish(Mhar @ W1t^T + b1)  (rounded)
            GP p{}; p.A = Mhar; p.lda = 256;
            p.B = W1t + (size_t)l * 1024 * 256; p.ldb = 256;
            p.bias = b1 + l * 1024; p.C = Ff; p.ldc = 1024; p.K = 256;
            gemm_tc<128, 4><<<dim3(8, 64, 1), 256, GEMM_SMEM128>>>(p);
        }
        {   // Xb = Ff @ W2t^T + b2 + Mha  (rounded)
            GP p{}; p.A = Ff; p.lda = 1024;
            p.B = W2t + (size_t)l * 256 * 1024; p.ldb = 1024;
            p.bias = b2 + l * 256; p.res = Mha; p.C = Xb; p.ldc = 256; p.K = 1024;
            gemm_tc<64, 5><<<dim3(4, 64, 1), 256, GEMM_SMEM64>>>(p);
        }
    }
    {   // lm head (exact output)
        GP p{}; p.A = Xb; p.lda = 256; p.B = Wlmt; p.ldb = 256;
        p.bias = blm; p.C = out; p.ldc = 256; p.K = 256;
        gemm_tc<64, 6><<<dim3(4, 64, 1), 256, GEMM_SMEM64>>>(p);
    }
}

// round 12
// speedup vs baseline: 1.0031x; 1.0031x over previous
#include <cuda_runtime.h>
#include <cstdint>

// ---------------------------------------------------------------------------
// CaT transformer, tf32 mma.sync (portable sm_100 target).
// R12: R10 structure (standalone AQ GEMM) + attention kernel re-tiled to
// 32 rows/CTA so 2 CTAs/SM co-reside (smem 109.5 KB). Bit-exact numerics
// (oracle rel_err 7.903782e-4).
// ---------------------------------------------------------------------------

#define DI __device__ __forceinline__

static DI float swishf(float x) { return x / (1.f + __expf(-x)); }

// ------------------------- static device scratch ---------------------------
__device__ float g_Wqkvt[4 * 1536 * 256];   // tf32
__device__ float g_Bqkv [4 * 1536];
__device__ float g_Wpt  [4 * 256 * 512];    // tf32
__device__ float g_W1t  [4 * 1024 * 256];   // tf32
__device__ float g_W2t  [4 * 256 * 1024];   // tf32
__device__ float g_Wlmt [256 * 256];        // tf32
__device__ unsigned char g_Amask[2 * 512 * 512];
__device__ float g_Amaskf[2 * 512 * 512];   // 0.0 / 1.0
__device__ float g_KQV[3 * 512 * 8192];     // K | Qt | Vt (tf32)
__device__ float g_AQ4[512 * 8192];         // [z][i][hs] tf32
__device__ float g_Ob [8192 * 512];         // tf32
__device__ float g_Mha[8192 * 256];         // exact residual
__device__ float g_Mhar[8192 * 256];        // tf32
__device__ float g_Ff [8192 * 1024];        // tf32
__device__ float g_Xb [8192 * 256];         // tf32

// --------------------------- helpers ---------------------------------------
DI unsigned tf32_rn(float x) {
    unsigned r;
    asm("cvt.rn.tf32.f32 %0, %1;" : "=r"(r) : "f"(x));
    return r;
}
DI float tf32f(float x) { return __uint_as_float(tf32_rn(x)); }
DI unsigned cvta_s(const void* p) { return (unsigned)__cvta_generic_to_shared(p); }
DI void cpa16(unsigned dst, const void* src) {
    asm volatile("cp.async.cg.shared.global [%0], [%1], 16;" :: "r"(dst), "l"(src) : "memory");
}
#define CPA_COMMIT() asm volatile("cp.async.commit_group;" ::: "memory")
#define CPA_WAIT(N)  asm volatile("cp.async.wait_group %0;" :: "n"(N) : "memory")

#define LDM_X4(r0, r1, r2, r3, addr) \
    asm volatile("ldmatrix.sync.aligned.m8n8.x4.shared.b16 {%0,%1,%2,%3}, [%4];" \
                 : "=r"(r0), "=r"(r1), "=r"(r2), "=r"(r3) : "r"(addr))
#define MMA_TF32(d, a, b) \
    asm volatile("mma.sync.aligned.m16n8k8.row.col.f32.tf32.tf32.f32 " \
                 "{%0,%1,%2,%3}, {%4,%5,%6,%7}, {%8,%9}, {%0,%1,%2,%3};" \
                 : "+f"((d)[0]), "+f"((d)[1]), "+f"((d)[2]), "+f"((d)[3]) \
                 : "r"((a)[0]), "r"((a)[1]), "r"((a)[2]), "r"((a)[3]), \
                   "r"((b)[0]), "r"((b)[1]))

// ------------------------------ prep kernels -------------------------------
__global__ void pack_qkv_k(const float* __restrict__ Wk, const float* __restrict__ Wq,
                           const float* __restrict__ Wv, const float* __restrict__ bk,
                           const float* __restrict__ bq, const float* __restrict__ bv) {
    int idx = blockIdx.x * 256 + threadIdx.x;          // < 1572864
    int l = idx / 393216;
    int rem = idx - l * 393216;
    int r = rem >> 8;
    int d = rem & 255;
    int t = r >> 9, h = (r >> 6) & 7, hs = r & 63;
    const float* W = (t == 0) ? Wk : (t == 1) ? Wq : Wv;
    g_Wqkvt[idx] = tf32f(W[(((size_t)(l * 8 + h)) * 256 + d) * 64 + hs]);
    if (idx < 4 * 1536) {
        int ll = idx / 1536;
        int c = idx - ll * 1536;
        int tt = c >> 9, hh = (c >> 6) & 7, hss = c & 63;
        const float* bb = (tt == 0) ? bk : (tt == 1) ? bq : bv;
        g_Bqkv[idx] = bb[(ll * 8 + hh) * 64 + hss];
    }
}

__global__ void pack_rest_k(const float* __restrict__ Wp, const float* __restrict__ W1,
                            const float* __restrict__ W2, const float* __restrict__ Wlm) {
    int idx = blockIdx.x * 256 + threadIdx.x;          // < 2686976
    if (idx < 524288) {
        int l = idx >> 17, rem = idx & 131071;
        int n = rem >> 9, k = rem & 511;
        g_Wpt[idx] = tf32f(Wp[((size_t)l * 512 + k) * 256 + n]);
        return;
    }
    idx -= 524288;
    if (idx < 1048576) {
        int l = idx >> 18, rem = idx & 262143;
        int n = rem >> 8, d = rem & 255;
        g_W1t[idx] = tf32f(W1[((size_t)l * 256 + d) * 1024 + n]);
        return;
    }
    idx -= 1048576;
    if (idx < 1048576) {
        int l = idx >> 18, rem = idx & 262143;
        int n = rem >> 10, f = rem & 1023;
        g_W2t[idx] = tf32f(W2[((size_t)l * 1024 + f) * 256 + n]);
        return;
    }
    idx -= 1048576;
    if (idx < 65536) {
        int n = idx >> 8, d = idx & 255;
        g_Wlmt[idx] = tf32f(Wlm[d * 256 + n]);
    }
}

__global__ void mask_k(const int* __restrict__ dag) {
    int idx = blockIdx.x * 256 + threadIdx.x;          // < 524288
    int v = idx >> 18;
    int rem = idx & 262143;
    int i = rem >> 9;
    int j = rem & 511;
    unsigned char m = (dag[j * 512 + i] != 0 || (v && i == j)) ? 1 : 0;
    g_Amask[idx] = m;
    g_Amaskf[idx] = (float)m;
}

__global__ void xr_k(const float* __restrict__ X) {
    int i = blockIdx.x * 256 + threadIdx.x;            // < 2097152
    g_Xb[i] = tf32f(X[i]);
}

// ------------------------------- GEMM core ---------------------------------
struct GP {
    const float* A; const float* B; float* C;
    const float* bias; const float* res;
    float* dst0;
    int K, lda, ldb, ldc;
    long long sAz, sBz, sCz;
};

static const int GEMM_SMEM128 = 4 * (128 * 20 + 128 * 20) * 4;   // 81920 B
static const int GEMM_SMEM64  = 4 * (128 * 20 +  64 * 20) * 4;   // 61440 B

// MODE: 1 QKV scatter  3 AQ scatter  4 bias+swish(rounded)  5 bias+res(rounded)
//       6 bias(exact)  8 bias+swish dual (C exact, dst0 rounded)
template <int BN, int MODE>
__global__ __launch_bounds__(256, 2) void gemm_tc(GP p) {
    constexpr int BM = 128, PITCH = 20, NS = 4;
    constexpr int WNW = (BN == 128) ? 4 : 2;
    constexpr int WM  = (BN == 128) ? 64 : 32;
    constexpr int WN  = 32;
    constexpr int MT = WM / 16, NT = WN / 8, NT2 = NT / 2;
    constexpr int ASZ = BM * PITCH, BSZ = BN * PITCH;

    extern __shared__ float dsm[];
    const unsigned sA = cvta_s(dsm);
    const unsigned sB = cvta_s(dsm + NS * ASZ);

    const int t = threadIdx.x, lane = t & 31, w = t >> 5;
    const int wm = w / WNW, wn = w % WNW;
    const int g = lane >> 2, cc = lane & 3;
    const int lrow = lane & 15;
    const unsigned loff = (unsigned)((lane >> 4) << 4);
    const int bx = blockIdx.x, by = blockIdx.y, bz = blockIdx.z;
    const int ar = t >> 2, ac = (t & 3) << 2;

    const float* Af = p.A + (size_t)bz * p.sAz + (size_t)by * BM * p.lda;
    const float* Bp = p.B + (size_t)bz * p.sBz + (size_t)bx * BN * p.ldb;
    float* C = p.C + (size_t)bz * p.sCz;

    float acc[MT][NT][4];
#pragma unroll
    for (int i = 0; i < MT; i++)
#pragma unroll
        for (int j = 0; j < NT; j++)
#pragma unroll
            for (int r = 0; r < 4; r++) acc[i][j][r] = 0.f;

    auto issue = [&](int ch, int s) {
        const int k0 = ch << 4;
        cpa16(sA + (unsigned)((s * ASZ + ar * PITCH + ac) * 4),
              Af + (size_t)ar * p.lda + k0 + ac);
        cpa16(sA + (unsigned)((s * ASZ + (ar + 64) * PITCH + ac) * 4),
              Af + (size_t)(ar + 64) * p.lda + k0 + ac);
        cpa16(sB + (unsigned)((s * BSZ + ar * PITCH + ac) * 4),
              Bp + (size_t)ar * p.ldb + k0 + ac);
        if (BN == 128)
            cpa16(sB + (unsigned)((s * BSZ + (ar + 64) * PITCH + ac) * 4),
                  Bp + (size_t)(ar + 64) * p.ldb + k0 + ac);
        CPA_COMMIT();
    };

    const int nch = p.K >> 4;
    issue(0, 0); issue(1, 1); issue(2, 2);
    for (int c = 0; c < nch; c++) {
        CPA_WAIT(2);
        __syncthreads();
        if (c + 3 < nch) issue(c + 3, (c + 3) & 3); else CPA_COMMIT();
        const int buf = c & 3;
#pragma unroll
        for (int ks = 0; ks < 2; ks++) {
            unsigned a[MT][4], b[NT][2];
#pragma unroll
            for (int i = 0; i < MT; i++) {
                const unsigned addr = sA + (unsigned)((buf * ASZ
                                    + (wm * WM + i * 16 + lrow) * PITCH + ks * 8) * 4) + loff;
                LDM_X4(a[i][0], a[i][1], a[i][2], a[i][3], addr);
            }
#pragma unroll
            for (int j2 = 0; j2 < NT2; j2++) {
                const unsigned addr = sB + (unsigned)((buf * BSZ
                                    + (wn * WN + j2 * 16 + lrow) * PITCH + ks * 8) * 4) + loff;
                LDM_X4(b[2 * j2][0], b[2 * j2 + 1][0], b[2 * j2][1], b[2 * j2 + 1][1], addr);
            }
#pragma unroll
            for (int i = 0; i < MT; i++)
#pragma unroll
                for (int j = 0; j < NT; j++)
                    MMA_TF32(acc[i][j], a[i], b[j]);
        }
    }

    // ------------------------------ epilogue -------------------------------
#pragma unroll
    for (int i = 0; i < MT; i++)
#pragma unroll
        for (int j = 0; j < NT; j++)
#pragma unroll
            for (int r = 0; r < 4; r++) {
                const int gm = by * BM + wm * WM + i * 16 + ((r >> 1) << 3) + g;
                const int gn = bx * BN + wn * WN + j * 8 + (cc << 1) + (r & 1);
                float v = acc[i][j][r];
                if (MODE == 1) {
                    v = swishf(v + p.bias[gn]);
                    const int tt = gn >> 9, h = (gn >> 6) & 7, hs = gn & 63;
                    const int b = gm >> 9, n = gm & 511, z = b * 8 + h;
                    if (tt == 0)      p.dst0[(size_t)(z * 512 + n) * 64 + hs] = tf32f(v);
                    else if (tt == 1) p.dst0[4194304u + (size_t)(z * 64 + hs) * 512 + n] = tf32f(v);
                    else              p.dst0[8388608u + (size_t)(z * 64 + hs) * 512 + n] = tf32f(v);
                } else if (MODE == 3) {
                    p.C[(size_t)(gn >> 6) * 32768 + (size_t)gm * 64 + (gn & 63)] = tf32f(v);
                } else if (MODE == 4) {
                    C[(size_t)gm * p.ldc + gn] = tf32f(swishf(v + p.bias[gn]));
                } else if (MODE == 5) {
                    C[(size_t)gm * p.ldc + gn] =
                        tf32f(v + p.bias[gn] + p.res[(size_t)gm * p.ldc + gn]);
                } else if (MODE == 6) {
                    C[(size_t)gm * p.ldc + gn] = v + p.bias[gn];
                } else {   // MODE 8
                    const float e = swishf(v + p.bias[gn]);
                    C[(size_t)gm * p.ldc + gn] = e;
                    p.dst0[(size_t)gm * p.ldc + gn] = tf32f(e);
                }
            }
}

// ------------------- fused attention: scores+softmax+PV --------------------
// Grid (16 i-tiles, 128 z), 256 threads (8 warps), 2 CTAs/SM.
// smem floats: S 32x516 @0 | At 32x68 @16512 | Bt 2x(64x68) @18688
static const int ATTN_SMEM = (16512 + 2176 + 8704) * 4;   // 109568 B

__global__ __launch_bounds__(256, 2) void attn_k(
    const float* __restrict__ AQ, const float* __restrict__ Kb,
    const float* __restrict__ Vt, const unsigned char* __restrict__ Mk,
    float* __restrict__ Ob) {
    extern __shared__ float sm[];
    float* S = sm;

    const int t = threadIdx.x, lane = t & 31, w = t >> 5;     // w: 0..7
    const int g = lane >> 2, cc = lane & 3;
    const int lrow = lane & 15;
    const unsigned loff = (unsigned)((lane >> 4) << 4);
    const int i0 = blockIdx.x * 32, z = blockIdx.y;
    const int wm = w >> 2, wn = w & 3;      // 2x4 warps: 16 rows x 16 cols

    const float* AQz = AQ + (size_t)z * 32768 + (size_t)i0 * 64;   // 32 x 64
    const float* Kp  = Kb + (size_t)z * 32768;                     // 512 x 64
    const float* Vz  = Vt + (size_t)z * 32768;                     // 64 x 512

    const unsigned sS = cvta_s(S);
    const unsigned sA = cvta_s(sm + 16512);
    const unsigned sB = cvta_s(sm + 18688);

    // ---- prologue: cp.async At (32x64 -> pitch 68) + K chunk 0 ------------
#pragma unroll
    for (int i = 0; i < 2; i++) {
        const int idx = i * 256 + t;
        const int r = idx >> 4, c = (idx & 15) << 2;
        cpa16(sA + (unsigned)((r * 68 + c) * 4), AQz + (size_t)r * 64 + c);
    }
    auto issueK = [&](int jc, int s) {
#pragma unroll
        for (int i = 0; i < 4; i++) {
            const int idx = i * 256 + t;
            const int r = idx >> 4, c = (idx & 15) << 2;
            cpa16(sB + (unsigned)((s * 4352 + r * 68 + c) * 4),
                  Kp + (size_t)(jc * 64 + r) * 64 + c);
        }
        CPA_COMMIT();
    };
    issueK(0, 0);   // single group: At + K0

    // ================= phase 1: S = At @ K^T, mask+scale ====================
    // 8 column chunks of 64; full K=64 accumulation inside each chunk.
    {
        float acc[2][4];
        for (int jc = 0; jc < 8; jc++) {
            if (jc + 1 < 8) issueK(jc + 1, (jc + 1) & 1); else CPA_COMMIT();
            CPA_WAIT(1);
            __syncthreads();
#pragma unroll
            for (int j = 0; j < 2; j++)
#pragma unroll
                for (int r = 0; r < 4; r++) acc[j][r] = 0.f;
            const int buf = jc & 1;
#pragma unroll
            for (int ks = 0; ks < 8; ks++) {
                unsigned a[4], b[2][2];
                LDM_X4(a[0], a[1], a[2], a[3],
                       sA + (unsigned)(((wm * 16 + lrow) * 68 + ks * 8) * 4) + loff);
                LDM_X4(b[0][0], b[1][0], b[0][1], b[1][1],
                       sB + (unsigned)((buf * 4352 + (wn * 16 + lrow) * 68 + ks * 8) * 4) + loff);
                MMA_TF32(acc[0], a, b[0]);
                MMA_TF32(acc[1], a, b[1]);
            }
            // epilogue: mask+scale -> S
#pragma unroll
            for (int j = 0; j < 2; j++)
#pragma unroll
                for (int r = 0; r < 4; r++) {
                    const int gm = wm * 16 + ((r >> 1) << 3) + g;
                    const int gn = jc * 64 + wn * 16 + j * 8 + (cc << 1) + (r & 1);
                    const float v = acc[j][r];
                    S[gm * 516 + gn] =
                        Mk[(size_t)(i0 + gm) * 512 + gn] ? v * 0.125f : -3.0e38f;
                }
            __syncthreads();
        }
    }

    // ---- overlap: start V chunk 0 copy before softmax ----
    auto issueV = [&](int kc, int s) {
#pragma unroll
        for (int i = 0; i < 4; i++) {
            const int idx = i * 256 + t;
            const int r = idx >> 4, c = (idx & 15) << 2;
            cpa16(sB + (unsigned)((s * 4352 + r * 68 + c) * 4),
                  Vz + (size_t)r * 512 + kc * 64 + c);
        }
        CPA_COMMIT();
    };
    issueV(0, 0);

    // ================= phase 2: exact softmax + (P + A), tf32 ===============
    for (int it = 0; it < 4; it++) {
        const int ir = it * 8 + w;
        float* r = S + ir * 516;
        const unsigned char* mr = Mk + (size_t)(i0 + ir) * 512;
        float x[16];
        float m = -3.4e38f;
#pragma unroll
        for (int k = 0; k < 16; k++) { x[k] = r[k * 32 + lane]; m = fmaxf(m, x[k]); }
#pragma unroll
        for (int o = 16; o; o >>= 1) m = fmaxf(m, __shfl_xor_sync(0xffffffffu, m, o));
        if (m <= -1e37f) {
#pragma unroll
            for (int k = 0; k < 16; k++) r[k * 32 + lane] = 0.f;
        } else {
            float s = 0.f;
#pragma unroll
            for (int k = 0; k < 16; k++) { x[k] = __expf(x[k] - m); s += x[k]; }
#pragma unroll
            for (int o = 16; o; o >>= 1) s += __shfl_xor_sync(0xffffffffu, s, o);
            const float inv = 1.f / s;
#pragma unroll
            for (int k = 0; k < 16; k++)
                r[k * 32 + lane] = tf32f(x[k] * inv + (float)mr[k * 32 + lane]);
        }
    }
    __syncthreads();

    // ================= phase 3: O = Ssm @ V^T (8 x K=64 chunks) =============
    {
        float oa[2][4];
#pragma unroll
        for (int j = 0; j < 2; j++)
#pragma unroll
            for (int r = 0; r < 4; r++) oa[j][r] = 0.f;
        for (int kc = 0; kc < 8; kc++) {
            if (kc + 1 < 8) issueV(kc + 1, (kc + 1) & 1); else CPA_COMMIT();
            CPA_WAIT(1);
            __syncthreads();
            const int buf = kc & 1;
#pragma unroll
            for (int ks = 0; ks < 8; ks++) {
                unsigned a[4], b[2][2];
                LDM_X4(a[0], a[1], a[2], a[3],
                       sS + (unsigned)(((wm * 16 + lrow) * 516 + kc * 64 + ks * 8) * 4) + loff);
                LDM_X4(b[0][0], b[1][0], b[0][1], b[1][1],
                       sB + (unsigned)((buf * 4352 + (wn * 16 + lrow) * 68 + ks * 8) * 4) + loff);
                MMA_TF32(oa[0], a, b[0]);
                MMA_TF32(oa[1], a, b[1]);
            }
            __syncthreads();
        }
        // epilogue -> Ob[(b*512 + i)][(h*64 + hs)]  (rounded)
        const int b = z >> 3, h = z & 7;
#pragma unroll
        for (int j = 0; j < 2; j++)
#pragma unroll
            for (int r = 0; r < 4; r++) {
                const int gm = wm * 16 + ((r >> 1) << 3) + g;
                const int gn = wn * 16 + j * 8 + (cc << 1) + (r & 1);
                Ob[(size_t)(b * 512 + i0 + gm) * 512 + h * 64 + gn] = tf32f(oa[j][r]);
            }
    }
}

// ------------------------------ host driver --------------------------------
extern "C" void kernel_launch(void* const* d_in, const int* in_sizes, int n_in,
                              void* d_out, int out_size) {
    (void)in_sizes; (void)n_in; (void)out_size;
    const float* X   = (const float*)d_in[0];
    const int*   dag = (const int*)d_in[1];
    const float* Wk  = (const float*)d_in[2],  *bk  = (const float*)d_in[3];
    const float* Wq  = (const float*)d_in[4],  *bq  = (const float*)d_in[5];
    const float* Wv  = (const float*)d_in[6],  *bv  = (const float*)d_in[7];
    const float* Wp  = (const float*)d_in[8],  *bp  = (const float*)d_in[9];
    const float* W1  = (const float*)d_in[10], *b1  = (const float*)d_in[11];
    const float* W2  = (const float*)d_in[12], *b2  = (const float*)d_in[13];
    const float* Wlm = (const float*)d_in[14], *blm = (const float*)d_in[15];
    float* out = (float*)d_out;

    cudaFuncSetAttribute(gemm_tc<128, 1>, cudaFuncAttributeMaxDynamicSharedMemorySize, GEMM_SMEM128);
    cudaFuncSetAttribute(gemm_tc<128, 3>, cudaFuncAttributeMaxDynamicSharedMemorySize, GEMM_SMEM128);
    cudaFuncSetAttribute(gemm_tc<128, 4>, cudaFuncAttributeMaxDynamicSharedMemorySize, GEMM_SMEM128);
    cudaFuncSetAttribute(gemm_tc<64, 8>,  cudaFuncAttributeMaxDynamicSharedMemorySize, GEMM_SMEM64);
    cudaFuncSetAttribute(gemm_tc<64, 5>,  cudaFuncAttributeMaxDynamicSharedMemorySize, GEMM_SMEM64);
    cudaFuncSetAttribute(gemm_tc<64, 6>,  cudaFuncAttributeMaxDynamicSharedMemorySize, GEMM_SMEM64);
    cudaFuncSetAttribute(attn_k, cudaFuncAttributeMaxDynamicSharedMemorySize, ATTN_SMEM);

    void* pv;
    cudaGetSymbolAddress(&pv, g_Wqkvt); float* Wqkvt = (float*)pv;
    cudaGetSymbolAddress(&pv, g_Bqkv);  float* Bqkv  = (float*)pv;
    cudaGetSymbolAddress(&pv, g_Wpt);   float* Wpt   = (float*)pv;
    cudaGetSymbolAddress(&pv, g_W1t);   float* W1t   = (float*)pv;
    cudaGetSymbolAddress(&pv, g_W2t);   float* W2t   = (float*)pv;
    cudaGetSymbolAddress(&pv, g_Wlmt);  float* Wlmt  = (float*)pv;
    cudaGetSymbolAddress(&pv, g_Amask); unsigned char* Amask = (unsigned char*)pv;
    cudaGetSymbolAddress(&pv, g_Amaskf); float* Amaskf = (float*)pv;
    cudaGetSymbolAddress(&pv, g_KQV);   float* KQV = (float*)pv;
    cudaGetSymbolAddress(&pv, g_AQ4);   float* AQ4 = (float*)pv;
    cudaGetSymbolAddress(&pv, g_Ob);    float* Ob  = (float*)pv;
    cudaGetSymbolAddress(&pv, g_Mha);   float* Mha = (float*)pv;
    cudaGetSymbolAddress(&pv, g_Mhar);  float* Mhar = (float*)pv;
    cudaGetSymbolAddress(&pv, g_Ff);    float* Ff  = (float*)pv;
    cudaGetSymbolAddress(&pv, g_Xb);    float* Xb  = (float*)pv;

    pack_qkv_k<<<6144, 256>>>(Wk, Wq, Wv, bk, bq, bv);
    pack_rest_k<<<10496, 256>>>(Wp, W1, W2, Wlm);
    mask_k<<<2048, 256>>>(dag);
    xr_k<<<8192, 256>>>(X);

    for (int l = 0; l < 4; l++) {
        const unsigned char* Am = Amask + (l ? 262144 : 0);
        const float* Amf = Amaskf + (l ? 262144 : 0);
        {   // QKV: Xb @ Wqkvt^T -> scatter K/Qt/Vt (+bias+swish, rounded)
            GP p{}; p.A = Xb; p.lda = 256;
            p.B = Wqkvt + (size_t)l * 1536 * 256; p.ldb = 256;
            p.bias = Bqkv + l * 1536; p.dst0 = KQV; p.K = 256;
            gemm_tc<128, 1><<<dim3(12, 64, 1), 256, GEMM_SMEM128>>>(p);
        }
        {   // AQ = maskf @ Qt^T -> AQ4[z][i][hs]  (rounded)
            GP p{}; p.A = Amf; p.lda = 512;
            p.B = KQV + 4194304; p.ldb = 512;
            p.C = AQ4; p.K = 512;
            gemm_tc<128, 3><<<dim3(64, 4, 1), 256, GEMM_SMEM128>>>(p);
        }
        // fused scores + softmax + PV  (32 rows/CTA, 2 CTAs/SM)
        attn_k<<<dim3(16, 128), 256, ATTN_SMEM>>>(AQ4, KQV, KQV + 2 * 4194304, Am, Ob);
        {   // mha = swish(Ob @ Wpt^T + bp): Mha exact + Mhar rounded
            GP p{}; p.A = Ob; p.lda = 512;
            p.B = Wpt + (size_t)l * 256 * 512; p.ldb = 512;
            p.bias = bp + l * 256; p.C = Mha; p.ldc = 256; p.dst0 = Mhar; p.K = 512;
            gemm_tc<64, 8><<<dim3(4, 64, 1), 256, GEMM_SMEM64>>>(p);
        }
        {   // ff = swish(Mhar @ W1t^T + b1)  (rounded)
            GP p{}; p.A = Mhar; p.lda = 256;
            p.B = W1t + (size_t)l * 1024 * 256; p.ldb = 256;
            p.bias = b1 + l * 1024; p.C = Ff; p.ldc = 1024; p.K = 256;
            gemm_tc<128, 4><<<dim3(8, 64, 1), 256, GEMM_SMEM128>>>(p);
        }
        {   // Xb = Ff @ W2t^T + b2 + Mha  (rounded)
            GP p{}; p.A = Ff; p.lda = 1024;
            p.B = W2t + (size_t)l * 256 * 1024; p.ldb = 1024;
            p.bias = b2 + l * 256; p.res = Mha; p.C = Xb; p.ldc = 256; p.K = 1024;
            gemm_tc<64, 5><<<dim3(4, 64, 1), 256, GEMM_SMEM64>>>(p);
        }
    }
    {   // lm head (exact output)
        GP p{}; p.A = Xb; p.lda = 256; p.B = Wlmt; p.ldb = 256;
        p.bias = blm; p.C = out; p.ldc = 256; p.K = 256;
        gemm_tc<64, 6><<<dim3(4, 64, 1), 256, GEMM_SMEM64>>>(p);
    }
}

// round 13
// speedup vs baseline: 1.0360x; 1.0328x over previous
#include <cuda_runtime.h>
#include <cstdint>

// ---------------------------------------------------------------------------
// CaT transformer, tf32 mma.sync (portable sm_100 target).
// R13: R10 structure; GEMM core rebuilt as BK=32 / 3-stage ring / one
// __syncthreads per 32-K chunk (half the barrier events). attn = R10 version.
// Bit-exact numerics (oracle rel_err 7.903782e-4).
// ---------------------------------------------------------------------------

#define DI __device__ __forceinline__

static DI float swishf(float x) { return x / (1.f + __expf(-x)); }

// ------------------------- static device scratch ---------------------------
__device__ float g_Wqkvt[4 * 1536 * 256];   // tf32
__device__ float g_Bqkv [4 * 1536];
__device__ float g_Wpt  [4 * 256 * 512];    // tf32
__device__ float g_W1t  [4 * 1024 * 256];   // tf32
__device__ float g_W2t  [4 * 256 * 1024];   // tf32
__device__ float g_Wlmt [256 * 256];        // tf32
__device__ unsigned char g_Amask[2 * 512 * 512];
__device__ float g_Amaskf[2 * 512 * 512];   // 0.0 / 1.0
__device__ float g_KQV[3 * 512 * 8192];     // K | Qt | Vt (tf32)
__device__ float g_AQ4[512 * 8192];         // [z][i][hs] tf32
__device__ float g_Ob [8192 * 512];         // tf32
__device__ float g_Mha[8192 * 256];         // exact residual
__device__ float g_Mhar[8192 * 256];        // tf32
__device__ float g_Ff [8192 * 1024];        // tf32
__device__ float g_Xb [8192 * 256];         // tf32

// --------------------------- helpers ---------------------------------------
DI unsigned tf32_rn(float x) {
    unsigned r;
    asm("cvt.rn.tf32.f32 %0, %1;" : "=r"(r) : "f"(x));
    return r;
}
DI float tf32f(float x) { return __uint_as_float(tf32_rn(x)); }
DI unsigned cvta_s(const void* p) { return (unsigned)__cvta_generic_to_shared(p); }
DI void cpa16(unsigned dst, const void* src) {
    asm volatile("cp.async.cg.shared.global [%0], [%1], 16;" :: "r"(dst), "l"(src) : "memory");
}
#define CPA_COMMIT() asm volatile("cp.async.commit_group;" ::: "memory")
#define CPA_WAIT(N)  asm volatile("cp.async.wait_group %0;" :: "n"(N) : "memory")

#define LDM_X4(r0, r1, r2, r3, addr) \
    asm volatile("ldmatrix.sync.aligned.m8n8.x4.shared.b16 {%0,%1,%2,%3}, [%4];" \
                 : "=r"(r0), "=r"(r1), "=r"(r2), "=r"(r3) : "r"(addr))
#define MMA_TF32(d, a, b) \
    asm volatile("mma.sync.aligned.m16n8k8.row.col.f32.tf32.tf32.f32 " \
                 "{%0,%1,%2,%3}, {%4,%5,%6,%7}, {%8,%9}, {%0,%1,%2,%3};" \
                 : "+f"((d)[0]), "+f"((d)[1]), "+f"((d)[2]), "+f"((d)[3]) \
                 : "r"((a)[0]), "r"((a)[1]), "r"((a)[2]), "r"((a)[3]), \
                   "r"((b)[0]), "r"((b)[1]))

// ------------------------------ prep kernels -------------------------------
__global__ void pack_qkv_k(const float* __restrict__ Wk, const float* __restrict__ Wq,
                           const float* __restrict__ Wv, const float* __restrict__ bk,
                           const float* __restrict__ bq, const float* __restrict__ bv) {
    int idx = blockIdx.x * 256 + threadIdx.x;          // < 1572864
    int l = idx / 393216;
    int rem = idx - l * 393216;
    int r = rem >> 8;
    int d = rem & 255;
    int t = r >> 9, h = (r >> 6) & 7, hs = r & 63;
    const float* W = (t == 0) ? Wk : (t == 1) ? Wq : Wv;
    g_Wqkvt[idx] = tf32f(W[(((size_t)(l * 8 + h)) * 256 + d) * 64 + hs]);
    if (idx < 4 * 1536) {
        int ll = idx / 1536;
        int c = idx - ll * 1536;
        int tt = c >> 9, hh = (c >> 6) & 7, hss = c & 63;
        const float* bb = (tt == 0) ? bk : (tt == 1) ? bq : bv;
        g_Bqkv[idx] = bb[(ll * 8 + hh) * 64 + hss];
    }
}

__global__ void pack_rest_k(const float* __restrict__ Wp, const float* __restrict__ W1,
                            const float* __restrict__ W2, const float* __restrict__ Wlm) {
    int idx = blockIdx.x * 256 + threadIdx.x;          // < 2686976
    if (idx < 524288) {
        int l = idx >> 17, rem = idx & 131071;
        int n = rem >> 9, k = rem & 511;
        g_Wpt[idx] = tf32f(Wp[((size_t)l * 512 + k) * 256 + n]);
        return;
    }
    idx -= 524288;
    if (idx < 1048576) {
        int l = idx >> 18, rem = idx & 262143;
        int n = rem >> 8, d = rem & 255;
        g_W1t[idx] = tf32f(W1[((size_t)l * 256 + d) * 1024 + n]);
        return;
    }
    idx -= 1048576;
    if (idx < 1048576) {
        int l = idx >> 18, rem = idx & 262143;
        int n = rem >> 10, f = rem & 1023;
        g_W2t[idx] = tf32f(W2[((size_t)l * 1024 + f) * 256 + n]);
        return;
    }
    idx -= 1048576;
    if (idx < 65536) {
        int n = idx >> 8, d = idx & 255;
        g_Wlmt[idx] = tf32f(Wlm[d * 256 + n]);
    }
}

__global__ void mask_k(const int* __restrict__ dag) {
    int idx = blockIdx.x * 256 + threadIdx.x;          // < 524288
    int v = idx >> 18;
    int rem = idx & 262143;
    int i = rem >> 9;
    int j = rem & 511;
    unsigned char m = (dag[j * 512 + i] != 0 || (v && i == j)) ? 1 : 0;
    g_Amask[idx] = m;
    g_Amaskf[idx] = (float)m;
}

__global__ void xr_k(const float* __restrict__ X) {
    int i = blockIdx.x * 256 + threadIdx.x;            // < 2097152
    g_Xb[i] = tf32f(X[i]);
}

// ------------------------------- GEMM core ---------------------------------
struct GP {
    const float* A; const float* B; float* C;
    const float* bias; const float* res;
    float* dst0;
    int K, lda, ldb, ldc;
    long long sAz, sBz, sCz;
};

// BK=32, pitch 36, 3 stages.
static const int GEMM_SMEM128 = 3 * (128 * 36 + 128 * 36) * 4;   // 110592 B
static const int GEMM_SMEM64  = 3 * (128 * 36 +  64 * 36) * 4;   // 82944 B

// MODE: 1 QKV scatter  3 AQ scatter  4 bias+swish(rounded)  5 bias+res(rounded)
//       6 bias(exact)  8 bias+swish dual (C exact, dst0 rounded)
template <int BN, int MODE>
__global__ __launch_bounds__(256, 2) void gemm_tc(GP p) {
    constexpr int BM = 128, PITCH = 36, NS = 3;
    constexpr int WNW = (BN == 128) ? 4 : 2;
    constexpr int WM  = (BN == 128) ? 64 : 32;
    constexpr int WN  = 32;
    constexpr int MT = WM / 16, NT = WN / 8, NT2 = NT / 2;
    constexpr int ASZ = BM * PITCH, BSZ = BN * PITCH;
    constexpr int BLD = (BN * 32) / (4 * 256);          // B float4 loads / thread

    extern __shared__ float dsm[];
    const unsigned sA = cvta_s(dsm);
    const unsigned sB = cvta_s(dsm + NS * ASZ);

    const int t = threadIdx.x, lane = t & 31, w = t >> 5;
    const int wm = w / WNW, wn = w % WNW;
    const int g = lane >> 2, cc = lane & 3;
    const int lrow = lane & 15;
    const unsigned loff = (unsigned)((lane >> 4) << 4);
    const int bx = blockIdx.x, by = blockIdx.y, bz = blockIdx.z;
    const int ar = t >> 3, ac = (t & 7) << 2;           // 32-wide rows, 8 f4 each

    const float* Af = p.A + (size_t)bz * p.sAz + (size_t)by * BM * p.lda;
    const float* Bp = p.B + (size_t)bz * p.sBz + (size_t)bx * BN * p.ldb;
    float* C = p.C + (size_t)bz * p.sCz;

    float acc[MT][NT][4];
#pragma unroll
    for (int i = 0; i < MT; i++)
#pragma unroll
        for (int j = 0; j < NT; j++)
#pragma unroll
            for (int r = 0; r < 4; r++) acc[i][j][r] = 0.f;

    auto issue = [&](int ch, int s) {
        const int k0 = ch << 5;
#pragma unroll
        for (int i = 0; i < 4; i++) {                   // A: 128 rows
            const int r = ar + i * 32;
            cpa16(sA + (unsigned)((s * ASZ + r * PITCH + ac) * 4),
                  Af + (size_t)r * p.lda + k0 + ac);
        }
#pragma unroll
        for (int i = 0; i < BLD; i++) {                 // B: BN rows
            const int r = ar + i * 32;
            cpa16(sB + (unsigned)((s * BSZ + r * PITCH + ac) * 4),
                  Bp + (size_t)r * p.ldb + k0 + ac);
        }
        CPA_COMMIT();
    };

    const int nch = p.K >> 5;
    issue(0, 0); issue(1, 1);
    for (int c = 0; c < nch; c++) {
        CPA_WAIT(1);
        __syncthreads();
        if (c + 2 < nch) issue(c + 2, (c + 2) % 3); else CPA_COMMIT();
        const int buf = c % 3;
#pragma unroll
        for (int ks = 0; ks < 4; ks++) {
            unsigned a[MT][4], b[NT][2];
#pragma unroll
            for (int i = 0; i < MT; i++) {
                const unsigned addr = sA + (unsigned)((buf * ASZ
                                    + (wm * WM + i * 16 + lrow) * PITCH + ks * 8) * 4) + loff;
                LDM_X4(a[i][0], a[i][1], a[i][2], a[i][3], addr);
            }
#pragma unroll
            for (int j2 = 0; j2 < NT2; j2++) {
                const unsigned addr = sB + (unsigned)((buf * BSZ
                                    + (wn * WN + j2 * 16 + lrow) * PITCH + ks * 8) * 4) + loff;
                LDM_X4(b[2 * j2][0], b[2 * j2 + 1][0], b[2 * j2][1], b[2 * j2 + 1][1], addr);
            }
#pragma unroll
            for (int i = 0; i < MT; i++)
#pragma unroll
                for (int j = 0; j < NT; j++)
                    MMA_TF32(acc[i][j], a[i], b[j]);
        }
    }

    // ------------------------------ epilogue -------------------------------
#pragma unroll
    for (int i = 0; i < MT; i++)
#pragma unroll
        for (int j = 0; j < NT; j++)
#pragma unroll
            for (int r = 0; r < 4; r++) {
                const int gm = by * BM + wm * WM + i * 16 + ((r >> 1) << 3) + g;
                const int gn = bx * BN + wn * WN + j * 8 + (cc << 1) + (r & 1);
                float v = acc[i][j][r];
                if (MODE == 1) {
                    v = swishf(v + p.bias[gn]);
                    const int tt = gn >> 9, h = (gn >> 6) & 7, hs = gn & 63;
                    const int b = gm >> 9, n = gm & 511, z = b * 8 + h;
                    if (tt == 0)      p.dst0[(size_t)(z * 512 + n) * 64 + hs] = tf32f(v);
                    else if (tt == 1) p.dst0[4194304u + (size_t)(z * 64 + hs) * 512 + n] = tf32f(v);
                    else              p.dst0[8388608u + (size_t)(z * 64 + hs) * 512 + n] = tf32f(v);
                } else if (MODE == 3) {
                    p.C[(size_t)(gn >> 6) * 32768 + (size_t)gm * 64 + (gn & 63)] = tf32f(v);
                } else if (MODE == 4) {
                    C[(size_t)gm * p.ldc + gn] = tf32f(swishf(v + p.bias[gn]));
                } else if (MODE == 5) {
                    C[(size_t)gm * p.ldc + gn] =
                        tf32f(v + p.bias[gn] + p.res[(size_t)gm * p.ldc + gn]);
                } else if (MODE == 6) {
                    C[(size_t)gm * p.ldc + gn] = v + p.bias[gn];
                } else {   // MODE 8
                    const float e = swishf(v + p.bias[gn]);
                    C[(size_t)gm * p.ldc + gn] = e;
                    p.dst0[(size_t)gm * p.ldc + gn] = tf32f(e);
                }
            }
}

// ------------------- fused attention: scores+softmax+PV --------------------
// Grid (8 i-tiles, 128 z), 512 threads (16 warps).  (R10 version, proven.)
// smem floats: S 64x516 @0 | At 64x68 @33024 | Bt @37376
static const int ATTN_SMEM = (33024 + 4352 + 17408) * 4;   // 219136 B

__global__ __launch_bounds__(512) void attn_k(
    const float* __restrict__ AQ, const float* __restrict__ Kb,
    const float* __restrict__ Vt, const unsigned char* __restrict__ Mk,
    float* __restrict__ Ob) {
    extern __shared__ float sm[];
    float* S = sm;

    const int t = threadIdx.x, lane = t & 31, w = t >> 5;     // w: 0..15
    const int g = lane >> 2, cc = lane & 3;
    const int lrow = lane & 15;
    const unsigned loff = (unsigned)((lane >> 4) << 4);
    const int i0 = blockIdx.x * 64, z = blockIdx.y;

    const float* AQz = AQ + (size_t)z * 32768 + (size_t)i0 * 64;   // 64 x 64
    const float* Kp  = Kb + (size_t)z * 32768;                     // 512 x 64
    const float* Vz  = Vt + (size_t)z * 32768;                     // 64 x 512

    const unsigned sS = cvta_s(S);
    const unsigned sA = cvta_s(sm + 33024);
    const unsigned sB = cvta_s(sm + 37376);

    // ---- prologue: cp.async At (64x64 -> pitch 68) + K chunk 0 ------------
#pragma unroll
    for (int i = 0; i < 2; i++) {
        const int idx = i * 512 + t;
        const int r = idx >> 4, c = (idx & 15) << 2;
        cpa16(sA + (unsigned)((r * 68 + c) * 4), AQz + (size_t)r * 64 + c);
    }
    auto issueK = [&](int jc, int s) {
#pragma unroll
        for (int i = 0; i < 4; i++) {
            const int idx = i * 512 + t;
            const int r = idx >> 4, c = (idx & 15) << 2;
            cpa16(sB + (unsigned)((s * 8704 + r * 68 + c) * 4),
                  Kp + (size_t)(jc * 128 + r) * 64 + c);
        }
        CPA_COMMIT();
    };
    issueK(0, 0);   // single group: At + K0

    // ================= phase 1: S = AQ @ K^T, mask+scale ====================
    {
        const int wm = w >> 2, wn = w & 3;      // 4x4 warps: 16 rows x 32 cols
        float acc[4][4];
        for (int jc = 0; jc < 4; jc++) {
            if (jc + 1 < 4) issueK(jc + 1, (jc + 1) & 1); else CPA_COMMIT();
            CPA_WAIT(1);
            __syncthreads();
#pragma unroll
            for (int j = 0; j < 4; j++)
#pragma unroll
                for (int r = 0; r < 4; r++) acc[j][r] = 0.f;
            const int buf = jc & 1;
#pragma unroll
            for (int ks = 0; ks < 8; ks++) {
                unsigned a[4], b[4][2];
                {
                    const unsigned addr = sA + (unsigned)(((wm * 16 + lrow) * 68
                                        + ks * 8) * 4) + loff;
                    LDM_X4(a[0], a[1], a[2], a[3], addr);
                }
#pragma unroll
                for (int j2 = 0; j2 < 2; j2++) {
                    const unsigned addr = sB + (unsigned)((buf * 8704
                                        + (wn * 32 + j2 * 16 + lrow) * 68 + ks * 8) * 4) + loff;
                    LDM_X4(b[2 * j2][0], b[2 * j2 + 1][0], b[2 * j2][1], b[2 * j2 + 1][1], addr);
                }
#pragma unroll
                for (int j = 0; j < 4; j++)
                    MMA_TF32(acc[j], a, b[j]);
            }
            // epilogue: mask+scale -> S
#pragma unroll
            for (int j = 0; j < 4; j++)
#pragma unroll
                for (int r = 0; r < 4; r++) {
                    const int gm = wm * 16 + ((r >> 1) << 3) + g;
                    const int gn = jc * 128 + wn * 32 + j * 8 + (cc << 1) + (r & 1);
                    const float v = acc[j][r];
                    S[gm * 516 + gn] =
                        Mk[(size_t)(i0 + gm) * 512 + gn] ? v * 0.125f : -3.0e38f;
                }
            __syncthreads();
        }
    }

    // ---- overlap: start V chunk 0 copy before softmax ----
    auto issueV = [&](int kc, int s) {
#pragma unroll
        for (int i = 0; i < 4; i++) {
            const int idx = i * 512 + t;
            const int r = idx >> 5, c = (idx & 31) << 2;
            cpa16(sB + (unsigned)((s * 8448 + r * 132 + c) * 4),
                  Vz + (size_t)r * 512 + kc * 128 + c);
        }
        CPA_COMMIT();
    };
    issueV(0, 0);

    // ================= phase 2: exact softmax + (P + A), tf32 ===============
    for (int it = 0; it < 4; it++) {
        const int ir = it * 16 + w;
        float* r = S + ir * 516;
        const unsigned char* mr = Mk + (size_t)(i0 + ir) * 512;
        float x[16];
        float m = -3.4e38f;
#pragma unroll
        for (int k = 0; k < 16; k++) { x[k] = r[k * 32 + lane]; m = fmaxf(m, x[k]); }
#pragma unroll
        for (int o = 16; o; o >>= 1) m = fmaxf(m, __shfl_xor_sync(0xffffffffu, m, o));
        if (m <= -1e37f) {
#pragma unroll
            for (int k = 0; k < 16; k++) r[k * 32 + lane] = 0.f;
        } else {
            float s = 0.f;
#pragma unroll
            for (int k = 0; k < 16; k++) { x[k] = __expf(x[k] - m); s += x[k]; }
#pragma unroll
            for (int o = 16; o; o >>= 1) s += __shfl_xor_sync(0xffffffffu, s, o);
            const float inv = 1.f / s;
#pragma unroll
            for (int k = 0; k < 16; k++)
                r[k * 32 + lane] = tf32f(x[k] * inv + (float)mr[k * 32 + lane]);
        }
    }
    __syncthreads();

    // ================= phase 3: O = Ssm @ V^T (4 x K=128 chunks) ============
    {
        const int wm = w >> 2, wn = w & 3;      // 4x4 warps: 16 rows x 16 cols
        float oa[2][4];
#pragma unroll
        for (int j = 0; j < 2; j++)
#pragma unroll
            for (int r = 0; r < 4; r++) oa[j][r] = 0.f;
        for (int kc = 0; kc < 4; kc++) {
            if (kc + 1 < 4) issueV(kc + 1, (kc + 1) & 1); else CPA_COMMIT();
            CPA_WAIT(1);
            __syncthreads();
            const int buf = kc & 1;
#pragma unroll
            for (int ks = 0; ks < 16; ks++) {
                unsigned a[4], b[2][2];
                {
                    const unsigned addr = sS + (unsigned)(((wm * 16 + lrow) * 516
                                        + kc * 128 + ks * 8) * 4) + loff;
                    LDM_X4(a[0], a[1], a[2], a[3], addr);
                }
                {
                    const unsigned addr = sB + (unsigned)((buf * 8448
                                        + (wn * 16 + lrow) * 132 + ks * 8) * 4) + loff;
                    LDM_X4(b[0][0], b[1][0], b[0][1], b[1][1], addr);
                }
#pragma unroll
                for (int j = 0; j < 2; j++)
                    MMA_TF32(oa[j], a, b[j]);
            }
            __syncthreads();
        }
        // epilogue -> Ob[(b*512 + i)][(h*64 + hs)]  (rounded)
        const int b = z >> 3, h = z & 7;
#pragma unroll
        for (int j = 0; j < 2; j++)
#pragma unroll
            for (int r = 0; r < 4; r++) {
                const int gm = wm * 16 + ((r >> 1) << 3) + g;
                const int gn = wn * 16 + j * 8 + (cc << 1) + (r & 1);
                Ob[(size_t)(b * 512 + i0 + gm) * 512 + h * 64 + gn] = tf32f(oa[j][r]);
            }
    }
}

// ------------------------------ host driver --------------------------------
extern "C" void kernel_launch(void* const* d_in, const int* in_sizes, int n_in,
                              void* d_out, int out_size) {
    (void)in_sizes; (void)n_in; (void)out_size;
    const float* X   = (const float*)d_in[0];
    const int*   dag = (const int*)d_in[1];
    const float* Wk  = (const float*)d_in[2],  *bk  = (const float*)d_in[3];
    const float* Wq  = (const float*)d_in[4],  *bq  = (const float*)d_in[5];
    const float* Wv  = (const float*)d_in[6],  *bv  = (const float*)d_in[7];
    const float* Wp  = (const float*)d_in[8],  *bp  = (const float*)d_in[9];
    const float* W1  = (const float*)d_in[10], *b1  = (const float*)d_in[11];
    const float* W2  = (const float*)d_in[12], *b2  = (const float*)d_in[13];
    const float* Wlm = (const float*)d_in[14], *blm = (const float*)d_in[15];
    float* out = (float*)d_out;

    cudaFuncSetAttribute(gemm_tc<128, 1>, cudaFuncAttributeMaxDynamicSharedMemorySize, GEMM_SMEM128);
    cudaFuncSetAttribute(gemm_tc<128, 3>, cudaFuncAttributeMaxDynamicSharedMemorySize, GEMM_SMEM128);
    cudaFuncSetAttribute(gemm_tc<128, 4>, cudaFuncAttributeMaxDynamicSharedMemorySize, GEMM_SMEM128);
    cudaFuncSetAttribute(gemm_tc<64, 8>,  cudaFuncAttributeMaxDynamicSharedMemorySize, GEMM_SMEM64);
    cudaFuncSetAttribute(gemm_tc<64, 5>,  cudaFuncAttributeMaxDynamicSharedMemorySize, GEMM_SMEM64);
    cudaFuncSetAttribute(gemm_tc<64, 6>,  cudaFuncAttributeMaxDynamicSharedMemorySize, GEMM_SMEM64);
    cudaFuncSetAttribute(attn_k, cudaFuncAttributeMaxDynamicSharedMemorySize, ATTN_SMEM);

    void* pv;
    cudaGetSymbolAddress(&pv, g_Wqkvt); float* Wqkvt = (float*)pv;
    cudaGetSymbolAddress(&pv, g_Bqkv);  float* Bqkv  = (float*)pv;
    cudaGetSymbolAddress(&pv, g_Wpt);   float* Wpt   = (float*)pv;
    cudaGetSymbolAddress(&pv, g_W1t);   float* W1t   = (float*)pv;
    cudaGetSymbolAddress(&pv, g_W2t);   float* W2t   = (float*)pv;
    cudaGetSymbolAddress(&pv, g_Wlmt);  float* Wlmt  = (float*)pv;
    cudaGetSymbolAddress(&pv, g_Amask); unsigned char* Amask = (unsigned char*)pv;
    cudaGetSymbolAddress(&pv, g_Amaskf); float* Amaskf = (float*)pv;
    cudaGetSymbolAddress(&pv, g_KQV);   float* KQV = (float*)pv;
    cudaGetSymbolAddress(&pv, g_AQ4);   float* AQ4 = (float*)pv;
    cudaGetSymbolAddress(&pv, g_Ob);    float* Ob  = (float*)pv;
    cudaGetSymbolAddress(&pv, g_Mha);   float* Mha = (float*)pv;
    cudaGetSymbolAddress(&pv, g_Mhar);  float* Mhar = (float*)pv;
    cudaGetSymbolAddress(&pv, g_Ff);    float* Ff  = (float*)pv;
    cudaGetSymbolAddress(&pv, g_Xb);    float* Xb  = (float*)pv;

    pack_qkv_k<<<6144, 256>>>(Wk, Wq, Wv, bk, bq, bv);
    pack_rest_k<<<10496, 256>>>(Wp, W1, W2, Wlm);
    mask_k<<<2048, 256>>>(dag);
    xr_k<<<8192, 256>>>(X);

    for (int l = 0; l < 4; l++) {
        const unsigned char* Am = Amask + (l ? 262144 : 0);
        const float* Amf = Amaskf + (l ? 262144 : 0);
        {   // QKV: Xb @ Wqkvt^T -> scatter K/Qt/Vt (+bias+swish, rounded)
            GP p{}; p.A = Xb; p.lda = 256;
            p.B = Wqkvt + (size_t)l * 1536 * 256; p.ldb = 256;
            p.bias = Bqkv + l * 1536; p.dst0 = KQV; p.K = 256;
            gemm_tc<128, 1><<<dim3(12, 64, 1), 256, GEMM_SMEM128>>>(p);
        }
        {   // AQ = maskf @ Qt^T -> AQ4[z][i][hs]  (rounded)
            GP p{}; p.A = Amf; p.lda = 512;
            p.B = KQV + 4194304; p.ldb = 512;
            p.C = AQ4; p.K = 512;
            gemm_tc<128, 3><<<dim3(64, 4, 1), 256, GEMM_SMEM128>>>(p);
        }
        // fused scores + softmax + PV  (R10 version)
        attn_k<<<dim3(8, 128), 512, ATTN_SMEM>>>(AQ4, KQV, KQV + 2 * 4194304, Am, Ob);
        {   // mha = swish(Ob @ Wpt^T + bp): Mha exact + Mhar rounded
            GP p{}; p.A = Ob; p.lda = 512;
            p.B = Wpt + (size_t)l * 256 * 512; p.ldb = 512;
            p.bias = bp + l * 256; p.C = Mha; p.ldc = 256; p.dst0 = Mhar; p.K = 512;
            gemm_tc<64, 8><<<dim3(4, 64, 1), 256, GEMM_SMEM64>>>(p);
        }
        {   // ff = swish(Mhar @ W1t^T + b1)  (rounded)
            GP p{}; p.A = Mhar; p.lda = 256;
            p.B = W1t + (size_t)l * 1024 * 256; p.ldb = 256;
            p.bias = b1 + l * 1024; p.C = Ff; p.ldc = 1024; p.K = 256;
            gemm_tc<128, 4><<<dim3(8, 64, 1), 256, GEMM_SMEM128>>>(p);
        }
        {   // Xb = Ff @ W2t^T + b2 + Mha  (rounded)
            GP p{}; p.A = Ff; p.lda = 1024;
            p.B = W2t + (size_t)l * 256 * 1024; p.ldb = 1024;
            p.bias = b2 + l * 256; p.res = Mha; p.C = Xb; p.ldc = 256; p.K = 1024;
            gemm_tc<64, 5><<<dim3(4, 64, 1), 256, GEMM_SMEM64>>>(p);
        }
    }
    {   // lm head (exact output)
        GP p{}; p.A = Xb; p.lda = 256; p.B = Wlmt; p.ldb = 256;
        p.bias = blm; p.C = out; p.ldc = 256; p.K = 256;
        gemm_tc<64, 6><<<dim3(4, 64, 1), 256, GEMM_SMEM64>>>(p);
    }
}

// round 14
// speedup vs baseline: 1.1175x; 1.0786x over previous
#include <cuda_runtime.h>
#include <cstdint>

// ---------------------------------------------------------------------------
// CaT transformer, tf32 mma.sync (portable sm_100 target).
// R14: R13 base + attn single-sync-per-chunk pipeline + bit-packed mask
// (broadcast u32 loads replace scattered u8 loads). Bit-exact numerics
// (oracle rel_err 7.903782e-4).
// ---------------------------------------------------------------------------

#define DI __device__ __forceinline__

static DI float swishf(float x) { return x / (1.f + __expf(-x)); }

// ------------------------- static device scratch ---------------------------
__device__ float g_Wqkvt[4 * 1536 * 256];   // tf32
__device__ float g_Bqkv [4 * 1536];
__device__ float g_Wpt  [4 * 256 * 512];    // tf32
__device__ float g_W1t  [4 * 1024 * 256];   // tf32
__device__ float g_W2t  [4 * 256 * 1024];   // tf32
__device__ float g_Wlmt [256 * 256];        // tf32
__device__ float g_Amaskf[2 * 512 * 512];   // 0.0 / 1.0
__device__ unsigned g_Amaskb[2 * 512 * 16]; // bit-packed mask rows
__device__ float g_KQV[3 * 512 * 8192];     // K | Qt | Vt (tf32)
__device__ float g_AQ4[512 * 8192];         // [z][i][hs] tf32
__device__ float g_Ob [8192 * 512];         // tf32
__device__ float g_Mha[8192 * 256];         // exact residual
__device__ float g_Mhar[8192 * 256];        // tf32
__device__ float g_Ff [8192 * 1024];        // tf32
__device__ float g_Xb [8192 * 256];         // tf32

// --------------------------- helpers ---------------------------------------
DI unsigned tf32_rn(float x) {
    unsigned r;
    asm("cvt.rn.tf32.f32 %0, %1;" : "=r"(r) : "f"(x));
    return r;
}
DI float tf32f(float x) { return __uint_as_float(tf32_rn(x)); }
DI unsigned cvta_s(const void* p) { return (unsigned)__cvta_generic_to_shared(p); }
DI void cpa16(unsigned dst, const void* src) {
    asm volatile("cp.async.cg.shared.global [%0], [%1], 16;" :: "r"(dst), "l"(src) : "memory");
}
#define CPA_COMMIT() asm volatile("cp.async.commit_group;" ::: "memory")
#define CPA_WAIT(N)  asm volatile("cp.async.wait_group %0;" :: "n"(N) : "memory")

#define LDM_X4(r0, r1, r2, r3, addr) \
    asm volatile("ldmatrix.sync.aligned.m8n8.x4.shared.b16 {%0,%1,%2,%3}, [%4];" \
                 : "=r"(r0), "=r"(r1), "=r"(r2), "=r"(r3) : "r"(addr))
#define MMA_TF32(d, a, b) \
    asm volatile("mma.sync.aligned.m16n8k8.row.col.f32.tf32.tf32.f32 " \
                 "{%0,%1,%2,%3}, {%4,%5,%6,%7}, {%8,%9}, {%0,%1,%2,%3};" \
                 : "+f"((d)[0]), "+f"((d)[1]), "+f"((d)[2]), "+f"((d)[3]) \
                 : "r"((a)[0]), "r"((a)[1]), "r"((a)[2]), "r"((a)[3]), \
                   "r"((b)[0]), "r"((b)[1]))

// ------------------------------ prep kernels -------------------------------
__global__ void pack_qkv_k(const float* __restrict__ Wk, const float* __restrict__ Wq,
                           const float* __restrict__ Wv, const float* __restrict__ bk,
                           const float* __restrict__ bq, const float* __restrict__ bv) {
    int idx = blockIdx.x * 256 + threadIdx.x;          // < 1572864
    int l = idx / 393216;
    int rem = idx - l * 393216;
    int r = rem >> 8;
    int d = rem & 255;
    int t = r >> 9, h = (r >> 6) & 7, hs = r & 63;
    const float* W = (t == 0) ? Wk : (t == 1) ? Wq : Wv;
    g_Wqkvt[idx] = tf32f(W[(((size_t)(l * 8 + h)) * 256 + d) * 64 + hs]);
    if (idx < 4 * 1536) {
        int ll = idx / 1536;
        int c = idx - ll * 1536;
        int tt = c >> 9, hh = (c >> 6) & 7, hss = c & 63;
        const float* bb = (tt == 0) ? bk : (tt == 1) ? bq : bv;
        g_Bqkv[idx] = bb[(ll * 8 + hh) * 64 + hss];
    }
}

__global__ void pack_rest_k(const float* __restrict__ Wp, const float* __restrict__ W1,
                            const float* __restrict__ W2, const float* __restrict__ Wlm) {
    int idx = blockIdx.x * 256 + threadIdx.x;          // < 2686976
    if (idx < 524288) {
        int l = idx >> 17, rem = idx & 131071;
        int n = rem >> 9, k = rem & 511;
        g_Wpt[idx] = tf32f(Wp[((size_t)l * 512 + k) * 256 + n]);
        return;
    }
    idx -= 524288;
    if (idx < 1048576) {
        int l = idx >> 18, rem = idx & 262143;
        int n = rem >> 8, d = rem & 255;
        g_W1t[idx] = tf32f(W1[((size_t)l * 256 + d) * 1024 + n]);
        return;
    }
    idx -= 1048576;
    if (idx < 1048576) {
        int l = idx >> 18, rem = idx & 262143;
        int n = rem >> 10, f = rem & 1023;
        g_W2t[idx] = tf32f(W2[((size_t)l * 1024 + f) * 256 + n]);
        return;
    }
    idx -= 1048576;
    if (idx < 65536) {
        int n = idx >> 8, d = idx & 255;
        g_Wlmt[idx] = tf32f(Wlm[d * 256 + n]);
    }
}

__global__ void mask_k(const int* __restrict__ dag) {
    int idx = blockIdx.x * 256 + threadIdx.x;          // < 524288
    int v = idx >> 18;
    int rem = idx & 262143;
    int i = rem >> 9;
    int j = rem & 511;
    g_Amaskf[idx] = (dag[j * 512 + i] != 0 || (v && i == j)) ? 1.f : 0.f;
}

__global__ void maskb_k(const int* __restrict__ dag) {
    int widx = blockIdx.x * 256 + threadIdx.x;         // < 16384
    int v = widx >> 13;
    int rem = widx & 8191;
    int i = rem >> 4;
    int w = rem & 15;
    unsigned bits = 0;
#pragma unroll 4
    for (int b = 0; b < 32; b++) {
        int j = w * 32 + b;
        if (dag[j * 512 + i] != 0 || (v && i == j)) bits |= 1u << b;
    }
    g_Amaskb[widx] = bits;
}

__global__ void xr_k(const float* __restrict__ X) {
    int i = blockIdx.x * 256 + threadIdx.x;            // < 2097152
    g_Xb[i] = tf32f(X[i]);
}

// ------------------------------- GEMM core ---------------------------------
struct GP {
    const float* A; const float* B; float* C;
    const float* bias; const float* res;
    float* dst0;
    int K, lda, ldb, ldc;
    long long sAz, sBz, sCz;
};

// BK=32, pitch 36, 3 stages.
static const int GEMM_SMEM128 = 3 * (128 * 36 + 128 * 36) * 4;   // 110592 B
static const int GEMM_SMEM64  = 3 * (128 * 36 +  64 * 36) * 4;   // 82944 B

// MODE: 1 QKV scatter  3 AQ scatter  4 bias+swish(rounded)  5 bias+res(rounded)
//       6 bias(exact)  8 bias+swish dual (C exact, dst0 rounded)
template <int BN, int MODE>
__global__ __launch_bounds__(256, 2) void gemm_tc(GP p) {
    constexpr int BM = 128, PITCH = 36, NS = 3;
    constexpr int WNW = (BN == 128) ? 4 : 2;
    constexpr int WM  = (BN == 128) ? 64 : 32;
    constexpr int WN  = 32;
    constexpr int MT = WM / 16, NT = WN / 8, NT2 = NT / 2;
    constexpr int ASZ = BM * PITCH, BSZ = BN * PITCH;
    constexpr int BLD = (BN * 32) / (4 * 256);

    extern __shared__ float dsm[];
    const unsigned sA = cvta_s(dsm);
    const unsigned sB = cvta_s(dsm + NS * ASZ);

    const int t = threadIdx.x, lane = t & 31, w = t >> 5;
    const int wm = w / WNW, wn = w % WNW;
    const int g = lane >> 2, cc = lane & 3;
    const int lrow = lane & 15;
    const unsigned loff = (unsigned)((lane >> 4) << 4);
    const int bx = blockIdx.x, by = blockIdx.y, bz = blockIdx.z;
    const int ar = t >> 3, ac = (t & 7) << 2;

    const float* Af = p.A + (size_t)bz * p.sAz + (size_t)by * BM * p.lda;
    const float* Bp = p.B + (size_t)bz * p.sBz + (size_t)bx * BN * p.ldb;
    float* C = p.C + (size_t)bz * p.sCz;

    float acc[MT][NT][4];
#pragma unroll
    for (int i = 0; i < MT; i++)
#pragma unroll
        for (int j = 0; j < NT; j++)
#pragma unroll
            for (int r = 0; r < 4; r++) acc[i][j][r] = 0.f;

    auto issue = [&](int ch, int s) {
        const int k0 = ch << 5;
#pragma unroll
        for (int i = 0; i < 4; i++) {
            const int r = ar + i * 32;
            cpa16(sA + (unsigned)((s * ASZ + r * PITCH + ac) * 4),
                  Af + (size_t)r * p.lda + k0 + ac);
        }
#pragma unroll
        for (int i = 0; i < BLD; i++) {
            const int r = ar + i * 32;
            cpa16(sB + (unsigned)((s * BSZ + r * PITCH + ac) * 4),
                  Bp + (size_t)r * p.ldb + k0 + ac);
        }
        CPA_COMMIT();
    };

    const int nch = p.K >> 5;
    issue(0, 0); issue(1, 1);
    for (int c = 0; c < nch; c++) {
        CPA_WAIT(1);
        __syncthreads();
        if (c + 2 < nch) issue(c + 2, (c + 2) % 3); else CPA_COMMIT();
        const int buf = c % 3;
#pragma unroll
        for (int ks = 0; ks < 4; ks++) {
            unsigned a[MT][4], b[NT][2];
#pragma unroll
            for (int i = 0; i < MT; i++) {
                const unsigned addr = sA + (unsigned)((buf * ASZ
                                    + (wm * WM + i * 16 + lrow) * PITCH + ks * 8) * 4) + loff;
                LDM_X4(a[i][0], a[i][1], a[i][2], a[i][3], addr);
            }
#pragma unroll
            for (int j2 = 0; j2 < NT2; j2++) {
                const unsigned addr = sB + (unsigned)((buf * BSZ
                                    + (wn * WN + j2 * 16 + lrow) * PITCH + ks * 8) * 4) + loff;
                LDM_X4(b[2 * j2][0], b[2 * j2 + 1][0], b[2 * j2][1], b[2 * j2 + 1][1], addr);
            }
#pragma unroll
            for (int i = 0; i < MT; i++)
#pragma unroll
                for (int j = 0; j < NT; j++)
                    MMA_TF32(acc[i][j], a[i], b[j]);
        }
    }

    // ------------------------------ epilogue -------------------------------
#pragma unroll
    for (int i = 0; i < MT; i++)
#pragma unroll
        for (int j = 0; j < NT; j++)
#pragma unroll
            for (int r = 0; r < 4; r++) {
                const int gm = by * BM + wm * WM + i * 16 + ((r >> 1) << 3) + g;
                const int gn = bx * BN + wn * WN + j * 8 + (cc << 1) + (r & 1);
                float v = acc[i][j][r];
                if (MODE == 1) {
                    v = swishf(v + p.bias[gn]);
                    const int tt = gn >> 9, h = (gn >> 6) & 7, hs = gn & 63;
                    const int b = gm >> 9, n = gm & 511, z = b * 8 + h;
                    if (tt == 0)      p.dst0[(size_t)(z * 512 + n) * 64 + hs] = tf32f(v);
                    else if (tt == 1) p.dst0[4194304u + (size_t)(z * 64 + hs) * 512 + n] = tf32f(v);
                    else              p.dst0[8388608u + (size_t)(z * 64 + hs) * 512 + n] = tf32f(v);
                } else if (MODE == 3) {
                    p.C[(size_t)(gn >> 6) * 32768 + (size_t)gm * 64 + (gn & 63)] = tf32f(v);
                } else if (MODE == 4) {
                    C[(size_t)gm * p.ldc + gn] = tf32f(swishf(v + p.bias[gn]));
                } else if (MODE == 5) {
                    C[(size_t)gm * p.ldc + gn] =
                        tf32f(v + p.bias[gn] + p.res[(size_t)gm * p.ldc + gn]);
                } else if (MODE == 6) {
                    C[(size_t)gm * p.ldc + gn] = v + p.bias[gn];
                } else {   // MODE 8
                    const float e = swishf(v + p.bias[gn]);
                    C[(size_t)gm * p.ldc + gn] = e;
                    p.dst0[(size_t)gm * p.ldc + gn] = tf32f(e);
                }
            }
}

// ------------------- fused attention: scores+softmax+PV --------------------
// Grid (8 i-tiles, 128 z), 512 threads (16 warps). Single sync per chunk.
// smem floats: S 64x516 @0 | At 64x68 @33024 | Bt @37376
static const int ATTN_SMEM = (33024 + 4352 + 17408) * 4;   // 219136 B

__global__ __launch_bounds__(512) void attn_k(
    const float* __restrict__ AQ, const float* __restrict__ Kb,
    const float* __restrict__ Vt, const unsigned* __restrict__ Mb,
    float* __restrict__ Ob) {
    extern __shared__ float sm[];
    float* S = sm;

    const int t = threadIdx.x, lane = t & 31, w = t >> 5;     // w: 0..15
    const int g = lane >> 2, cc = lane & 3;
    const int lrow = lane & 15;
    const unsigned loff = (unsigned)((lane >> 4) << 4);
    const int i0 = blockIdx.x * 64, z = blockIdx.y;

    const float* AQz = AQ + (size_t)z * 32768 + (size_t)i0 * 64;   // 64 x 64
    const float* Kp  = Kb + (size_t)z * 32768;                     // 512 x 64
    const float* Vz  = Vt + (size_t)z * 32768;                     // 64 x 512

    const unsigned sS = cvta_s(S);
    const unsigned sA = cvta_s(sm + 33024);
    const unsigned sB = cvta_s(sm + 37376);

    // ---- prologue: cp.async At (64x64 -> pitch 68) + K chunk 0 ------------
#pragma unroll
    for (int i = 0; i < 2; i++) {
        const int idx = i * 512 + t;
        const int r = idx >> 4, c = (idx & 15) << 2;
        cpa16(sA + (unsigned)((r * 68 + c) * 4), AQz + (size_t)r * 64 + c);
    }
    auto issueK = [&](int jc, int s) {
#pragma unroll
        for (int i = 0; i < 4; i++) {
            const int idx = i * 512 + t;
            const int r = idx >> 4, c = (idx & 15) << 2;
            cpa16(sB + (unsigned)((s * 8704 + r * 68 + c) * 4),
                  Kp + (size_t)(jc * 128 + r) * 64 + c);
        }
        CPA_COMMIT();
    };
    issueK(0, 0);   // single group: At + K0

    // ================= phase 1: S = AQ @ K^T, mask+scale ====================
    {
        const int wm = w >> 2, wn = w & 3;      // 4x4 warps: 16 rows x 32 cols
        for (int jc = 0; jc < 4; jc++) {
            CPA_WAIT(0);
            __syncthreads();
            if (jc + 1 < 4) issueK(jc + 1, (jc + 1) & 1);
            float acc[4][4];
#pragma unroll
            for (int j = 0; j < 4; j++)
#pragma unroll
                for (int r = 0; r < 4; r++) acc[j][r] = 0.f;
            const int buf = jc & 1;
#pragma unroll
            for (int ks = 0; ks < 8; ks++) {
                unsigned a[4], b[4][2];
                {
                    const unsigned addr = sA + (unsigned)(((wm * 16 + lrow) * 68
                                        + ks * 8) * 4) + loff;
                    LDM_X4(a[0], a[1], a[2], a[3], addr);
                }
#pragma unroll
                for (int j2 = 0; j2 < 2; j2++) {
                    const unsigned addr = sB + (unsigned)((buf * 8704
                                        + (wn * 32 + j2 * 16 + lrow) * 68 + ks * 8) * 4) + loff;
                    LDM_X4(b[2 * j2][0], b[2 * j2 + 1][0], b[2 * j2][1], b[2 * j2 + 1][1], addr);
                }
#pragma unroll
                for (int j = 0; j < 4; j++)
                    MMA_TF32(acc[j], a, b[j]);
            }
            // epilogue: bit-mask + scale -> S (2 broadcast words per thread)
            const unsigned mw0 = Mb[(size_t)(i0 + wm * 16 + g) * 16 + jc * 4 + wn];
            const unsigned mw1 = Mb[(size_t)(i0 + wm * 16 + 8 + g) * 16 + jc * 4 + wn];
#pragma unroll
            for (int j = 0; j < 4; j++)
#pragma unroll
                for (int r = 0; r < 4; r++) {
                    const int gm = wm * 16 + ((r >> 1) << 3) + g;
                    const int gn = jc * 128 + wn * 32 + j * 8 + (cc << 1) + (r & 1);
                    const unsigned mw = (r >> 1) ? mw1 : mw0;
                    const int bp = j * 8 + (cc << 1) + (r & 1);
                    S[gm * 516 + gn] =
                        ((mw >> bp) & 1u) ? acc[j][r] * 0.125f : -3.0e38f;
                }
        }
    }
    __syncthreads();   // all S written before softmax (and before V overwrites Bt)

    // ---- overlap: start V chunk 0 copy before softmax ----
    auto issueV = [&](int kc, int s) {
#pragma unroll
        for (int i = 0; i < 4; i++) {
            const int idx = i * 512 + t;
            const int r = idx >> 5, c = (idx & 31) << 2;
            cpa16(sB + (unsigned)((s * 8448 + r * 132 + c) * 4),
                  Vz + (size_t)r * 512 + kc * 128 + c);
        }
        CPA_COMMIT();
    };
    issueV(0, 0);

    // ================= phase 2: exact softmax + (P + A), tf32 ===============
    for (int it = 0; it < 4; it++) {
        const int ir = it * 16 + w;
        float* r = S + ir * 516;
        const unsigned* mwp = Mb + (size_t)(i0 + ir) * 16;
        float x[16];
        float m = -3.4e38f;
#pragma unroll
        for (int k = 0; k < 16; k++) { x[k] = r[k * 32 + lane]; m = fmaxf(m, x[k]); }
#pragma unroll
        for (int o = 16; o; o >>= 1) m = fmaxf(m, __shfl_xor_sync(0xffffffffu, m, o));
        if (m <= -1e37f) {
#pragma unroll
            for (int k = 0; k < 16; k++) r[k * 32 + lane] = 0.f;
        } else {
            float s = 0.f;
#pragma unroll
            for (int k = 0; k < 16; k++) { x[k] = __expf(x[k] - m); s += x[k]; }
#pragma unroll
            for (int o = 16; o; o >>= 1) s += __shfl_xor_sync(0xffffffffu, s, o);
            const float inv = 1.f / s;
#pragma unroll
            for (int k = 0; k < 16; k++)
                r[k * 32 + lane] =
                    tf32f(x[k] * inv + (float)((mwp[k] >> lane) & 1u));
        }
    }
    __syncthreads();

    // ================= phase 3: O = Ssm @ V^T (4 x K=128 chunks) ============
    {
        const int wm = w >> 2, wn = w & 3;      // 4x4 warps: 16 rows x 16 cols
        float oa[2][4];
#pragma unroll
        for (int j = 0; j < 2; j++)
#pragma unroll
            for (int r = 0; r < 4; r++) oa[j][r] = 0.f;
        for (int kc = 0; kc < 4; kc++) {
            CPA_WAIT(0);
            __syncthreads();
            if (kc + 1 < 4) issueV(kc + 1, (kc + 1) & 1);
            const int buf = kc & 1;
#pragma unroll
            for (int ks = 0; ks < 16; ks++) {
                unsigned a[4], b[2][2];
                {
                    const unsigned addr = sS + (unsigned)(((wm * 16 + lrow) * 516
                                        + kc * 128 + ks * 8) * 4) + loff;
                    LDM_X4(a[0], a[1], a[2], a[3], addr);
                }
                {
                    const unsigned addr = sB + (unsigned)((buf * 8448
                                        + (wn * 16 + lrow) * 132 + ks * 8) * 4) + loff;
                    LDM_X4(b[0][0], b[1][0], b[0][1], b[1][1], addr);
                }
#pragma unroll
                for (int j = 0; j < 2; j++)
                    MMA_TF32(oa[j], a, b[j]);
            }
        }
        // epilogue -> Ob[(b*512 + i)][(h*64 + hs)]  (rounded)
        const int b = z >> 3, h = z & 7;
#pragma unroll
        for (int j = 0; j < 2; j++)
#pragma unroll
            for (int r = 0; r < 4; r++) {
                const int gm = wm * 16 + ((r >> 1) << 3) + g;
                const int gn = wn * 16 + j * 8 + (cc << 1) + (r & 1);
                Ob[(size_t)(b * 512 + i0 + gm) * 512 + h * 64 + gn] = tf32f(oa[j][r]);
            }
    }
}

// ------------------------------ host driver --------------------------------
extern "C" void kernel_launch(void* const* d_in, const int* in_sizes, int n_in,
                              void* d_out, int out_size) {
    (void)in_sizes; (void)n_in; (void)out_size;
    const float* X   = (const float*)d_in[0];
    const int*   dag = (const int*)d_in[1];
    const float* Wk  = (const float*)d_in[2],  *bk  = (const float*)d_in[3];
    const float* Wq  = (const float*)d_in[4],  *bq  = (const float*)d_in[5];
    const float* Wv  = (const float*)d_in[6],  *bv  = (const float*)d_in[7];
    const float* Wp  = (const float*)d_in[8],  *bp  = (const float*)d_in[9];
    const float* W1  = (const float*)d_in[10], *b1  = (const float*)d_in[11];
    const float* W2  = (const float*)d_in[12], *b2  = (const float*)d_in[13];
    const float* Wlm = (const float*)d_in[14], *blm = (const float*)d_in[15];
    float* out = (float*)d_out;

    cudaFuncSetAttribute(gemm_tc<128, 1>, cudaFuncAttributeMaxDynamicSharedMemorySize, GEMM_SMEM128);
    cudaFuncSetAttribute(gemm_tc<128, 3>, cudaFuncAttributeMaxDynamicSharedMemorySize, GEMM_SMEM128);
    cudaFuncSetAttribute(gemm_tc<128, 4>, cudaFuncAttributeMaxDynamicSharedMemorySize, GEMM_SMEM128);
    cudaFuncSetAttribute(gemm_tc<64, 8>,  cudaFuncAttributeMaxDynamicSharedMemorySize, GEMM_SMEM64);
    cudaFuncSetAttribute(gemm_tc<64, 5>,  cudaFuncAttributeMaxDynamicSharedMemorySize, GEMM_SMEM64);
    cudaFuncSetAttribute(gemm_tc<64, 6>,  cudaFuncAttributeMaxDynamicSharedMemorySize, GEMM_SMEM64);
    cudaFuncSetAttribute(attn_k, cudaFuncAttributeMaxDynamicSharedMemorySize, ATTN_SMEM);

    void* pv;
    cudaGetSymbolAddress(&pv, g_Wqkvt); float* Wqkvt = (float*)pv;
    cudaGetSymbolAddress(&pv, g_Bqkv);  float* Bqkv  = (float*)pv;
    cudaGetSymbolAddress(&pv, g_Wpt);   float* Wpt   = (float*)pv;
    cudaGetSymbolAddress(&pv, g_W1t);   float* W1t   = (float*)pv;
    cudaGetSymbolAddress(&pv, g_W2t);   float* W2t   = (float*)pv;
    cudaGetSymbolAddress(&pv, g_Wlmt);  float* Wlmt  = (float*)pv;
    cudaGetSymbolAddress(&pv, g_Amaskf); float* Amaskf = (float*)pv;
    cudaGetSymbolAddress(&pv, g_Amaskb); unsigned* Amaskb = (unsigned*)pv;
    cudaGetSymbolAddress(&pv, g_KQV);   float* KQV = (float*)pv;
    cudaGetSymbolAddress(&pv, g_AQ4);   float* AQ4 = (float*)pv;
    cudaGetSymbolAddress(&pv, g_Ob);    float* Ob  = (float*)pv;
    cudaGetSymbolAddress(&pv, g_Mha);   float* Mha = (float*)pv;
    cudaGetSymbolAddress(&pv, g_Mhar);  float* Mhar = (float*)pv;
    cudaGetSymbolAddress(&pv, g_Ff);    float* Ff  = (float*)pv;
    cudaGetSymbolAddress(&pv, g_Xb);    float* Xb  = (float*)pv;

    pack_qkv_k<<<6144, 256>>>(Wk, Wq, Wv, bk, bq, bv);
    pack_rest_k<<<10496, 256>>>(Wp, W1, W2, Wlm);
    mask_k<<<2048, 256>>>(dag);
    maskb_k<<<64, 256>>>(dag);
    xr_k<<<8192, 256>>>(X);

    for (int l = 0; l < 4; l++) {
        const float* Amf = Amaskf + (l ? 262144 : 0);
        const unsigned* Amb = Amaskb + (l ? 8192 : 0);
        {   // QKV: Xb @ Wqkvt^T -> scatter K/Qt/Vt (+bias+swish, rounded)
            GP p{}; p.A = Xb; p.lda = 256;
            p.B = Wqkvt + (size_t)l * 1536 * 256; p.ldb = 256;
            p.bias = Bqkv + l * 1536; p.dst0 = KQV; p.K = 256;
            gemm_tc<128, 1><<<dim3(12, 64, 1), 256, GEMM_SMEM128>>>(p);
        }
        {   // AQ = maskf @ Qt^T -> AQ4[z][i][hs]  (rounded)
            GP p{}; p.A = Amf; p.lda = 512;
            p.B = KQV + 4194304; p.ldb = 512;
            p.C = AQ4; p.K = 512;
            gemm_tc<128, 3><<<dim3(64, 4, 1), 256, GEMM_SMEM128>>>(p);
        }
        // fused scores + softmax + PV
        attn_k<<<dim3(8, 128), 512, ATTN_SMEM>>>(AQ4, KQV, KQV + 2 * 4194304, Amb, Ob);
        {   // mha = swish(Ob @ Wpt^T + bp): Mha exact + Mhar rounded
            GP p{}; p.A = Ob; p.lda = 512;
            p.B = Wpt + (size_t)l * 256 * 512; p.ldb = 512;
            p.bias = bp + l * 256; p.C = Mha; p.ldc = 256; p.dst0 = Mhar; p.K = 512;
            gemm_tc<64, 8><<<dim3(4, 64, 1), 256, GEMM_SMEM64>>>(p);
        }
        {   // ff = swish(Mhar @ W1t^T + b1)  (rounded)
            GP p{}; p.A = Mhar; p.lda = 256;
            p.B = W1t + (size_t)l * 1024 * 256; p.ldb = 256;
            p.bias = b1 + l * 1024; p.C = Ff; p.ldc = 1024; p.K = 256;
            gemm_tc<128, 4><<<dim3(8, 64, 1), 256, GEMM_SMEM128>>>(p);
        }
        {   // Xb = Ff @ W2t^T + b2 + Mha  (rounded)
            GP p{}; p.A = Ff; p.lda = 1024;
            p.B = W2t + (size_t)l * 256 * 1024; p.ldb = 1024;
            p.bias = b2 + l * 256; p.res = Mha; p.C = Xb; p.ldc = 256; p.K = 1024;
            gemm_tc<64, 5><<<dim3(4, 64, 1), 256, GEMM_SMEM64>>>(p);
        }
    }
    {   // lm head (exact output)
        GP p{}; p.A = Xb; p.lda = 256; p.B = Wlmt; p.ldb = 256;
        p.bias = blm; p.C = out; p.ldc = 256; p.K = 256;
        gemm_tc<64, 6><<<dim3(4, 64, 1), 256, GEMM_SMEM64>>>(p);
    }
}

// round 15
// speedup vs baseline: 1.1758x; 1.0521x over previous
#include <cuda_runtime.h>
#include <cstdint>

// ---------------------------------------------------------------------------
// CaT transformer, tf32 mma.sync (portable sm_100 target).
// R15: R14 base + smem-tiled transpose prep kernels (coalesced), ballot-built
// bit-mask, float2-paired epilogue stores. Bit-exact numerics
// (oracle rel_err 7.903782e-4).
// ---------------------------------------------------------------------------

#define DI __device__ __forceinline__

static DI float swishf(float x) { return x / (1.f + __expf(-x)); }

// ------------------------- static device scratch ---------------------------
__device__ float g_Wqkvt[4 * 1536 * 256];   // tf32
__device__ float g_Bqkv [4 * 1536];
__device__ float g_Wpt  [4 * 256 * 512];    // tf32
__device__ float g_W1t  [4 * 1024 * 256];   // tf32
__device__ float g_W2t  [4 * 256 * 1024];   // tf32
__device__ float g_Wlmt [256 * 256];        // tf32
__device__ float g_Amaskf[2 * 512 * 512];   // 0.0 / 1.0
__device__ unsigned g_Amaskb[2 * 512 * 16]; // bit-packed mask rows
__device__ float g_KQV[3 * 512 * 8192];     // K | Qt | Vt (tf32)
__device__ float g_AQ4[512 * 8192];         // [z][i][hs] tf32
__device__ float g_Ob [8192 * 512];         // tf32
__device__ float g_Mha[8192 * 256];         // exact residual
__device__ float g_Mhar[8192 * 256];        // tf32
__device__ float g_Ff [8192 * 1024];        // tf32
__device__ float g_Xb [8192 * 256];         // tf32

// --------------------------- helpers ---------------------------------------
DI unsigned tf32_rn(float x) {
    unsigned r;
    asm("cvt.rn.tf32.f32 %0, %1;" : "=r"(r) : "f"(x));
    return r;
}
DI float tf32f(float x) { return __uint_as_float(tf32_rn(x)); }
DI unsigned cvta_s(const void* p) { return (unsigned)__cvta_generic_to_shared(p); }
DI void cpa16(unsigned dst, const void* src) {
    asm volatile("cp.async.cg.shared.global [%0], [%1], 16;" :: "r"(dst), "l"(src) : "memory");
}
#define CPA_COMMIT() asm volatile("cp.async.commit_group;" ::: "memory")
#define CPA_WAIT(N)  asm volatile("cp.async.wait_group %0;" :: "n"(N) : "memory")

#define LDM_X4(r0, r1, r2, r3, addr) \
    asm volatile("ldmatrix.sync.aligned.m8n8.x4.shared.b16 {%0,%1,%2,%3}, [%4];" \
                 : "=r"(r0), "=r"(r1), "=r"(r2), "=r"(r3) : "r"(addr))
#define MMA_TF32(d, a, b) \
    asm volatile("mma.sync.aligned.m16n8k8.row.col.f32.tf32.tf32.f32 " \
                 "{%0,%1,%2,%3}, {%4,%5,%6,%7}, {%8,%9}, {%0,%1,%2,%3};" \
                 : "+f"((d)[0]), "+f"((d)[1]), "+f"((d)[2]), "+f"((d)[3]) \
                 : "r"((a)[0]), "r"((a)[1]), "r"((a)[2]), "r"((a)[3]), \
                   "r"((b)[0]), "r"((b)[1]))

// ------------------------------ prep kernels -------------------------------
// Generic batched 32x32 smem transpose with tf32 rounding.
// dst[n*M + m] = tf32(src[m*N + n]); batch strides sS/sD.
// qkv mode: dst base = dst + (bz>>3)*393216 + (bz&7)*16384 (t baked into dst).
struct TP { const float* src; float* dst; int M, N; long long sS, sD; int qkv; };

__global__ void tr_k(TP p) {
    __shared__ float s[32][33];
    const int bz = blockIdx.z;
    const float* src = p.src + (size_t)bz * p.sS;
    float* dst = p.qkv
        ? p.dst + (size_t)(bz >> 3) * 393216 + (size_t)(bz & 7) * 16384
        : p.dst + (size_t)bz * p.sD;
    const int tx = threadIdx.x, ty = threadIdx.y;
    const int m0 = blockIdx.y * 32, n0 = blockIdx.x * 32;
#pragma unroll
    for (int i = 0; i < 32; i += 8)
        s[ty + i][tx] = src[(size_t)(m0 + ty + i) * p.N + n0 + tx];
    __syncthreads();
#pragma unroll
    for (int i = 0; i < 32; i += 8)
        dst[(size_t)(n0 + ty + i) * p.M + m0 + tx] = tf32f(s[tx][ty + i]);
}

__global__ void bias_k(const float* __restrict__ bk, const float* __restrict__ bq,
                       const float* __restrict__ bv) {
    int idx = blockIdx.x * 256 + threadIdx.x;          // < 6144
    int ll = idx / 1536;
    int c = idx - ll * 1536;
    int tt = c >> 9, hh = (c >> 6) & 7, hss = c & 63;
    const float* bb = (tt == 0) ? bk : (tt == 1) ? bq : bv;
    g_Bqkv[idx] = bb[(ll * 8 + hh) * 64 + hss];
}

// maskf (transposed, coalesced both sides) + bit-packed maskb via ballot.
__global__ void mask2_k(const int* __restrict__ dag) {
    __shared__ float s[32][33];
    const int v = blockIdx.z;
    const int i0 = blockIdx.y * 32, j0 = blockIdx.x * 32;
    const int tx = threadIdx.x, ty = threadIdx.y;
    {   // load: (i = i0+tx, j = j0+ty); coalesced over tx
        const int i = i0 + tx, j = j0 + ty;
        s[ty][tx] = (dag[j * 512 + i] != 0 || (v && i == j)) ? 1.f : 0.f;
    }
    __syncthreads();
    const float mv = s[tx][ty];                        // (i = i0+ty, j = j0+tx)
    g_Amaskf[v * 262144 + (i0 + ty) * 512 + j0 + tx] = mv;
    const unsigned bits = __ballot_sync(0xffffffffu, mv != 0.f);
    if (tx == 0)
        g_Amaskb[v * 8192 + (i0 + ty) * 16 + blockIdx.x] = bits;
}

__global__ void xr_k(const float* __restrict__ X) {
    int i = blockIdx.x * 256 + threadIdx.x;            // < 2097152
    g_Xb[i] = tf32f(X[i]);
}

// ------------------------------- GEMM core ---------------------------------
struct GP {
    const float* A; const float* B; float* C;
    const float* bias; const float* res;
    float* dst0;
    int K, lda, ldb, ldc;
    long long sAz, sBz, sCz;
};

// BK=32, pitch 36, 3 stages.
static const int GEMM_SMEM128 = 3 * (128 * 36 + 128 * 36) * 4;   // 110592 B
static const int GEMM_SMEM64  = 3 * (128 * 36 +  64 * 36) * 4;   // 82944 B

// MODE: 1 QKV scatter  3 AQ scatter  4 bias+swish(rounded)  5 bias+res(rounded)
//       6 bias(exact)  8 bias+swish dual (C exact, dst0 rounded)
template <int BN, int MODE>
__global__ __launch_bounds__(256, 2) void gemm_tc(GP p) {
    constexpr int BM = 128, PITCH = 36, NS = 3;
    constexpr int WNW = (BN == 128) ? 4 : 2;
    constexpr int WM  = (BN == 128) ? 64 : 32;
    constexpr int WN  = 32;
    constexpr int MT = WM / 16, NT = WN / 8, NT2 = NT / 2;
    constexpr int ASZ = BM * PITCH, BSZ = BN * PITCH;
    constexpr int BLD = (BN * 32) / (4 * 256);

    extern __shared__ float dsm[];
    const unsigned sA = cvta_s(dsm);
    const unsigned sB = cvta_s(dsm + NS * ASZ);

    const int t = threadIdx.x, lane = t & 31, w = t >> 5;
    const int wm = w / WNW, wn = w % WNW;
    const int g = lane >> 2, cc = lane & 3;
    const int lrow = lane & 15;
    const unsigned loff = (unsigned)((lane >> 4) << 4);
    const int bx = blockIdx.x, by = blockIdx.y, bz = blockIdx.z;
    const int ar = t >> 3, ac = (t & 7) << 2;

    const float* Af = p.A + (size_t)bz * p.sAz + (size_t)by * BM * p.lda;
    const float* Bp = p.B + (size_t)bz * p.sBz + (size_t)bx * BN * p.ldb;
    float* C = p.C + (size_t)bz * p.sCz;

    float acc[MT][NT][4];
#pragma unroll
    for (int i = 0; i < MT; i++)
#pragma unroll
        for (int j = 0; j < NT; j++)
#pragma unroll
            for (int r = 0; r < 4; r++) acc[i][j][r] = 0.f;

    auto issue = [&](int ch, int s) {
        const int k0 = ch << 5;
#pragma unroll
        for (int i = 0; i < 4; i++) {
            const int r = ar + i * 32;
            cpa16(sA + (unsigned)((s * ASZ + r * PITCH + ac) * 4),
                  Af + (size_t)r * p.lda + k0 + ac);
        }
#pragma unroll
        for (int i = 0; i < BLD; i++) {
            const int r = ar + i * 32;
            cpa16(sB + (unsigned)((s * BSZ + r * PITCH + ac) * 4),
                  Bp + (size_t)r * p.ldb + k0 + ac);
        }
        CPA_COMMIT();
    };

    const int nch = p.K >> 5;
    issue(0, 0); issue(1, 1);
    for (int c = 0; c < nch; c++) {
        CPA_WAIT(1);
        __syncthreads();
        if (c + 2 < nch) issue(c + 2, (c + 2) % 3); else CPA_COMMIT();
        const int buf = c % 3;
#pragma unroll
        for (int ks = 0; ks < 4; ks++) {
            unsigned a[MT][4], b[NT][2];
#pragma unroll
            for (int i = 0; i < MT; i++) {
                const unsigned addr = sA + (unsigned)((buf * ASZ
                                    + (wm * WM + i * 16 + lrow) * PITCH + ks * 8) * 4) + loff;
                LDM_X4(a[i][0], a[i][1], a[i][2], a[i][3], addr);
            }
#pragma unroll
            for (int j2 = 0; j2 < NT2; j2++) {
                const unsigned addr = sB + (unsigned)((buf * BSZ
                                    + (wn * WN + j2 * 16 + lrow) * PITCH + ks * 8) * 4) + loff;
                LDM_X4(b[2 * j2][0], b[2 * j2 + 1][0], b[2 * j2][1], b[2 * j2 + 1][1], addr);
            }
#pragma unroll
            for (int i = 0; i < MT; i++)
#pragma unroll
                for (int j = 0; j < NT; j++)
                    MMA_TF32(acc[i][j], a[i], b[j]);
        }
    }

    // ---------------- epilogue: float2-paired stores -----------------------
#pragma unroll
    for (int i = 0; i < MT; i++)
#pragma unroll
        for (int j = 0; j < NT; j++)
#pragma unroll
            for (int h2 = 0; h2 < 2; h2++) {
                const int gm = by * BM + wm * WM + i * 16 + h2 * 8 + g;
                const int gn = bx * BN + wn * WN + j * 8 + (cc << 1);
                const float v0 = acc[i][j][h2 * 2 + 0];
                const float v1 = acc[i][j][h2 * 2 + 1];
                if (MODE == 1) {
                    const float e0 = swishf(v0 + p.bias[gn]);
                    const float e1 = swishf(v1 + p.bias[gn + 1]);
                    const int tt = gn >> 9, h = (gn >> 6) & 7, hs = gn & 63;
                    const int b = gm >> 9, n = gm & 511, z = b * 8 + h;
                    if (tt == 0) {
                        *(float2*)&p.dst0[(size_t)(z * 512 + n) * 64 + hs] =
                            make_float2(tf32f(e0), tf32f(e1));
                    } else if (tt == 1) {
                        p.dst0[4194304u + (size_t)(z * 64 + hs) * 512 + n] = tf32f(e0);
                        p.dst0[4194304u + (size_t)(z * 64 + hs + 1) * 512 + n] = tf32f(e1);
                    } else {
                        p.dst0[8388608u + (size_t)(z * 64 + hs) * 512 + n] = tf32f(e0);
                        p.dst0[8388608u + (size_t)(z * 64 + hs + 1) * 512 + n] = tf32f(e1);
                    }
                } else if (MODE == 3) {
                    *(float2*)&p.C[(size_t)(gn >> 6) * 32768 + (size_t)gm * 64 + (gn & 63)] =
                        make_float2(tf32f(v0), tf32f(v1));
                } else if (MODE == 4) {
                    *(float2*)&C[(size_t)gm * p.ldc + gn] =
                        make_float2(tf32f(swishf(v0 + p.bias[gn])),
                                    tf32f(swishf(v1 + p.bias[gn + 1])));
                } else if (MODE == 5) {
                    const float2 rr = *(const float2*)&p.res[(size_t)gm * p.ldc + gn];
                    *(float2*)&C[(size_t)gm * p.ldc + gn] =
                        make_float2(tf32f(v0 + p.bias[gn] + rr.x),
                                    tf32f(v1 + p.bias[gn + 1] + rr.y));
                } else if (MODE == 6) {
                    *(float2*)&C[(size_t)gm * p.ldc + gn] =
                        make_float2(v0 + p.bias[gn], v1 + p.bias[gn + 1]);
                } else {   // MODE 8
                    const float e0 = swishf(v0 + p.bias[gn]);
                    const float e1 = swishf(v1 + p.bias[gn + 1]);
                    *(float2*)&C[(size_t)gm * p.ldc + gn] = make_float2(e0, e1);
                    *(float2*)&p.dst0[(size_t)gm * p.ldc + gn] =
                        make_float2(tf32f(e0), tf32f(e1));
                }
            }
}

// ------------------- fused attention: scores+softmax+PV --------------------
// Grid (8 i-tiles, 128 z), 512 threads (16 warps). Single sync per chunk.
// smem floats: S 64x516 @0 | At 64x68 @33024 | Bt @37376
static const int ATTN_SMEM = (33024 + 4352 + 17408) * 4;   // 219136 B

__global__ __launch_bounds__(512) void attn_k(
    const float* __restrict__ AQ, const float* __restrict__ Kb,
    const float* __restrict__ Vt, const unsigned* __restrict__ Mb,
    float* __restrict__ Ob) {
    extern __shared__ float sm[];
    float* S = sm;

    const int t = threadIdx.x, lane = t & 31, w = t >> 5;     // w: 0..15
    const int g = lane >> 2, cc = lane & 3;
    const int lrow = lane & 15;
    const unsigned loff = (unsigned)((lane >> 4) << 4);
    const int i0 = blockIdx.x * 64, z = blockIdx.y;

    const float* AQz = AQ + (size_t)z * 32768 + (size_t)i0 * 64;   // 64 x 64
    const float* Kp  = Kb + (size_t)z * 32768;                     // 512 x 64
    const float* Vz  = Vt + (size_t)z * 32768;                     // 64 x 512

    const unsigned sS = cvta_s(S);
    const unsigned sA = cvta_s(sm + 33024);
    const unsigned sB = cvta_s(sm + 37376);

    // ---- prologue: cp.async At (64x64 -> pitch 68) + K chunk 0 ------------
#pragma unroll
    for (int i = 0; i < 2; i++) {
        const int idx = i * 512 + t;
        const int r = idx >> 4, c = (idx & 15) << 2;
        cpa16(sA + (unsigned)((r * 68 + c) * 4), AQz + (size_t)r * 64 + c);
    }
    auto issueK = [&](int jc, int s) {
#pragma unroll
        for (int i = 0; i < 4; i++) {
            const int idx = i * 512 + t;
            const int r = idx >> 4, c = (idx & 15) << 2;
            cpa16(sB + (unsigned)((s * 8704 + r * 68 + c) * 4),
                  Kp + (size_t)(jc * 128 + r) * 64 + c);
        }
        CPA_COMMIT();
    };
    issueK(0, 0);   // single group: At + K0

    // ================= phase 1: S = AQ @ K^T, mask+scale ====================
    {
        const int wm = w >> 2, wn = w & 3;      // 4x4 warps: 16 rows x 32 cols
        for (int jc = 0; jc < 4; jc++) {
            CPA_WAIT(0);
            __syncthreads();
            if (jc + 1 < 4) issueK(jc + 1, (jc + 1) & 1);
            float acc[4][4];
#pragma unroll
            for (int j = 0; j < 4; j++)
#pragma unroll
                for (int r = 0; r < 4; r++) acc[j][r] = 0.f;
            const int buf = jc & 1;
#pragma unroll
            for (int ks = 0; ks < 8; ks++) {
                unsigned a[4], b[4][2];
                {
                    const unsigned addr = sA + (unsigned)(((wm * 16 + lrow) * 68
                                        + ks * 8) * 4) + loff;
                    LDM_X4(a[0], a[1], a[2], a[3], addr);
                }
#pragma unroll
                for (int j2 = 0; j2 < 2; j2++) {
                    const unsigned addr = sB + (unsigned)((buf * 8704
                                        + (wn * 32 + j2 * 16 + lrow) * 68 + ks * 8) * 4) + loff;
                    LDM_X4(b[2 * j2][0], b[2 * j2 + 1][0], b[2 * j2][1], b[2 * j2 + 1][1], addr);
                }
#pragma unroll
                for (int j = 0; j < 4; j++)
                    MMA_TF32(acc[j], a, b[j]);
            }
            // epilogue: bit-mask + scale -> S (float2-paired smem stores)
            const unsigned mw0 = Mb[(size_t)(i0 + wm * 16 + g) * 16 + jc * 4 + wn];
            const unsigned mw1 = Mb[(size_t)(i0 + wm * 16 + 8 + g) * 16 + jc * 4 + wn];
#pragma unroll
            for (int j = 0; j < 4; j++)
#pragma unroll
                for (int h2 = 0; h2 < 2; h2++) {
                    const int gm = wm * 16 + h2 * 8 + g;
                    const int gn = jc * 128 + wn * 32 + j * 8 + (cc << 1);
                    const unsigned mw = h2 ? mw1 : mw0;
                    const int bp = j * 8 + (cc << 1);
                    const float s0 = ((mw >> bp) & 1u) ? acc[j][h2 * 2] * 0.125f : -3.0e38f;
                    const float s1 = ((mw >> (bp + 1)) & 1u) ? acc[j][h2 * 2 + 1] * 0.125f : -3.0e38f;
                    *(float2*)&S[gm * 516 + gn] = make_float2(s0, s1);
                }
        }
    }
    __syncthreads();   // all S written before softmax (and before V overwrites Bt)

    // ---- overlap: start V chunk 0 copy before softmax ----
    auto issueV = [&](int kc, int s) {
#pragma unroll
        for (int i = 0; i < 4; i++) {
            const int idx = i * 512 + t;
            const int r = idx >> 5, c = (idx & 31) << 2;
            cpa16(sB + (unsigned)((s * 8448 + r * 132 + c) * 4),
                  Vz + (size_t)r * 512 + kc * 128 + c);
        }
        CPA_COMMIT();
    };
    issueV(0, 0);

    // ================= phase 2: exact softmax + (P + A), tf32 ===============
    for (int it = 0; it < 4; it++) {
        const int ir = it * 16 + w;
        float* r = S + ir * 516;
        const unsigned* mwp = Mb + (size_t)(i0 + ir) * 16;
        float x[16];
        float m = -3.4e38f;
#pragma unroll
        for (int k = 0; k < 16; k++) { x[k] = r[k * 32 + lane]; m = fmaxf(m, x[k]); }
#pragma unroll
        for (int o = 16; o; o >>= 1) m = fmaxf(m, __shfl_xor_sync(0xffffffffu, m, o));
        if (m <= -1e37f) {
#pragma unroll
            for (int k = 0; k < 16; k++) r[k * 32 + lane] = 0.f;
        } else {
            float s = 0.f;
#pragma unroll
            for (int k = 0; k < 16; k++) { x[k] = __expf(x[k] - m); s += x[k]; }
#pragma unroll
            for (int o = 16; o; o >>= 1) s += __shfl_xor_sync(0xffffffffu, s, o);
            const float inv = 1.f / s;
#pragma unroll
            for (int k = 0; k < 16; k++)
                r[k * 32 + lane] =
                    tf32f(x[k] * inv + (float)((mwp[k] >> lane) & 1u));
        }
    }
    __syncthreads();

    // ================= phase 3: O = Ssm @ V^T (4 x K=128 chunks) ============
    {
        const int wm = w >> 2, wn = w & 3;      // 4x4 warps: 16 rows x 16 cols
        float oa[2][4];
#pragma unroll
        for (int j = 0; j < 2; j++)
#pragma unroll
            for (int r = 0; r < 4; r++) oa[j][r] = 0.f;
        for (int kc = 0; kc < 4; kc++) {
            CPA_WAIT(0);
            __syncthreads();
            if (kc + 1 < 4) issueV(kc + 1, (kc + 1) & 1);
            const int buf = kc & 1;
#pragma unroll
            for (int ks = 0; ks < 16; ks++) {
                unsigned a[4], b[2][2];
                {
                    const unsigned addr = sS + (unsigned)(((wm * 16 + lrow) * 516
                                        + kc * 128 + ks * 8) * 4) + loff;
                    LDM_X4(a[0], a[1], a[2], a[3], addr);
                }
                {
                    const unsigned addr = sB + (unsigned)((buf * 8448
                                        + (wn * 16 + lrow) * 132 + ks * 8) * 4) + loff;
                    LDM_X4(b[0][0], b[1][0], b[0][1], b[1][1], addr);
                }
#pragma unroll
                for (int j = 0; j < 2; j++)
                    MMA_TF32(oa[j], a, b[j]);
            }
        }
        // epilogue -> Ob (float2-paired, rounded)
        const int b = z >> 3, h = z & 7;
#pragma unroll
        for (int j = 0; j < 2; j++)
#pragma unroll
            for (int h2 = 0; h2 < 2; h2++) {
                const int gm = wm * 16 + h2 * 8 + g;
                const int gn = wn * 16 + j * 8 + (cc << 1);
                *(float2*)&Ob[(size_t)(b * 512 + i0 + gm) * 512 + h * 64 + gn] =
                    make_float2(tf32f(oa[j][h2 * 2]), tf32f(oa[j][h2 * 2 + 1]));
            }
    }
}

// ------------------------------ host driver --------------------------------
extern "C" void kernel_launch(void* const* d_in, const int* in_sizes, int n_in,
                              void* d_out, int out_size) {
    (void)in_sizes; (void)n_in; (void)out_size;
    const float* X   = (const float*)d_in[0];
    const int*   dag = (const int*)d_in[1];
    const float* Wk  = (const float*)d_in[2],  *bk  = (const float*)d_in[3];
    const float* Wq  = (const float*)d_in[4],  *bq  = (const float*)d_in[5];
    const float* Wv  = (const float*)d_in[6],  *bv  = (const float*)d_in[7];
    const float* Wp  = (const float*)d_in[8],  *bp  = (const float*)d_in[9];
    const float* W1  = (const float*)d_in[10], *b1  = (const float*)d_in[11];
    const float* W2  = (const float*)d_in[12], *b2  = (const float*)d_in[13];
    const float* Wlm = (const float*)d_in[14], *blm = (const float*)d_in[15];
    float* out = (float*)d_out;

    cudaFuncSetAttribute(gemm_tc<128, 1>, cudaFuncAttributeMaxDynamicSharedMemorySize, GEMM_SMEM128);
    cudaFuncSetAttribute(gemm_tc<128, 3>, cudaFuncAttributeMaxDynamicSharedMemorySize, GEMM_SMEM128);
    cudaFuncSetAttribute(gemm_tc<128, 4>, cudaFuncAttributeMaxDynamicSharedMemorySize, GEMM_SMEM128);
    cudaFuncSetAttribute(gemm_tc<64, 8>,  cudaFuncAttributeMaxDynamicSharedMemorySize, GEMM_SMEM64);
    cudaFuncSetAttribute(gemm_tc<64, 5>,  cudaFuncAttributeMaxDynamicSharedMemorySize, GEMM_SMEM64);
    cudaFuncSetAttribute(gemm_tc<64, 6>,  cudaFuncAttributeMaxDynamicSharedMemorySize, GEMM_SMEM64);
    cudaFuncSetAttribute(attn_k, cudaFuncAttributeMaxDynamicSharedMemorySize, ATTN_SMEM);

    void* pv;
    cudaGetSymbolAddress(&pv, g_Wqkvt); float* Wqkvt = (float*)pv;
    cudaGetSymbolAddress(&pv, g_Bqkv);  float* Bqkv  = (float*)pv;
    cudaGetSymbolAddress(&pv, g_Wpt);   float* Wpt   = (float*)pv;
    cudaGetSymbolAddress(&pv, g_W1t);   float* W1t   = (float*)pv;
    cudaGetSymbolAddress(&pv, g_W2t);   float* W2t   = (float*)pv;
    cudaGetSymbolAddress(&pv, g_Wlmt);  float* Wlmt  = (float*)pv;
    cudaGetSymbolAddress(&pv, g_Amaskf); float* Amaskf = (float*)pv;
    cudaGetSymbolAddress(&pv, g_Amaskb); unsigned* Amaskb = (unsigned*)pv;
    cudaGetSymbolAddress(&pv, g_KQV);   float* KQV = (float*)pv;
    cudaGetSymbolAddress(&pv, g_AQ4);   float* AQ4 = (float*)pv;
    cudaGetSymbolAddress(&pv, g_Ob);    float* Ob  = (float*)pv;
    cudaGetSymbolAddress(&pv, g_Mha);   float* Mha = (float*)pv;
    cudaGetSymbolAddress(&pv, g_Mhar);  float* Mhar = (float*)pv;
    cudaGetSymbolAddress(&pv, g_Ff);    float* Ff  = (float*)pv;
    cudaGetSymbolAddress(&pv, g_Xb);    float* Xb  = (float*)pv;

    // ---- prep: coalesced smem-tiled transposes ----
    {
        TP tp{}; tp.qkv = 1; tp.M = 256; tp.N = 64; tp.sS = 16384; tp.sD = 0;
        tp.src = Wk; tp.dst = Wqkvt + 0 * 131072;
        tr_k<<<dim3(2, 8, 32), dim3(32, 8)>>>(tp);
        tp.src = Wq; tp.dst = Wqkvt + 1 * 131072;
        tr_k<<<dim3(2, 8, 32), dim3(32, 8)>>>(tp);
        tp.src = Wv; tp.dst = Wqkvt + 2 * 131072;
        tr_k<<<dim3(2, 8, 32), dim3(32, 8)>>>(tp);
    }
    bias_k<<<24, 256>>>(bk, bq, bv);
    {
        TP tp{}; tp.qkv = 0;
        tp.src = Wp; tp.dst = Wpt; tp.M = 512; tp.N = 256;
        tp.sS = 131072; tp.sD = 131072;
        tr_k<<<dim3(8, 16, 4), dim3(32, 8)>>>(tp);
        tp.src = W1; tp.dst = W1t; tp.M = 256; tp.N = 1024;
        tp.sS = 262144; tp.sD = 262144;
        tr_k<<<dim3(32, 8, 4), dim3(32, 8)>>>(tp);
        tp.src = W2; tp.dst = W2t; tp.M = 1024; tp.N = 256;
        tp.sS = 262144; tp.sD = 262144;
        tr_k<<<dim3(8, 32, 4), dim3(32, 8)>>>(tp);
        tp.src = Wlm; tp.dst = Wlmt; tp.M = 256; tp.N = 256;
        tp.sS = 0; tp.sD = 0;
        tr_k<<<dim3(8, 8, 1), dim3(32, 8)>>>(tp);
    }
    mask2_k<<<dim3(16, 16, 2), dim3(32, 32)>>>(dag);
    xr_k<<<8192, 256>>>(X);

    for (int l = 0; l < 4; l++) {
        const float* Amf = Amaskf + (l ? 262144 : 0);
        const unsigned* Amb = Amaskb + (l ? 8192 : 0);
        {   // QKV: Xb @ Wqkvt^T -> scatter K/Qt/Vt (+bias+swish, rounded)
            GP p{}; p.A = Xb; p.lda = 256;
            p.B = Wqkvt + (size_t)l * 1536 * 256; p.ldb = 256;
            p.bias = Bqkv + l * 1536; p.dst0 = KQV; p.K = 256;
            gemm_tc<128, 1><<<dim3(12, 64, 1), 256, GEMM_SMEM128>>>(p);
        }
        {   // AQ = maskf @ Qt^T -> AQ4[z][i][hs]  (rounded)
            GP p{}; p.A = Amf; p.lda = 512;
            p.B = KQV + 4194304; p.ldb = 512;
            p.C = AQ4; p.K = 512;
            gemm_tc<128, 3><<<dim3(64, 4, 1), 256, GEMM_SMEM128>>>(p);
        }
        // fused scores + softmax + PV
        attn_k<<<dim3(8, 128), 512, ATTN_SMEM>>>(AQ4, KQV, KQV + 2 * 4194304, Amb, Ob);
        {   // mha = swish(Ob @ Wpt^T + bp): Mha exact + Mhar rounded
            GP p{}; p.A = Ob; p.lda = 512;
            p.B = Wpt + (size_t)l * 256 * 512; p.ldb = 512;
            p.bias = bp + l * 256; p.C = Mha; p.ldc = 256; p.dst0 = Mhar; p.K = 512;
            gemm_tc<64, 8><<<dim3(4, 64, 1), 256, GEMM_SMEM64>>>(p);
        }
        {   // ff = swish(Mhar @ W1t^T + b1)  (rounded)
            GP p{}; p.A = Mhar; p.lda = 256;
            p.B = W1t + (size_t)l * 1024 * 256; p.ldb = 256;
            p.bias = b1 + l * 1024; p.C = Ff; p.ldc = 1024; p.K = 256;
            gemm_tc<128, 4><<<dim3(8, 64, 1), 256, GEMM_SMEM128>>>(p);
        }
        {   // Xb = Ff @ W2t^T + b2 + Mha  (rounded)
            GP p{}; p.A = Ff; p.lda = 1024;
            p.B = W2t + (size_t)l * 256 * 1024; p.ldb = 1024;
            p.bias = b2 + l * 256; p.res = Mha; p.C = Xb; p.ldc = 256; p.K = 1024;
            gemm_tc<64, 5><<<dim3(4, 64, 1), 256, GEMM_SMEM64>>>(p);
        }
    }
    {   // lm head (exact output)
        GP p{}; p.A = Xb; p.lda = 256; p.B = Wlmt; p.ldb = 256;
        p.bias = blm; p.C = out; p.ldc = 256; p.K = 256;
        gemm_tc<64, 6><<<dim3(4, 64, 1), 256, GEMM_SMEM64>>>(p);
    }
}

// round 16
// speedup vs baseline: 1.1921x; 1.0139x over previous
#include <cuda_runtime.h>
#include <cstdint>

// ---------------------------------------------------------------------------
// CaT transformer, tf32 mma.sync (portable sm_100 target).
// R16: R15 base + smem-staged transposed (coalesced) Qt/Vt stores in the QKV
// GEMM epilogue; merged QKV weight transposes. Bit-exact numerics
// (oracle rel_err 7.903782e-4).
// ---------------------------------------------------------------------------

#define DI __device__ __forceinline__

static DI float swishf(float x) { return x / (1.f + __expf(-x)); }

// ------------------------- static device scratch ---------------------------
__device__ float g_Wqkvt[4 * 1536 * 256];   // tf32
__device__ float g_Bqkv [4 * 1536];
__device__ float g_Wpt  [4 * 256 * 512];    // tf32
__device__ float g_W1t  [4 * 1024 * 256];   // tf32
__device__ float g_W2t  [4 * 256 * 1024];   // tf32
__device__ float g_Wlmt [256 * 256];        // tf32
__device__ float g_Amaskf[2 * 512 * 512];   // 0.0 / 1.0
__device__ unsigned g_Amaskb[2 * 512 * 16]; // bit-packed mask rows
__device__ float g_KQV[3 * 512 * 8192];     // K | Qt | Vt (tf32)
__device__ float g_AQ4[512 * 8192];         // [z][i][hs] tf32
__device__ float g_Ob [8192 * 512];         // tf32
__device__ float g_Mha[8192 * 256];         // exact residual
__device__ float g_Mhar[8192 * 256];        // tf32
__device__ float g_Ff [8192 * 1024];        // tf32
__device__ float g_Xb [8192 * 256];         // tf32

// --------------------------- helpers ---------------------------------------
DI unsigned tf32_rn(float x) {
    unsigned r;
    asm("cvt.rn.tf32.f32 %0, %1;" : "=r"(r) : "f"(x));
    return r;
}
DI float tf32f(float x) { return __uint_as_float(tf32_rn(x)); }
DI unsigned cvta_s(const void* p) { return (unsigned)__cvta_generic_to_shared(p); }
DI void cpa16(unsigned dst, const void* src) {
    asm volatile("cp.async.cg.shared.global [%0], [%1], 16;" :: "r"(dst), "l"(src) : "memory");
}
#define CPA_COMMIT() asm volatile("cp.async.commit_group;" ::: "memory")
#define CPA_WAIT(N)  asm volatile("cp.async.wait_group %0;" :: "n"(N) : "memory")

#define LDM_X4(r0, r1, r2, r3, addr) \
    asm volatile("ldmatrix.sync.aligned.m8n8.x4.shared.b16 {%0,%1,%2,%3}, [%4];" \
                 : "=r"(r0), "=r"(r1), "=r"(r2), "=r"(r3) : "r"(addr))
#define MMA_TF32(d, a, b) \
    asm volatile("mma.sync.aligned.m16n8k8.row.col.f32.tf32.tf32.f32 " \
                 "{%0,%1,%2,%3}, {%4,%5,%6,%7}, {%8,%9}, {%0,%1,%2,%3};" \
                 : "+f"((d)[0]), "+f"((d)[1]), "+f"((d)[2]), "+f"((d)[3]) \
                 : "r"((a)[0]), "r"((a)[1]), "r"((a)[2]), "r"((a)[3]), \
                   "r"((b)[0]), "r"((b)[1]))

// ------------------------------ prep kernels -------------------------------
// Merged QKV weight transpose: z = 96 blocks of 32x32 tiles.
// bz: sel = bz/32 (k/q/v), within = bz%32 -> (l = within>>3, h = within&7).
struct TP3 { const float* s0; const float* s1; const float* s2; float* dst; };

__global__ void tr3_k(TP3 p) {
    __shared__ float s[32][33];
    const int bz = blockIdx.z;
    const int sel = bz >> 5, within = bz & 31;
    const float* src = ((sel == 0) ? p.s0 : (sel == 1) ? p.s1 : p.s2)
                     + (size_t)within * 16384;          // [256 x 64] slab
    float* dst = p.dst + (size_t)sel * 131072
               + (size_t)(within >> 3) * 393216 + (size_t)(within & 7) * 16384;
    const int tx = threadIdx.x, ty = threadIdx.y;
    const int m0 = blockIdx.y * 32, n0 = blockIdx.x * 32;
#pragma unroll
    for (int i = 0; i < 32; i += 8)
        s[ty + i][tx] = src[(size_t)(m0 + ty + i) * 64 + n0 + tx];
    __syncthreads();
#pragma unroll
    for (int i = 0; i < 32; i += 8)
        dst[(size_t)(n0 + ty + i) * 256 + m0 + tx] = tf32f(s[tx][ty + i]);
}

// Generic batched 32x32 transpose with tf32 rounding.
struct TP { const float* src; float* dst; int M, N; long long sS, sD; };

__global__ void tr_k(TP p) {
    __shared__ float s[32][33];
    const int bz = blockIdx.z;
    const float* src = p.src + (size_t)bz * p.sS;
    float* dst = p.dst + (size_t)bz * p.sD;
    const int tx = threadIdx.x, ty = threadIdx.y;
    const int m0 = blockIdx.y * 32, n0 = blockIdx.x * 32;
#pragma unroll
    for (int i = 0; i < 32; i += 8)
        s[ty + i][tx] = src[(size_t)(m0 + ty + i) * p.N + n0 + tx];
    __syncthreads();
#pragma unroll
    for (int i = 0; i < 32; i += 8)
        dst[(size_t)(n0 + ty + i) * p.M + m0 + tx] = tf32f(s[tx][ty + i]);
}

__global__ void bias_k(const float* __restrict__ bk, const float* __restrict__ bq,
                       const float* __restrict__ bv) {
    int idx = blockIdx.x * 256 + threadIdx.x;          // < 6144
    int ll = idx / 1536;
    int c = idx - ll * 1536;
    int tt = c >> 9, hh = (c >> 6) & 7, hss = c & 63;
    const float* bb = (tt == 0) ? bk : (tt == 1) ? bq : bv;
    g_Bqkv[idx] = bb[(ll * 8 + hh) * 64 + hss];
}

__global__ void mask2_k(const int* __restrict__ dag) {
    __shared__ float s[32][33];
    const int v = blockIdx.z;
    const int i0 = blockIdx.y * 32, j0 = blockIdx.x * 32;
    const int tx = threadIdx.x, ty = threadIdx.y;
    {
        const int i = i0 + tx, j = j0 + ty;
        s[ty][tx] = (dag[j * 512 + i] != 0 || (v && i == j)) ? 1.f : 0.f;
    }
    __syncthreads();
    const float mv = s[tx][ty];
    g_Amaskf[v * 262144 + (i0 + ty) * 512 + j0 + tx] = mv;
    const unsigned bits = __ballot_sync(0xffffffffu, mv != 0.f);
    if (tx == 0)
        g_Amaskb[v * 8192 + (i0 + ty) * 16 + blockIdx.x] = bits;
}

__global__ void xr_k(const float* __restrict__ X) {
    int i = blockIdx.x * 256 + threadIdx.x;            // < 2097152
    g_Xb[i] = tf32f(X[i]);
}

// ------------------------------- GEMM core ---------------------------------
struct GP {
    const float* A; const float* B; float* C;
    const float* bias; const float* res;
    float* dst0;
    int K, lda, ldb, ldc;
    long long sAz, sBz, sCz;
};

// BK=32, pitch 36, 3 stages.
static const int GEMM_SMEM128 = 3 * (128 * 36 + 128 * 36) * 4;   // 110592 B
static const int GEMM_SMEM64  = 3 * (128 * 36 +  64 * 36) * 4;   // 82944 B

// MODE: 1 QKV scatter  3 AQ scatter  4 bias+swish(rounded)  5 bias+res(rounded)
//       6 bias(exact)  8 bias+swish dual (C exact, dst0 rounded)
template <int BN, int MODE>
__global__ __launch_bounds__(256, 2) void gemm_tc(GP p) {
    constexpr int BM = 128, PITCH = 36, NS = 3;
    constexpr int WNW = (BN == 128) ? 4 : 2;
    constexpr int WM  = (BN == 128) ? 64 : 32;
    constexpr int WN  = 32;
    constexpr int MT = WM / 16, NT = WN / 8, NT2 = NT / 2;
    constexpr int ASZ = BM * PITCH, BSZ = BN * PITCH;
    constexpr int BLD = (BN * 32) / (4 * 256);

    extern __shared__ float dsm[];
    const unsigned sA = cvta_s(dsm);
    const unsigned sB = cvta_s(dsm + NS * ASZ);

    const int t = threadIdx.x, lane = t & 31, w = t >> 5;
    const int wm = w / WNW, wn = w % WNW;
    const int g = lane >> 2, cc = lane & 3;
    const int lrow = lane & 15;
    const unsigned loff = (unsigned)((lane >> 4) << 4);
    const int bx = blockIdx.x, by = blockIdx.y, bz = blockIdx.z;
    const int ar = t >> 3, ac = (t & 7) << 2;

    const float* Af = p.A + (size_t)bz * p.sAz + (size_t)by * BM * p.lda;
    const float* Bp = p.B + (size_t)bz * p.sBz + (size_t)bx * BN * p.ldb;
    float* C = p.C + (size_t)bz * p.sCz;

    float acc[MT][NT][4];
#pragma unroll
    for (int i = 0; i < MT; i++)
#pragma unroll
        for (int j = 0; j < NT; j++)
#pragma unroll
            for (int r = 0; r < 4; r++) acc[i][j][r] = 0.f;

    auto issue = [&](int ch, int s) {
        const int k0 = ch << 5;
#pragma unroll
        for (int i = 0; i < 4; i++) {
            const int r = ar + i * 32;
            cpa16(sA + (unsigned)((s * ASZ + r * PITCH + ac) * 4),
                  Af + (size_t)r * p.lda + k0 + ac);
        }
#pragma unroll
        for (int i = 0; i < BLD; i++) {
            const int r = ar + i * 32;
            cpa16(sB + (unsigned)((s * BSZ + r * PITCH + ac) * 4),
                  Bp + (size_t)r * p.ldb + k0 + ac);
        }
        CPA_COMMIT();
    };

    const int nch = p.K >> 5;
    issue(0, 0); issue(1, 1);
    for (int c = 0; c < nch; c++) {
        CPA_WAIT(1);
        __syncthreads();
        if (c + 2 < nch) issue(c + 2, (c + 2) % 3); else CPA_COMMIT();
        const int buf = c % 3;
#pragma unroll
        for (int ks = 0; ks < 4; ks++) {
            unsigned a[MT][4], b[NT][2];
#pragma unroll
            for (int i = 0; i < MT; i++) {
                const unsigned addr = sA + (unsigned)((buf * ASZ
                                    + (wm * WM + i * 16 + lrow) * PITCH + ks * 8) * 4) + loff;
                LDM_X4(a[i][0], a[i][1], a[i][2], a[i][3], addr);
            }
#pragma unroll
            for (int j2 = 0; j2 < NT2; j2++) {
                const unsigned addr = sB + (unsigned)((buf * BSZ
                                    + (wn * WN + j2 * 16 + lrow) * PITCH + ks * 8) * 4) + loff;
                LDM_X4(b[2 * j2][0], b[2 * j2 + 1][0], b[2 * j2][1], b[2 * j2 + 1][1], addr);
            }
#pragma unroll
            for (int i = 0; i < MT; i++)
#pragma unroll
                for (int j = 0; j < NT; j++)
                    MMA_TF32(acc[i][j], a[i], b[j]);
        }
    }

    // ---------------- epilogue -----------------
    if (MODE == 1 && bx >= 4) {
        // Q/V tile: stage transposed in smem, then coalesced float4 writes.
        __syncthreads();                       // mainloop smem reads done
        float* st = dsm;                       // 128 x pitch132 = 67584 B
#pragma unroll
        for (int i = 0; i < MT; i++)
#pragma unroll
            for (int j = 0; j < NT; j++)
#pragma unroll
                for (int h2 = 0; h2 < 2; h2++) {
                    const int gmL = wm * WM + i * 16 + h2 * 8 + g;
                    const int gnL = wn * WN + j * 8 + (cc << 1);
                    const int gn = bx * BN + gnL;
                    const float e0 = swishf(acc[i][j][h2 * 2] + p.bias[gn]);
                    const float e1 = swishf(acc[i][j][h2 * 2 + 1] + p.bias[gn + 1]);
                    st[gnL * 132 + gmL] = tf32f(e0);
                    st[(gnL + 1) * 132 + gmL] = tf32f(e1);
                }
        __syncthreads();
        const int b = by >> 2, n0 = (by & 3) * 128;
        const int tt = bx >> 2;                // 1 = Q, 2 = V
        float* dst = p.dst0 + (tt == 1 ? 4194304u : 8388608u);
        const int h0 = (bx * 2) & 7;
#pragma unroll
        for (int i = 0; i < 16; i++) {
            const int idx = i * 256 + t;       // 4096 float4s
            const int row = idx >> 5, c4 = (idx & 31) << 2;
            const int zrow = (b * 8 + h0 + (row >> 6)) * 64 + (row & 63);
            const float* sp = st + row * 132 + c4;
            *(float4*)&dst[(size_t)zrow * 512 + n0 + c4] =
                make_float4(sp[0], sp[1], sp[2], sp[3]);
        }
        return;
    }
#pragma unroll
    for (int i = 0; i < MT; i++)
#pragma unroll
        for (int j = 0; j < NT; j++)
#pragma unroll
            for (int h2 = 0; h2 < 2; h2++) {
                const int gm = by * BM + wm * WM + i * 16 + h2 * 8 + g;
                const int gn = bx * BN + wn * WN + j * 8 + (cc << 1);
                const float v0 = acc[i][j][h2 * 2 + 0];
                const float v1 = acc[i][j][h2 * 2 + 1];
                if (MODE == 1) {               // K tile only (bx < 4)
                    const float e0 = swishf(v0 + p.bias[gn]);
                    const float e1 = swishf(v1 + p.bias[gn + 1]);
                    const int h = (gn >> 6) & 7, hs = gn & 63;
                    const int b = gm >> 9, n = gm & 511, z = b * 8 + h;
                    *(float2*)&p.dst0[(size_t)(z * 512 + n) * 64 + hs] =
                        make_float2(tf32f(e0), tf32f(e1));
                } else if (MODE == 3) {
                    *(float2*)&p.C[(size_t)(gn >> 6) * 32768 + (size_t)gm * 64 + (gn & 63)] =
                        make_float2(tf32f(v0), tf32f(v1));
                } else if (MODE == 4) {
                    *(float2*)&C[(size_t)gm * p.ldc + gn] =
                        make_float2(tf32f(swishf(v0 + p.bias[gn])),
                                    tf32f(swishf(v1 + p.bias[gn + 1])));
                } else if (MODE == 5) {
                    const float2 rr = *(const float2*)&p.res[(size_t)gm * p.ldc + gn];
                    *(float2*)&C[(size_t)gm * p.ldc + gn] =
                        make_float2(tf32f(v0 + p.bias[gn] + rr.x),
                                    tf32f(v1 + p.bias[gn + 1] + rr.y));
                } else if (MODE == 6) {
                    *(float2*)&C[(size_t)gm * p.ldc + gn] =
                        make_float2(v0 + p.bias[gn], v1 + p.bias[gn + 1]);
                } else {   // MODE 8
                    const float e0 = swishf(v0 + p.bias[gn]);
                    const float e1 = swishf(v1 + p.bias[gn + 1]);
                    *(float2*)&C[(size_t)gm * p.ldc + gn] = make_float2(e0, e1);
                    *(float2*)&p.dst0[(size_t)gm * p.ldc + gn] =
                        make_float2(tf32f(e0), tf32f(e1));
                }
            }
}

// ------------------- fused attention: scores+softmax+PV --------------------
// Grid (8 i-tiles, 128 z), 512 threads (16 warps). Single sync per chunk.
// smem floats: S 64x516 @0 | At 64x68 @33024 | Bt @37376
static const int ATTN_SMEM = (33024 + 4352 + 17408) * 4;   // 219136 B

__global__ __launch_bounds__(512) void attn_k(
    const float* __restrict__ AQ, const float* __restrict__ Kb,
    const float* __restrict__ Vt, const unsigned* __restrict__ Mb,
    float* __restrict__ Ob) {
    extern __shared__ float sm[];
    float* S = sm;

    const int t = threadIdx.x, lane = t & 31, w = t >> 5;     // w: 0..15
    const int g = lane >> 2, cc = lane & 3;
    const int lrow = lane & 15;
    const unsigned loff = (unsigned)((lane >> 4) << 4);
    const int i0 = blockIdx.x * 64, z = blockIdx.y;

    const float* AQz = AQ + (size_t)z * 32768 + (size_t)i0 * 64;   // 64 x 64
    const float* Kp  = Kb + (size_t)z * 32768;                     // 512 x 64
    const float* Vz  = Vt + (size_t)z * 32768;                     // 64 x 512

    const unsigned sS = cvta_s(S);
    const unsigned sA = cvta_s(sm + 33024);
    const unsigned sB = cvta_s(sm + 37376);

    // ---- prologue: cp.async At (64x64 -> pitch 68) + K chunk 0 ------------
#pragma unroll
    for (int i = 0; i < 2; i++) {
        const int idx = i * 512 + t;
        const int r = idx >> 4, c = (idx & 15) << 2;
        cpa16(sA + (unsigned)((r * 68 + c) * 4), AQz + (size_t)r * 64 + c);
    }
    auto issueK = [&](int jc, int s) {
#pragma unroll
        for (int i = 0; i < 4; i++) {
            const int idx = i * 512 + t;
            const int r = idx >> 4, c = (idx & 15) << 2;
            cpa16(sB + (unsigned)((s * 8704 + r * 68 + c) * 4),
                  Kp + (size_t)(jc * 128 + r) * 64 + c);
        }
        CPA_COMMIT();
    };
    issueK(0, 0);   // single group: At + K0

    // ================= phase 1: S = AQ @ K^T, mask+scale ====================
    {
        const int wm = w >> 2, wn = w & 3;      // 4x4 warps: 16 rows x 32 cols
        for (int jc = 0; jc < 4; jc++) {
            CPA_WAIT(0);
            __syncthreads();
            if (jc + 1 < 4) issueK(jc + 1, (jc + 1) & 1);
            float acc[4][4];
#pragma unroll
            for (int j = 0; j < 4; j++)
#pragma unroll
                for (int r = 0; r < 4; r++) acc[j][r] = 0.f;
            const int buf = jc & 1;
#pragma unroll
            for (int ks = 0; ks < 8; ks++) {
                unsigned a[4], b[4][2];
                {
                    const unsigned addr = sA + (unsigned)(((wm * 16 + lrow) * 68
                                        + ks * 8) * 4) + loff;
                    LDM_X4(a[0], a[1], a[2], a[3], addr);
                }
#pragma unroll
                for (int j2 = 0; j2 < 2; j2++) {
                    const unsigned addr = sB + (unsigned)((buf * 8704
                                        + (wn * 32 + j2 * 16 + lrow) * 68 + ks * 8) * 4) + loff;
                    LDM_X4(b[2 * j2][0], b[2 * j2 + 1][0], b[2 * j2][1], b[2 * j2 + 1][1], addr);
                }
#pragma unroll
                for (int j = 0; j < 4; j++)
                    MMA_TF32(acc[j], a, b[j]);
            }
            // epilogue: bit-mask + scale -> S (float2-paired smem stores)
            const unsigned mw0 = Mb[(size_t)(i0 + wm * 16 + g) * 16 + jc * 4 + wn];
            const unsigned mw1 = Mb[(size_t)(i0 + wm * 16 + 8 + g) * 16 + jc * 4 + wn];
#pragma unroll
            for (int j = 0; j < 4; j++)
#pragma unroll
                for (int h2 = 0; h2 < 2; h2++) {
                    const int gm = wm * 16 + h2 * 8 + g;
                    const int gn = jc * 128 + wn * 32 + j * 8 + (cc << 1);
                    const unsigned mw = h2 ? mw1 : mw0;
                    const int bp = j * 8 + (cc << 1);
                    const float s0 = ((mw >> bp) & 1u) ? acc[j][h2 * 2] * 0.125f : -3.0e38f;
                    const float s1 = ((mw >> (bp + 1)) & 1u) ? acc[j][h2 * 2 + 1] * 0.125f : -3.0e38f;
                    *(float2*)&S[gm * 516 + gn] = make_float2(s0, s1);
                }
        }
    }
    __syncthreads();   // all S written before softmax (and before V overwrites Bt)

    // ---- overlap: start V chunk 0 copy before softmax ----
    auto issueV = [&](int kc, int s) {
#pragma unroll
        for (int i = 0; i < 4; i++) {
            const int idx = i * 512 + t;
            const int r = idx >> 5, c = (idx & 31) << 2;
            cpa16(sB + (unsigned)((s * 8448 + r * 132 + c) * 4),
                  Vz + (size_t)r * 512 + kc * 128 + c);
        }
        CPA_COMMIT();
    };
    issueV(0, 0);

    // ================= phase 2: exact softmax + (P + A), tf32 ===============
    for (int it = 0; it < 4; it++) {
        const int ir = it * 16 + w;
        float* r = S + ir * 516;
        const unsigned* mwp = Mb + (size_t)(i0 + ir) * 16;
        float x[16];
        float m = -3.4e38f;
#pragma unroll
        for (int k = 0; k < 16; k++) { x[k] = r[k * 32 + lane]; m = fmaxf(m, x[k]); }
#pragma unroll
        for (int o = 16; o; o >>= 1) m = fmaxf(m, __shfl_xor_sync(0xffffffffu, m, o));
        if (m <= -1e37f) {
#pragma unroll
            for (int k = 0; k < 16; k++) r[k * 32 + lane] = 0.f;
        } else {
            float s = 0.f;
#pragma unroll
            for (int k = 0; k < 16; k++) { x[k] = __expf(x[k] - m); s += x[k]; }
#pragma unroll
            for (int o = 16; o; o >>= 1) s += __shfl_xor_sync(0xffffffffu, s, o);
            const float inv = 1.f / s;
#pragma unroll
            for (int k = 0; k < 16; k++)
                r[k * 32 + lane] =
                    tf32f(x[k] * inv + (float)((mwp[k] >> lane) & 1u));
        }
    }
    __syncthreads();

    // ================= phase 3: O = Ssm @ V^T (4 x K=128 chunks) ============
    {
        const int wm = w >> 2, wn = w & 3;      // 4x4 warps: 16 rows x 16 cols
        float oa[2][4];
#pragma unroll
        for (int j = 0; j < 2; j++)
#pragma unroll
            for (int r = 0; r < 4; r++) oa[j][r] = 0.f;
        for (int kc = 0; kc < 4; kc++) {
            CPA_WAIT(0);
            __syncthreads();
            if (kc + 1 < 4) issueV(kc + 1, (kc + 1) & 1);
            const int buf = kc & 1;
#pragma unroll
            for (int ks = 0; ks < 16; ks++) {
                unsigned a[4], b[2][2];
                {
                    const unsigned addr = sS + (unsigned)(((wm * 16 + lrow) * 516
                                        + kc * 128 + ks * 8) * 4) + loff;
                    LDM_X4(a[0], a[1], a[2], a[3], addr);
                }
                {
                    const unsigned addr = sB + (unsigned)((buf * 8448
                                        + (wn * 16 + lrow) * 132 + ks * 8) * 4) + loff;
                    LDM_X4(b[0][0], b[1][0], b[0][1], b[1][1], addr);
                }
#pragma unroll
                for (int j = 0; j < 2; j++)
                    MMA_TF32(oa[j], a, b[j]);
            }
        }
        // epilogue -> Ob (float2-paired, rounded)
        const int b = z >> 3, h = z & 7;
#pragma unroll
        for (int j = 0; j < 2; j++)
#pragma unroll
            for (int h2 = 0; h2 < 2; h2++) {
                const int gm = wm * 16 + h2 * 8 + g;
                const int gn = wn * 16 + j * 8 + (cc << 1);
                *(float2*)&Ob[(size_t)(b * 512 + i0 + gm) * 512 + h * 64 + gn] =
                    make_float2(tf32f(oa[j][h2 * 2]), tf32f(oa[j][h2 * 2 + 1]));
            }
    }
}

// ------------------------------ host driver --------------------------------
extern "C" void kernel_launch(void* const* d_in, const int* in_sizes, int n_in,
                              void* d_out, int out_size) {
    (void)in_sizes; (void)n_in; (void)out_size;
    const float* X   = (const float*)d_in[0];
    const int*   dag = (const int*)d_in[1];
    const float* Wk  = (const float*)d_in[2],  *bk  = (const float*)d_in[3];
    const float* Wq  = (const float*)d_in[4],  *bq  = (const float*)d_in[5];
    const float* Wv  = (const float*)d_in[6],  *bv  = (const float*)d_in[7];
    const float* Wp  = (const float*)d_in[8],  *bp  = (const float*)d_in[9];
    const float* W1  = (const float*)d_in[10], *b1  = (const float*)d_in[11];
    const float* W2  = (const float*)d_in[12], *b2  = (const float*)d_in[13];
    const float* Wlm = (const float*)d_in[14], *blm = (const float*)d_in[15];
    float* out = (float*)d_out;

    cudaFuncSetAttribute(gemm_tc<128, 1>, cudaFuncAttributeMaxDynamicSharedMemorySize, GEMM_SMEM128);
    cudaFuncSetAttribute(gemm_tc<128, 3>, cudaFuncAttributeMaxDynamicSharedMemorySize, GEMM_SMEM128);
    cudaFuncSetAttribute(gemm_tc<128, 4>, cudaFuncAttributeMaxDynamicSharedMemorySize, GEMM_SMEM128);
    cudaFuncSetAttribute(gemm_tc<64, 8>,  cudaFuncAttributeMaxDynamicSharedMemorySize, GEMM_SMEM64);
    cudaFuncSetAttribute(gemm_tc<64, 5>,  cudaFuncAttributeMaxDynamicSharedMemorySize, GEMM_SMEM64);
    cudaFuncSetAttribute(gemm_tc<64, 6>,  cudaFuncAttributeMaxDynamicSharedMemorySize, GEMM_SMEM64);
    cudaFuncSetAttribute(attn_k, cudaFuncAttributeMaxDynamicSharedMemorySize, ATTN_SMEM);

    void* pv;
    cudaGetSymbolAddress(&pv, g_Wqkvt); float* Wqkvt = (float*)pv;
    cudaGetSymbolAddress(&pv, g_Bqkv);  float* Bqkv  = (float*)pv;
    cudaGetSymbolAddress(&pv, g_Wpt);   float* Wpt   = (float*)pv;
    cudaGetSymbolAddress(&pv, g_W1t);   float* W1t   = (float*)pv;
    cudaGetSymbolAddress(&pv, g_W2t);   float* W2t   = (float*)pv;
    cudaGetSymbolAddress(&pv, g_Wlmt);  float* Wlmt  = (float*)pv;
    cudaGetSymbolAddress(&pv, g_Amaskf); float* Amaskf = (float*)pv;
    cudaGetSymbolAddress(&pv, g_Amaskb); unsigned* Amaskb = (unsigned*)pv;
    cudaGetSymbolAddress(&pv, g_KQV);   float* KQV = (float*)pv;
    cudaGetSymbolAddress(&pv, g_AQ4);   float* AQ4 = (float*)pv;
    cudaGetSymbolAddress(&pv, g_Ob);    float* Ob  = (float*)pv;
    cudaGetSymbolAddress(&pv, g_Mha);   float* Mha = (float*)pv;
    cudaGetSymbolAddress(&pv, g_Mhar);  float* Mhar = (float*)pv;
    cudaGetSymbolAddress(&pv, g_Ff);    float* Ff  = (float*)pv;
    cudaGetSymbolAddress(&pv, g_Xb);    float* Xb  = (float*)pv;

    // ---- prep: coalesced smem-tiled transposes ----
    {
        TP3 tp{Wk, Wq, Wv, Wqkvt};
        tr3_k<<<dim3(2, 8, 96), dim3(32, 8)>>>(tp);
    }
    bias_k<<<24, 256>>>(bk, bq, bv);
    {
        TP tp{};
        tp.src = Wp; tp.dst = Wpt; tp.M = 512; tp.N = 256;
        tp.sS = 131072; tp.sD = 131072;
        tr_k<<<dim3(8, 16, 4), dim3(32, 8)>>>(tp);
        tp.src = W1; tp.dst = W1t; tp.M = 256; tp.N = 1024;
        tp.sS = 262144; tp.sD = 262144;
        tr_k<<<dim3(32, 8, 4), dim3(32, 8)>>>(tp);
        tp.src = W2; tp.dst = W2t; tp.M = 1024; tp.N = 256;
        tp.sS = 262144; tp.sD = 262144;
        tr_k<<<dim3(8, 32, 4), dim3(32, 8)>>>(tp);
        tp.src = Wlm; tp.dst = Wlmt; tp.M = 256; tp.N = 256;
        tp.sS = 0; tp.sD = 0;
        tr_k<<<dim3(8, 8, 1), dim3(32, 8)>>>(tp);
    }
    mask2_k<<<dim3(16, 16, 2), dim3(32, 32)>>>(dag);
    xr_k<<<8192, 256>>>(X);

    for (int l = 0; l < 4; l++) {
        const float* Amf = Amaskf + (l ? 262144 : 0);
        const unsigned* Amb = Amaskb + (l ? 8192 : 0);
        {   // QKV: Xb @ Wqkvt^T -> scatter K/Qt/Vt (+bias+swish, rounded)
            GP p{}; p.A = Xb; p.lda = 256;
            p.B = Wqkvt + (size_t)l * 1536 * 256; p.ldb = 256;
            p.bias = Bqkv + l * 1536; p.dst0 = KQV; p.K = 256;
            gemm_tc<128, 1><<<dim3(12, 64, 1), 256, GEMM_SMEM128>>>(p);
        }
        {   // AQ = maskf @ Qt^T -> AQ4[z][i][hs]  (rounded)
            GP p{}; p.A = Amf; p.lda = 512;
            p.B = KQV + 4194304; p.ldb = 512;
            p.C = AQ4; p.K = 512;
            gemm_tc<128, 3><<<dim3(64, 4, 1), 256, GEMM_SMEM128>>>(p);
        }
        // fused scores + softmax + PV
        attn_k<<<dim3(8, 128), 512, ATTN_SMEM>>>(AQ4, KQV, KQV + 2 * 4194304, Amb, Ob);
        {   // mha = swish(Ob @ Wpt^T + bp): Mha exact + Mhar rounded
            GP p{}; p.A = Ob; p.lda = 512;
            p.B = Wpt + (size_t)l * 256 * 512; p.ldb = 512;
            p.bias = bp + l * 256; p.C = Mha; p.ldc = 256; p.dst0 = Mhar; p.K = 512;
            gemm_tc<64, 8><<<dim3(4, 64, 1), 256, GEMM_SMEM64>>>(p);
        }
        {   // ff = swish(Mhar @ W1t^T + b1)  (rounded)
            GP p{}; p.A = Mhar; p.lda = 256;
            p.B = W1t + (size_t)l * 1024 * 256; p.ldb = 256;
            p.bias = b1 + l * 1024; p.C = Ff; p.ldc = 1024; p.K = 256;
            gemm_tc<128, 4><<<dim3(8, 64, 1), 256, GEMM_SMEM128>>>(p);
        }
        {   // Xb = Ff @ W2t^T + b2 + Mha  (rounded)
            GP p{}; p.A = Ff; p.lda = 1024;
            p.B = W2t + (size_t)l * 256 * 1024; p.ldb = 1024;
            p.bias = b2 + l * 256; p.res = Mha; p.C = Xb; p.ldc = 256; p.K = 1024;
            gemm_tc<64, 5><<<dim3(4, 64, 1), 256, GEMM_SMEM64>>>(p);
        }
    }
    {   // lm head (exact output)
        GP p{}; p.A = Xb; p.lda = 256; p.B = Wlmt; p.ldb = 256;
        p.bias = blm; p.C = out; p.ldc = 256; p.K = 256;
        gemm_tc<64, 6><<<dim3(4, 64, 1), 256, GEMM_SMEM64>>>(p);
    }
}

// round 17
// speedup vs baseline: 1.1940x; 1.0016x over previous
#include <cuda_runtime.h>
#include <cstdint>

// ---------------------------------------------------------------------------
// CaT transformer, tf32 mma.sync (portable sm_100 target).
// R17: R16 base + prep merged into 2 launches + 4-stage cp.async ring for
// BN=64 GEMMs. Bit-exact numerics (oracle rel_err 7.903782e-4).
// ---------------------------------------------------------------------------

#define DI __device__ __forceinline__

static DI float swishf(float x) { return x / (1.f + __expf(-x)); }

// ------------------------- static device scratch ---------------------------
__device__ float g_Wqkvt[4 * 1536 * 256];   // tf32
__device__ float g_Bqkv [4 * 1536];
__device__ float g_Wpt  [4 * 256 * 512];    // tf32
__device__ float g_W1t  [4 * 1024 * 256];   // tf32
__device__ float g_W2t  [4 * 256 * 1024];   // tf32
__device__ float g_Wlmt [256 * 256];        // tf32
__device__ float g_Amaskf[2 * 512 * 512];   // 0.0 / 1.0
__device__ unsigned g_Amaskb[2 * 512 * 16]; // bit-packed mask rows
__device__ float g_KQV[3 * 512 * 8192];     // K | Qt | Vt (tf32)
__device__ float g_AQ4[512 * 8192];         // [z][i][hs] tf32
__device__ float g_Ob [8192 * 512];         // tf32
__device__ float g_Mha[8192 * 256];         // exact residual
__device__ float g_Mhar[8192 * 256];        // tf32
__device__ float g_Ff [8192 * 1024];        // tf32
__device__ float g_Xb [8192 * 256];         // tf32

// --------------------------- helpers ---------------------------------------
DI unsigned tf32_rn(float x) {
    unsigned r;
    asm("cvt.rn.tf32.f32 %0, %1;" : "=r"(r) : "f"(x));
    return r;
}
DI float tf32f(float x) { return __uint_as_float(tf32_rn(x)); }
DI unsigned cvta_s(const void* p) { return (unsigned)__cvta_generic_to_shared(p); }
DI void cpa16(unsigned dst, const void* src) {
    asm volatile("cp.async.cg.shared.global [%0], [%1], 16;" :: "r"(dst), "l"(src) : "memory");
}
#define CPA_COMMIT() asm volatile("cp.async.commit_group;" ::: "memory")
#define CPA_WAIT(N)  asm volatile("cp.async.wait_group %0;" :: "n"(N) : "memory")

#define LDM_X4(r0, r1, r2, r3, addr) \
    asm volatile("ldmatrix.sync.aligned.m8n8.x4.shared.b16 {%0,%1,%2,%3}, [%4];" \
                 : "=r"(r0), "=r"(r1), "=r"(r2), "=r"(r3) : "r"(addr))
#define MMA_TF32(d, a, b) \
    asm volatile("mma.sync.aligned.m16n8k8.row.col.f32.tf32.tf32.f32 " \
                 "{%0,%1,%2,%3}, {%4,%5,%6,%7}, {%8,%9}, {%0,%1,%2,%3};" \
                 : "+f"((d)[0]), "+f"((d)[1]), "+f"((d)[2]), "+f"((d)[3]) \
                 : "r"((a)[0]), "r"((a)[1]), "r"((a)[2]), "r"((a)[3]), \
                   "r"((b)[0]), "r"((b)[1]))

// ------------------------------ prep kernels -------------------------------
// prep_w: ALL weight 32x32 transpose tiles in one launch (4096 blocks, (32,8)).
//   [0,1536)    QKV: z3 = bid/16 (sel = z3>>5, within = z3&31), tile = bid%16
//   [1536,2048) Wp  (M=512, N=256), 128 tiles per l
//   [2048,3072) W1  (M=256, N=1024), 256 tiles per l
//   [3072,4096) W2  (M=1024, N=256), 256 tiles per l
struct PW { const float* wk; const float* wq; const float* wv;
            const float* wp; const float* w1; const float* w2; };

__global__ void prep_w(PW p) {
    __shared__ float s[32][33];
    const int tx = threadIdx.x, ty = threadIdx.y;
    int bid = blockIdx.x;
    const float* src; float* dst; int M, N, m0, n0;
    if (bid < 1536) {
        const int z3 = bid >> 4, tile = bid & 15;
        const int sel = z3 >> 5, within = z3 & 31;
        src = ((sel == 0) ? p.wk : (sel == 1) ? p.wq : p.wv) + (size_t)within * 16384;
        dst = g_Wqkvt + (size_t)sel * 131072
            + (size_t)(within >> 3) * 393216 + (size_t)(within & 7) * 16384;
        M = 256; N = 64; n0 = (tile & 1) * 32; m0 = (tile >> 1) * 32;
    } else if (bid < 2048) {
        bid -= 1536;
        const int l = bid >> 7, tile = bid & 127;
        src = p.wp + (size_t)l * 131072; dst = g_Wpt + (size_t)l * 131072;
        M = 512; N = 256; n0 = (tile & 7) * 32; m0 = (tile >> 3) * 32;
    } else if (bid < 3072) {
        bid -= 2048;
        const int l = bid >> 8, tile = bid & 255;
        src = p.w1 + (size_t)l * 262144; dst = g_W1t + (size_t)l * 262144;
        M = 256; N = 1024; n0 = (tile & 31) * 32; m0 = (tile >> 5) * 32;
    } else {
        bid -= 3072;
        const int l = bid >> 8, tile = bid & 255;
        src = p.w2 + (size_t)l * 262144; dst = g_W2t + (size_t)l * 262144;
        M = 1024; N = 256; n0 = (tile & 7) * 32; m0 = (tile >> 3) * 32;
    }
#pragma unroll
    for (int i = 0; i < 32; i += 8)
        s[ty + i][tx] = src[(size_t)(m0 + ty + i) * N + n0 + tx];
    __syncthreads();
#pragma unroll
    for (int i = 0; i < 32; i += 8)
        dst[(size_t)(n0 + ty + i) * M + m0 + tx] = tf32f(s[tx][ty + i]);
}

// prep_s: xr (8192) | mask tiles (512) | bias (24) | Wlm tiles (64).  (32,8)
struct PS { const float* X; const int* dag;
            const float* bk; const float* bq; const float* bv;
            const float* wlm; };

__global__ void prep_s(PS p) {
    const int tx = threadIdx.x, ty = threadIdx.y;
    const int t = ty * 32 + tx;
    int bid = blockIdx.x;
    if (bid < 8192) {                               // xr
        const int i = bid * 256 + t;
        g_Xb[i] = tf32f(p.X[i]);
        return;
    }
    bid -= 8192;
    if (bid < 512) {                                // mask tiles (32x32)
        __shared__ float s[32][33];
        const int v = bid >> 8, rem = bid & 255;
        const int i0 = (rem >> 4) * 32, j0 = (rem & 15) * 32;
#pragma unroll
        for (int ii = 0; ii < 4; ii++) {
            const int i = i0 + tx, j = j0 + ty + 8 * ii;
            s[ty + 8 * ii][tx] =
                (p.dag[j * 512 + i] != 0 || (v && i == j)) ? 1.f : 0.f;
        }
        __syncthreads();
#pragma unroll
        for (int ii = 0; ii < 4; ii++) {
            const float mv = s[tx][ty + 8 * ii];    // (i = i0+ty+8ii, j = j0+tx)
            const int irow = i0 + ty + 8 * ii;
            g_Amaskf[v * 262144 + irow * 512 + j0 + tx] = mv;
            const unsigned bits = __ballot_sync(0xffffffffu, mv != 0.f);
            if (tx == 0)
                g_Amaskb[v * 8192 + irow * 16 + (j0 >> 5)] = bits;
        }
        return;
    }
    bid -= 512;
    if (bid < 24) {                                 // bias
        const int idx = bid * 256 + t;
        const int ll = idx / 1536;
        const int c = idx - ll * 1536;
        const int tt = c >> 9, hh = (c >> 6) & 7, hss = c & 63;
        const float* bb = (tt == 0) ? p.bk : (tt == 1) ? p.bq : p.bv;
        g_Bqkv[idx] = bb[(ll * 8 + hh) * 64 + hss];
        return;
    }
    bid -= 24;
    {                                               // Wlm transpose (32x32)
        __shared__ float s[32][33];
        const int m0 = (bid >> 3) * 32, n0 = (bid & 7) * 32;
#pragma unroll
        for (int i = 0; i < 32; i += 8)
            s[ty + i][tx] = p.wlm[(size_t)(m0 + ty + i) * 256 + n0 + tx];
        __syncthreads();
#pragma unroll
        for (int i = 0; i < 32; i += 8)
            g_Wlmt[(size_t)(n0 + ty + i) * 256 + m0 + tx] = tf32f(s[tx][ty + i]);
    }
}

// ------------------------------- GEMM core ---------------------------------
struct GP {
    const float* A; const float* B; float* C;
    const float* bias; const float* res;
    float* dst0;
    int K, lda, ldb, ldc;
    long long sAz, sBz, sCz;
};

// BK=32, pitch 36. BN=128: 3 stages; BN=64: 4 stages. Both 110592 B.
static const int GEMM_SMEM128 = 3 * (128 * 36 + 128 * 36) * 4;   // 110592 B
static const int GEMM_SMEM64  = 4 * (128 * 36 +  64 * 36) * 4;   // 110592 B

// MODE: 1 QKV scatter  3 AQ scatter  4 bias+swish(rounded)  5 bias+res(rounded)
//       6 bias(exact)  8 bias+swish dual (C exact, dst0 rounded)
template <int BN, int MODE>
__global__ __launch_bounds__(256, 2) void gemm_tc(GP p) {
    constexpr int BM = 128, PITCH = 36;
    constexpr int NS  = (BN == 128) ? 3 : 4;
    constexpr int WNW = (BN == 128) ? 4 : 2;
    constexpr int WM  = (BN == 128) ? 64 : 32;
    constexpr int WN  = 32;
    constexpr int MT = WM / 16, NT = WN / 8, NT2 = NT / 2;
    constexpr int ASZ = BM * PITCH, BSZ = BN * PITCH;
    constexpr int BLD = (BN * 32) / (4 * 256);

    extern __shared__ float dsm[];
    const unsigned sA = cvta_s(dsm);
    const unsigned sB = cvta_s(dsm + NS * ASZ);

    const int t = threadIdx.x, lane = t & 31, w = t >> 5;
    const int wm = w / WNW, wn = w % WNW;
    const int g = lane >> 2, cc = lane & 3;
    const int lrow = lane & 15;
    const unsigned loff = (unsigned)((lane >> 4) << 4);
    const int bx = blockIdx.x, by = blockIdx.y, bz = blockIdx.z;
    const int ar = t >> 3, ac = (t & 7) << 2;

    const float* Af = p.A + (size_t)bz * p.sAz + (size_t)by * BM * p.lda;
    const float* Bp = p.B + (size_t)bz * p.sBz + (size_t)bx * BN * p.ldb;
    float* C = p.C + (size_t)bz * p.sCz;

    float acc[MT][NT][4];
#pragma unroll
    for (int i = 0; i < MT; i++)
#pragma unroll
        for (int j = 0; j < NT; j++)
#pragma unroll
            for (int r = 0; r < 4; r++) acc[i][j][r] = 0.f;

    auto issue = [&](int ch, int s) {
        const int k0 = ch << 5;
#pragma unroll
        for (int i = 0; i < 4; i++) {
            const int r = ar + i * 32;
            cpa16(sA + (unsigned)((s * ASZ + r * PITCH + ac) * 4),
                  Af + (size_t)r * p.lda + k0 + ac);
        }
#pragma unroll
        for (int i = 0; i < BLD; i++) {
            const int r = ar + i * 32;
            cpa16(sB + (unsigned)((s * BSZ + r * PITCH + ac) * 4),
                  Bp + (size_t)r * p.ldb + k0 + ac);
        }
        CPA_COMMIT();
    };

    const int nch = p.K >> 5;
    issue(0, 0); issue(1, 1);
    if (NS == 4) issue(2, 2);
    for (int c = 0; c < nch; c++) {
        asm volatile("cp.async.wait_group %0;" :: "n"(NS - 2) : "memory");
        __syncthreads();
        if (c + NS - 1 < nch) issue(c + NS - 1, (c + NS - 1) % NS);
        else CPA_COMMIT();
        const int buf = c % NS;
#pragma unroll
        for (int ks = 0; ks < 4; ks++) {
            unsigned a[MT][4], b[NT][2];
#pragma unroll
            for (int i = 0; i < MT; i++) {
                const unsigned addr = sA + (unsigned)((buf * ASZ
                                    + (wm * WM + i * 16 + lrow) * PITCH + ks * 8) * 4) + loff;
                LDM_X4(a[i][0], a[i][1], a[i][2], a[i][3], addr);
            }
#pragma unroll
            for (int j2 = 0; j2 < NT2; j2++) {
                const unsigned addr = sB + (unsigned)((buf * BSZ
                                    + (wn * WN + j2 * 16 + lrow) * PITCH + ks * 8) * 4) + loff;
                LDM_X4(b[2 * j2][0], b[2 * j2 + 1][0], b[2 * j2][1], b[2 * j2 + 1][1], addr);
            }
#pragma unroll
            for (int i = 0; i < MT; i++)
#pragma unroll
                for (int j = 0; j < NT; j++)
                    MMA_TF32(acc[i][j], a[i], b[j]);
        }
    }

    // ---------------- epilogue -----------------
    if (MODE == 1 && bx >= 4) {
        // Q/V tile: stage transposed in smem, then coalesced float4 writes.
        __syncthreads();
        float* st = dsm;                       // 128 x pitch132 = 67584 B
#pragma unroll
        for (int i = 0; i < MT; i++)
#pragma unroll
            for (int j = 0; j < NT; j++)
#pragma unroll
                for (int h2 = 0; h2 < 2; h2++) {
                    const int gmL = wm * WM + i * 16 + h2 * 8 + g;
                    const int gnL = wn * WN + j * 8 + (cc << 1);
                    const int gn = bx * BN + gnL;
                    const float e0 = swishf(acc[i][j][h2 * 2] + p.bias[gn]);
                    const float e1 = swishf(acc[i][j][h2 * 2 + 1] + p.bias[gn + 1]);
                    st[gnL * 132 + gmL] = tf32f(e0);
                    st[(gnL + 1) * 132 + gmL] = tf32f(e1);
                }
        __syncthreads();
        const int b = by >> 2, n0 = (by & 3) * 128;
        const int tt = bx >> 2;                // 1 = Q, 2 = V
        float* dst = p.dst0 + (tt == 1 ? 4194304u : 8388608u);
        const int h0 = (bx * 2) & 7;
#pragma unroll
        for (int i = 0; i < 16; i++) {
            const int idx = i * 256 + t;
            const int row = idx >> 5, c4 = (idx & 31) << 2;
            const int zrow = (b * 8 + h0 + (row >> 6)) * 64 + (row & 63);
            const float* sp = st + row * 132 + c4;
            *(float4*)&dst[(size_t)zrow * 512 + n0 + c4] =
                make_float4(sp[0], sp[1], sp[2], sp[3]);
        }
        return;
    }
#pragma unroll
    for (int i = 0; i < MT; i++)
#pragma unroll
        for (int j = 0; j < NT; j++)
#pragma unroll
            for (int h2 = 0; h2 < 2; h2++) {
                const int gm = by * BM + wm * WM + i * 16 + h2 * 8 + g;
                const int gn = bx * BN + wn * WN + j * 8 + (cc << 1);
                const float v0 = acc[i][j][h2 * 2 + 0];
                const float v1 = acc[i][j][h2 * 2 + 1];
                if (MODE == 1) {               // K tile only (bx < 4)
                    const float e0 = swishf(v0 + p.bias[gn]);
                    const float e1 = swishf(v1 + p.bias[gn + 1]);
                    const int h = (gn >> 6) & 7, hs = gn & 63;
                    const int b = gm >> 9, n = gm & 511, z = b * 8 + h;
                    *(float2*)&p.dst0[(size_t)(z * 512 + n) * 64 + hs] =
                        make_float2(tf32f(e0), tf32f(e1));
                } else if (MODE == 3) {
                    *(float2*)&p.C[(size_t)(gn >> 6) * 32768 + (size_t)gm * 64 + (gn & 63)] =
                        make_float2(tf32f(v0), tf32f(v1));
                } else if (MODE == 4) {
                    *(float2*)&C[(size_t)gm * p.ldc + gn] =
                        make_float2(tf32f(swishf(v0 + p.bias[gn])),
                                    tf32f(swishf(v1 + p.bias[gn + 1])));
                } else if (MODE == 5) {
                    const float2 rr = *(const float2*)&p.res[(size_t)gm * p.ldc + gn];
                    *(float2*)&C[(size_t)gm * p.ldc + gn] =
                        make_float2(tf32f(v0 + p.bias[gn] + rr.x),
                                    tf32f(v1 + p.bias[gn + 1] + rr.y));
                } else if (MODE == 6) {
                    *(float2*)&C[(size_t)gm * p.ldc + gn] =
                        make_float2(v0 + p.bias[gn], v1 + p.bias[gn + 1]);
                } else {   // MODE 8
                    const float e0 = swishf(v0 + p.bias[gn]);
                    const float e1 = swishf(v1 + p.bias[gn + 1]);
                    *(float2*)&C[(size_t)gm * p.ldc + gn] = make_float2(e0, e1);
                    *(float2*)&p.dst0[(size_t)gm * p.ldc + gn] =
                        make_float2(tf32f(e0), tf32f(e1));
                }
            }
}

// ------------------- fused attention: scores+softmax+PV --------------------
// Grid (8 i-tiles, 128 z), 512 threads (16 warps). Single sync per chunk.
// smem floats: S 64x516 @0 | At 64x68 @33024 | Bt @37376
static const int ATTN_SMEM = (33024 + 4352 + 17408) * 4;   // 219136 B

__global__ __launch_bounds__(512) void attn_k(
    const float* __restrict__ AQ, const float* __restrict__ Kb,
    const float* __restrict__ Vt, const unsigned* __restrict__ Mb,
    float* __restrict__ Ob) {
    extern __shared__ float sm[];
    float* S = sm;

    const int t = threadIdx.x, lane = t & 31, w = t >> 5;     // w: 0..15
    const int g = lane >> 2, cc = lane & 3;
    const int lrow = lane & 15;
    const unsigned loff = (unsigned)((lane >> 4) << 4);
    const int i0 = blockIdx.x * 64, z = blockIdx.y;

    const float* AQz = AQ + (size_t)z * 32768 + (size_t)i0 * 64;   // 64 x 64
    const float* Kp  = Kb + (size_t)z * 32768;                     // 512 x 64
    const float* Vz  = Vt + (size_t)z * 32768;                     // 64 x 512

    const unsigned sS = cvta_s(S);
    const unsigned sA = cvta_s(sm + 33024);
    const unsigned sB = cvta_s(sm + 37376);

    // ---- prologue: cp.async At (64x64 -> pitch 68) + K chunk 0 ------------
#pragma unroll
    for (int i = 0; i < 2; i++) {
        const int idx = i * 512 + t;
        const int r = idx >> 4, c = (idx & 15) << 2;
        cpa16(sA + (unsigned)((r * 68 + c) * 4), AQz + (size_t)r * 64 + c);
    }
    auto issueK = [&](int jc, int s) {
#pragma unroll
        for (int i = 0; i < 4; i++) {
            const int idx = i * 512 + t;
            const int r = idx >> 4, c = (idx & 15) << 2;
            cpa16(sB + (unsigned)((s * 8704 + r * 68 + c) * 4),
                  Kp + (size_t)(jc * 128 + r) * 64 + c);
        }
        CPA_COMMIT();
    };
    issueK(0, 0);   // single group: At + K0

    // ================= phase 1: S = AQ @ K^T, mask+scale ====================
    {
        const int wm = w >> 2, wn = w & 3;      // 4x4 warps: 16 rows x 32 cols
        for (int jc = 0; jc < 4; jc++) {
            CPA_WAIT(0);
            __syncthreads();
            if (jc + 1 < 4) issueK(jc + 1, (jc + 1) & 1);
            float acc[4][4];
#pragma unroll
            for (int j = 0; j < 4; j++)
#pragma unroll
                for (int r = 0; r < 4; r++) acc[j][r] = 0.f;
            const int buf = jc & 1;
#pragma unroll
            for (int ks = 0; ks < 8; ks++) {
                unsigned a[4], b[4][2];
                {
                    const unsigned addr = sA + (unsigned)(((wm * 16 + lrow) * 68
                                        + ks * 8) * 4) + loff;
                    LDM_X4(a[0], a[1], a[2], a[3], addr);
                }
#pragma unroll
                for (int j2 = 0; j2 < 2; j2++) {
                    const unsigned addr = sB + (unsigned)((buf * 8704
                                        + (wn * 32 + j2 * 16 + lrow) * 68 + ks * 8) * 4) + loff;
                    LDM_X4(b[2 * j2][0], b[2 * j2 + 1][0], b[2 * j2][1], b[2 * j2 + 1][1], addr);
                }
#pragma unroll
                for (int j = 0; j < 4; j++)
                    MMA_TF32(acc[j], a, b[j]);
            }
            // epilogue: bit-mask + scale -> S (float2-paired smem stores)
            const unsigned mw0 = Mb[(size_t)(i0 + wm * 16 + g) * 16 + jc * 4 + wn];
            const unsigned mw1 = Mb[(size_t)(i0 + wm * 16 + 8 + g) * 16 + jc * 4 + wn];
#pragma unroll
            for (int j = 0; j < 4; j++)
#pragma unroll
                for (int h2 = 0; h2 < 2; h2++) {
                    const int gm = wm * 16 + h2 * 8 + g;
                    const int gn = jc * 128 + wn * 32 + j * 8 + (cc << 1);
                    const unsigned mw = h2 ? mw1 : mw0;
                    const int bp = j * 8 + (cc << 1);
                    const float s0 = ((mw >> bp) & 1u) ? acc[j][h2 * 2] * 0.125f : -3.0e38f;
                    const float s1 = ((mw >> (bp + 1)) & 1u) ? acc[j][h2 * 2 + 1] * 0.125f : -3.0e38f;
                    *(float2*)&S[gm * 516 + gn] = make_float2(s0, s1);
                }
        }
    }
    __syncthreads();   // all S written before softmax (and before V overwrites Bt)

    // ---- overlap: start V chunk 0 copy before softmax ----
    auto issueV = [&](int kc, int s) {
#pragma unroll
        for (int i = 0; i < 4; i++) {
            const int idx = i * 512 + t;
            const int r = idx >> 5, c = (idx & 31) << 2;
            cpa16(sB + (unsigned)((s * 8448 + r * 132 + c) * 4),
                  Vz + (size_t)r * 512 + kc * 128 + c);
        }
        CPA_COMMIT();
    };
    issueV(0, 0);

    // ================= phase 2: exact softmax + (P + A), tf32 ===============
    for (int it = 0; it < 4; it++) {
        const int ir = it * 16 + w;
        float* r = S + ir * 516;
        const unsigned* mwp = Mb + (size_t)(i0 + ir) * 16;
        float x[16];
        float m = -3.4e38f;
#pragma unroll
        for (int k = 0; k < 16; k++) { x[k] = r[k * 32 + lane]; m = fmaxf(m, x[k]); }
#pragma unroll
        for (int o = 16; o; o >>= 1) m = fmaxf(m, __shfl_xor_sync(0xffffffffu, m, o));
        if (m <= -1e37f) {
#pragma unroll
            for (int k = 0; k < 16; k++) r[k * 32 + lane] = 0.f;
        } else {
            float s = 0.f;
#pragma unroll
            for (int k = 0; k < 16; k++) { x[k] = __expf(x[k] - m); s += x[k]; }
#pragma unroll
            for (int o = 16; o; o >>= 1) s += __shfl_xor_sync(0xffffffffu, s, o);
            const float inv = 1.f / s;
#pragma unroll
            for (int k = 0; k < 16; k++)
                r[k * 32 + lane] =
                    tf32f(x[k] * inv + (float)((mwp[k] >> lane) & 1u));
        }
    }
    __syncthreads();

    // ================= phase 3: O = Ssm @ V^T (4 x K=128 chunks) ============
    {
        const int wm = w >> 2, wn = w & 3;      // 4x4 warps: 16 rows x 16 cols
        float oa[2][4];
#pragma unroll
        for (int j = 0; j < 2; j++)
#pragma unroll
            for (int r = 0; r < 4; r++) oa[j][r] = 0.f;
        for (int kc = 0; kc < 4; kc++) {
            CPA_WAIT(0);
            __syncthreads();
            if (kc + 1 < 4) issueV(kc + 1, (kc + 1) & 1);
            const int buf = kc & 1;
#pragma unroll
            for (int ks = 0; ks < 16; ks++) {
                unsigned a[4], b[2][2];
                {
                    const unsigned addr = sS + (unsigned)(((wm * 16 + lrow) * 516
                                        + kc * 128 + ks * 8) * 4) + loff;
                    LDM_X4(a[0], a[1], a[2], a[3], addr);
                }
                {
                    const unsigned addr = sB + (unsigned)((buf * 8448
                                        + (wn * 16 + lrow) * 132 + ks * 8) * 4) + loff;
                    LDM_X4(b[0][0], b[1][0], b[0][1], b[1][1], addr);
                }
#pragma unroll
                for (int j = 0; j < 2; j++)
                    MMA_TF32(oa[j], a, b[j]);
            }
        }
        // epilogue -> Ob (float2-paired, rounded)
        const int b = z >> 3, h = z & 7;
#pragma unroll
        for (int j = 0; j < 2; j++)
#pragma unroll
            for (int h2 = 0; h2 < 2; h2++) {
                const int gm = wm * 16 + h2 * 8 + g;
                const int gn = wn * 16 + j * 8 + (cc << 1);
                *(float2*)&Ob[(size_t)(b * 512 + i0 + gm) * 512 + h * 64 + gn] =
                    make_float2(tf32f(oa[j][h2 * 2]), tf32f(oa[j][h2 * 2 + 1]));
            }
    }
}

// ------------------------------ host driver --------------------------------
extern "C" void kernel_launch(void* const* d_in, const int* in_sizes, int n_in,
                              void* d_out, int out_size) {
    (void)in_sizes; (void)n_in; (void)out_size;
    const float* X   = (const float*)d_in[0];
    const int*   dag = (const int*)d_in[1];
    const float* Wk  = (const float*)d_in[2],  *bk  = (const float*)d_in[3];
    const float* Wq  = (const float*)d_in[4],  *bq  = (const float*)d_in[5];
    const float* Wv  = (const float*)d_in[6],  *bv  = (const float*)d_in[7];
    const float* Wp  = (const float*)d_in[8],  *bp  = (const float*)d_in[9];
    const float* W1  = (const float*)d_in[10], *b1  = (const float*)d_in[11];
    const float* W2  = (const float*)d_in[12], *b2  = (const float*)d_in[13];
    const float* Wlm = (const float*)d_in[14], *blm = (const float*)d_in[15];
    float* out = (float*)d_out;

    cudaFuncSetAttribute(gemm_tc<128, 1>, cudaFuncAttributeMaxDynamicSharedMemorySize, GEMM_SMEM128);
    cudaFuncSetAttribute(gemm_tc<128, 3>, cudaFuncAttributeMaxDynamicSharedMemorySize, GEMM_SMEM128);
    cudaFuncSetAttribute(gemm_tc<128, 4>, cudaFuncAttributeMaxDynamicSharedMemorySize, GEMM_SMEM128);
    cudaFuncSetAttribute(gemm_tc<64, 8>,  cudaFuncAttributeMaxDynamicSharedMemorySize, GEMM_SMEM64);
    cudaFuncSetAttribute(gemm_tc<64, 5>,  cudaFuncAttributeMaxDynamicSharedMemorySize, GEMM_SMEM64);
    cudaFuncSetAttribute(gemm_tc<64, 6>,  cudaFuncAttributeMaxDynamicSharedMemorySize, GEMM_SMEM64);
    cudaFuncSetAttribute(attn_k, cudaFuncAttributeMaxDynamicSharedMemorySize, ATTN_SMEM);

    void* pv;
    cudaGetSymbolAddress(&pv, g_Wqkvt); float* Wqkvt = (float*)pv;
    cudaGetSymbolAddress(&pv, g_Bqkv);  float* Bqkv  = (float*)pv;
    cudaGetSymbolAddress(&pv, g_Wpt);   float* Wpt   = (float*)pv;
    cudaGetSymbolAddress(&pv, g_W1t);   float* W1t   = (float*)pv;
    cudaGetSymbolAddress(&pv, g_W2t);   float* W2t   = (float*)pv;
    cudaGetSymbolAddress(&pv, g_Wlmt);  float* Wlmt  = (float*)pv;
    cudaGetSymbolAddress(&pv, g_Amaskf); float* Amaskf = (float*)pv;
    cudaGetSymbolAddress(&pv, g_Amaskb); unsigned* Amaskb = (unsigned*)pv;
    cudaGetSymbolAddress(&pv, g_KQV);   float* KQV = (float*)pv;
    cudaGetSymbolAddress(&pv, g_AQ4);   float* AQ4 = (float*)pv;
    cudaGetSymbolAddress(&pv, g_Ob);    float* Ob  = (float*)pv;
    cudaGetSymbolAddress(&pv, g_Mha);   float* Mha = (float*)pv;
    cudaGetSymbolAddress(&pv, g_Mhar);  float* Mhar = (float*)pv;
    cudaGetSymbolAddress(&pv, g_Ff);    float* Ff  = (float*)pv;
    cudaGetSymbolAddress(&pv, g_Xb);    float* Xb  = (float*)pv;

    // ---- prep: 2 merged launches ----
    {
        PW pw{Wk, Wq, Wv, Wp, W1, W2};
        prep_w<<<4096, dim3(32, 8)>>>(pw);
        PS ps{X, dag, bk, bq, bv, Wlm};
        prep_s<<<8792, dim3(32, 8)>>>(ps);
    }

    for (int l = 0; l < 4; l++) {
        const float* Amf = Amaskf + (l ? 262144 : 0);
        const unsigned* Amb = Amaskb + (l ? 8192 : 0);
        {   // QKV: Xb @ Wqkvt^T -> scatter K/Qt/Vt (+bias+swish, rounded)
            GP p{}; p.A = Xb; p.lda = 256;
            p.B = Wqkvt + (size_t)l * 1536 * 256; p.ldb = 256;
            p.bias = Bqkv + l * 1536; p.dst0 = KQV; p.K = 256;
            gemm_tc<128, 1><<<dim3(12, 64, 1), 256, GEMM_SMEM128>>>(p);
        }
        {   // AQ = maskf @ Qt^T -> AQ4[z][i][hs]  (rounded)
            GP p{}; p.A = Amf; p.lda = 512;
            p.B = KQV + 4194304; p.ldb = 512;
            p.C = AQ4; p.K = 512;
            gemm_tc<128, 3><<<dim3(64, 4, 1), 256, GEMM_SMEM128>>>(p);
        }
        // fused scores + softmax + PV
        attn_k<<<dim3(8, 128), 512, ATTN_SMEM>>>(AQ4, KQV, KQV + 2 * 4194304, Amb, Ob);
        {   // mha = swish(Ob @ Wpt^T + bp): Mha exact + Mhar rounded
            GP p{}; p.A = Ob; p.lda = 512;
            p.B = Wpt + (size_t)l * 256 * 512; p.ldb = 512;
            p.bias = bp + l * 256; p.C = Mha; p.ldc = 256; p.dst0 = Mhar; p.K = 512;
            gemm_tc<64, 8><<<dim3(4, 64, 1), 256, GEMM_SMEM64>>>(p);
        }
        {   // ff = swish(Mhar @ W1t^T + b1)  (rounded)
            GP p{}; p.A = Mhar; p.lda = 256;
            p.B = W1t + (size_t)l * 1024 * 256; p.ldb = 256;
            p.bias = b1 + l * 1024; p.C = Ff; p.ldc = 1024; p.K = 256;
            gemm_tc<128, 4><<<dim3(8, 64, 1), 256, GEMM_SMEM128>>>(p);
        }
        {   // Xb = Ff @ W2t^T + b2 + Mha  (rounded)
            GP p{}; p.A = Ff; p.lda = 1024;
            p.B = W2t + (size_t)l * 256 * 1024; p.ldb = 1024;
            p.bias = b2 + l * 256; p.res = Mha; p.C = Xb; p.ldc = 256; p.K = 1024;
            gemm_tc<64, 5><<<dim3(4, 64, 1), 256, GEMM_SMEM64>>>(p);
        }
    }
    {   // lm head (exact output)
        GP p{}; p.A = Xb; p.lda = 256; p.B = Wlmt; p.ldb = 256;
        p.bias = blm; p.C = out; p.ldc = 256; p.K = 256;
        gemm_tc<64, 6><<<dim3(4, 64, 1), 256, GEMM_SMEM64>>>(p);
    }
}